// round 4
// baseline (speedup 1.0000x reference)
#include <cuda_runtime.h>

#define NN 100000
#define DD 128
#define EE 1600000
#define DEE 16
#define GG 512
#define BN_EPS 1e-5f

// ---------------- scratch (static device globals; no allocation) -------------
__device__ __align__(16) float g_bufA[NN * DD];          // 51.2 MB
__device__ __align__(16) float g_bufB[NN * DD];          // 51.2 MB
__device__ int   g_deg[NN];
__device__ int   g_rowptr[NN + 1];
__device__ int   g_curn[NN];
__device__ int   g_csrsrc[EE];
__device__ int   g_ge[EE];
__device__ int   g_egcnt[GG];
__device__ int   g_egptr[GG + 1];
__device__ int   g_curg[GG];
__device__ int   g_egedge[EE];
__device__ int   g_ncnt[GG];
__device__ float g_dinv[NN];
__device__ float g_nsum[GG * DD];
__device__ float g_hsum[GG * DD];
__device__ int   g_blksums[128];
__device__ int   g_is64;

// ---------------- index helpers (dtype-agnostic) -------------------------------
__device__ __forceinline__ int load_idx(const void* p, long long i) {
    if (g_is64) return (int)((const long long*)p)[i];
    return ((const int*)p)[i];
}
__device__ __forceinline__ int clampi(int v, int lo, int hi) {
    return v < lo ? lo : (v > hi ? hi : v);
}

// ---------------- dtype detection: int64 values <2^31 have zero odd words ------
__global__ void k_detect(const int* __restrict__ w) {
    __shared__ int ok;
    if (threadIdx.x == 0) ok = 1;
    __syncthreads();
    int bad = 0;
    for (int i = threadIdx.x; i < 2048; i += blockDim.x)
        if (w[2 * i + 1] != 0) bad = 1;
    if (bad) atomicAnd(&ok, 0);
    __syncthreads();
    if (threadIdx.x == 0) g_is64 = ok;
}

// ---------------- init: zero accumulators/histograms ---------------------------
__global__ void k_init() {
    int i = blockIdx.x * blockDim.x + threadIdx.x;
    int stride = gridDim.x * blockDim.x;
    for (int j = i; j < NN; j += stride) g_deg[j] = 0;
    for (int j = i; j < GG; j += stride) { g_egcnt[j] = 0; g_ncnt[j] = 0; }
    for (int j = i; j < GG * DD; j += stride) { g_nsum[j] = 0.f; g_hsum[j] = 0.f; }
}

// ---------------- histograms ----------------------------------------------------
__global__ void k_hist_edges(const void* __restrict__ ei,
                             const void* __restrict__ batch) {
    int e = blockIdx.x * blockDim.x + threadIdx.x;
    if (e >= EE) return;
    int s = clampi(load_idx(ei, e), 0, NN - 1);
    int d = clampi(load_idx(ei, (long long)EE + e), 0, NN - 1);
    atomicAdd(&g_deg[d], 1);
    int g = clampi(load_idx(batch, s), 0, GG - 1);
    g_ge[e] = g;
    atomicAdd(&g_egcnt[g], 1);
}

__global__ void k_hist_nodes(const void* __restrict__ batch) {
    int i = blockIdx.x * blockDim.x + threadIdx.x;
    if (i >= NN) return;
    int g = clampi(load_idx(batch, i), 0, GG - 1);
    atomicAdd(&g_ncnt[g], 1);
}

// ---------------- 3-phase exclusive scan over g_deg -> g_rowptr ------------------
__global__ void k_scan1() {
    __shared__ int s[1024];
    int b = blockIdx.x, t = threadIdx.x;
    int i = b * 1024 + t;
    int v = (i < NN) ? g_deg[i] : 0;
    s[t] = v;
    __syncthreads();
    for (int off = 1; off < 1024; off <<= 1) {
        int x = (t >= off) ? s[t - off] : 0;
        __syncthreads();
        s[t] += x;
        __syncthreads();
    }
    if (i < NN) g_rowptr[i] = s[t] - v;
    if (t == 1023) g_blksums[b] = s[t];
}

__global__ void k_scan2(int nb) {
    __shared__ int s[128];
    int t = threadIdx.x;
    int v = (t < nb) ? g_blksums[t] : 0;
    s[t] = v;
    __syncthreads();
    for (int off = 1; off < 128; off <<= 1) {
        int x = (t >= off) ? s[t - off] : 0;
        __syncthreads();
        s[t] += x;
        __syncthreads();
    }
    g_blksums[t] = s[t] - v;
}

__global__ void k_scan3() {
    int b = blockIdx.x, t = threadIdx.x;
    int i = b * 1024 + t;
    if (i < NN) {
        int rp = g_rowptr[i] + g_blksums[b];
        g_rowptr[i] = rp;
        g_curn[i] = rp;
        g_dinv[i] = rsqrtf((float)(g_deg[i] + 1));   // +1 = self-loop
    }
    if (i == 0) g_rowptr[NN] = EE;
}

__global__ void k_scanG() {
    __shared__ int s[512];
    int t = threadIdx.x;
    int v = g_egcnt[t];
    s[t] = v;
    __syncthreads();
    for (int off = 1; off < 512; off <<= 1) {
        int x = (t >= off) ? s[t - off] : 0;
        __syncthreads();
        s[t] += x;
        __syncthreads();
    }
    int p = s[t] - v;
    g_egptr[t] = p;
    g_curg[t] = p;
    if (t == 0) g_egptr[GG] = EE;
}

// ---------------- CSR scatter ------------------------------------------------------
__global__ void k_scatter(const void* __restrict__ ei) {
    int e = blockIdx.x * blockDim.x + threadIdx.x;
    if (e >= EE) return;
    int s = clampi(load_idx(ei, e), 0, NN - 1);
    int d = clampi(load_idx(ei, (long long)EE + e), 0, NN - 1);
    int p = atomicAdd(&g_curn[d], 1);
    if (p >= 0 && p < EE) g_csrsrc[p] = s;
    int g = g_ge[e];
    int p2 = atomicAdd(&g_curg[g], 1);
    if (p2 >= 0 && p2 < EE) g_egedge[p2] = e;
}

// ---------------- GEMM: g_bufA[nrows,128] = X[nrows,128] @ W[128,128] -------------
template <bool FIRST>
__global__ void k_gemm(const float* __restrict__ Xext, const float* __restrict__ W,
                       int nrows) {
    const float* __restrict__ X = FIRST ? Xext : (const float*)g_bufB;
    float* __restrict__ Y = g_bufA;
    __shared__ float xs[32][64];    // transposed: xs[k][row]
    __shared__ float ws[32][128];
    int tid = threadIdx.x;
    int c = tid & 15;
    int r = tid >> 4;
    int row0 = blockIdx.x * 64;

    float acc[4][8];
#pragma unroll
    for (int i = 0; i < 4; i++)
#pragma unroll
        for (int j = 0; j < 8; j++) acc[i][j] = 0.f;

    for (int kc = 0; kc < 128; kc += 32) {
#pragma unroll
        for (int l = 0; l < 8; l++) {
            int idx = tid + l * 256;
            int rr = idx >> 5;
            int kk = idx & 31;
            int grow = row0 + rr;
            float v = 0.f;
            if (grow < nrows) v = X[grow * DD + kc + kk];
            xs[kk][rr] = v;
        }
#pragma unroll
        for (int l = 0; l < 16; l++) {
            int idx = tid + l * 256;
            int kk = idx >> 7;
            int cc = idx & 127;
            ws[kk][cc] = W[(kc + kk) * DD + cc];
        }
        __syncthreads();
#pragma unroll
        for (int k = 0; k < 32; k++) {
            float4 xv = *reinterpret_cast<float4*>(&xs[k][r * 4]);
            float4 w0 = *reinterpret_cast<float4*>(&ws[k][c * 8]);
            float4 w1 = *reinterpret_cast<float4*>(&ws[k][c * 8 + 4]);
            float xr[4] = {xv.x, xv.y, xv.z, xv.w};
            float wr[8] = {w0.x, w0.y, w0.z, w0.w, w1.x, w1.y, w1.z, w1.w};
#pragma unroll
            for (int i = 0; i < 4; i++)
#pragma unroll
                for (int j = 0; j < 8; j++)
                    acc[i][j] = fmaf(xr[i], wr[j], acc[i][j]);
        }
        __syncthreads();
    }
#pragma unroll
    for (int i = 0; i < 4; i++) {
        int grow = row0 + r * 4 + i;
        if (grow < nrows) {
            float4 o0 = make_float4(acc[i][0], acc[i][1], acc[i][2], acc[i][3]);
            float4 o1 = make_float4(acc[i][4], acc[i][5], acc[i][6], acc[i][7]);
            *reinterpret_cast<float4*>(&Y[grow * DD + c * 8]) = o0;
            *reinterpret_cast<float4*>(&Y[grow * DD + c * 8 + 4]) = o1;
        }
    }
}

// ---------------- gather + bias + BN(eval) + ReLU ----------------------------------
__global__ void k_gather(const float* __restrict__ B, const float* __restrict__ GA,
                         const float* __restrict__ BT, const float* __restrict__ M,
                         const float* __restrict__ V) {
    int warp = (blockIdx.x * blockDim.x + threadIdx.x) >> 5;
    int lane = threadIdx.x & 31;
    if (warp >= NN) return;
    int node = warp;
    float di = g_dinv[node];
    const float4* xw4 = reinterpret_cast<const float4*>((const float*)g_bufA);
    float4 a = xw4[node * 32 + lane];
    float w0 = di * di;
    float4 acc;
    acc.x = a.x * w0; acc.y = a.y * w0; acc.z = a.z * w0; acc.w = a.w * w0;
    int jb = g_rowptr[node], je = g_rowptr[node + 1];
    for (int j = jb; j < je; j++) {
        int s = g_csrsrc[j];
        float w = g_dinv[s] * di;
        float4 v4 = xw4[s * 32 + lane];
        acc.x = fmaf(v4.x, w, acc.x);
        acc.y = fmaf(v4.y, w, acc.y);
        acc.z = fmaf(v4.z, w, acc.z);
        acc.w = fmaf(v4.w, w, acc.w);
    }
    int f = lane * 4;
    float4 b4  = *reinterpret_cast<const float4*>(&B[f]);
    float4 g4  = *reinterpret_cast<const float4*>(&GA[f]);
    float4 bt4 = *reinterpret_cast<const float4*>(&BT[f]);
    float4 m4  = *reinterpret_cast<const float4*>(&M[f]);
    float4 vv4 = *reinterpret_cast<const float4*>(&V[f]);
    float4 o;
    o.x = fmaxf((acc.x + b4.x - m4.x) * rsqrtf(vv4.x + BN_EPS) * g4.x + bt4.x, 0.f);
    o.y = fmaxf((acc.y + b4.y - m4.y) * rsqrtf(vv4.y + BN_EPS) * g4.y + bt4.y, 0.f);
    o.z = fmaxf((acc.z + b4.z - m4.z) * rsqrtf(vv4.z + BN_EPS) * g4.z + bt4.z, 0.f);
    o.w = fmaxf((acc.w + b4.w - m4.w) * rsqrtf(vv4.w + BN_EPS) * g4.w + bt4.w, 0.f);
    float4* out4 = reinterpret_cast<float4*>((float*)g_bufB);
    out4[node * 32 + lane] = o;
}

// ---------------- per-graph node-sum pooling (reads g_bufB) -------------------------
__global__ void k_pool(const void* __restrict__ batch) {
    int warp = (blockIdx.x * blockDim.x + threadIdx.x) >> 5;
    int lane = threadIdx.x & 31;
    if (warp >= NN) return;
    int node = warp;
    int g = clampi(load_idx(batch, node), 0, GG - 1);
    const float4* h4 = reinterpret_cast<const float4*>((const float*)g_bufB);
    float4 hv = h4[node * 32 + lane];
    int base = g * DD + lane * 4;
    atomicAdd(&g_nsum[base + 0], hv.x);
    atomicAdd(&g_nsum[base + 1], hv.y);
    atomicAdd(&g_nsum[base + 2], hv.z);
    atomicAdd(&g_nsum[base + 3], hv.w);
}

// ---------------- edge MLP first layer, summed per graph ----------------------------
__global__ void k_edgemlp(const float* __restrict__ EA, const float* __restrict__ W1e,
                          const float* __restrict__ B1e) {
    int g = blockIdx.x;
    int tid = threadIdx.x, warp = tid >> 5, lane = tid & 31;
    __shared__ float eas[8][16];
    __shared__ float red[DD];
    float4 wc[16];
#pragma unroll
    for (int k = 0; k < 16; k++)
        wc[k] = *reinterpret_cast<const float4*>(&W1e[k * DD + lane * 4]);
    float4 b4 = *reinterpret_cast<const float4*>(&B1e[lane * 4]);
    float4 acc = make_float4(0.f, 0.f, 0.f, 0.f);
    int jb = g_egptr[g], je = g_egptr[g + 1];
    for (int j = jb + warp; j < je; j += 8) {
        int e = g_egedge[j];
        if (lane < 16) eas[warp][lane] = EA[(long long)e * DEE + lane];
        __syncwarp();
        float4 h = b4;
#pragma unroll
        for (int k = 0; k < 16; k++) {
            float a = eas[warp][k];
            h.x = fmaf(a, wc[k].x, h.x);
            h.y = fmaf(a, wc[k].y, h.y);
            h.z = fmaf(a, wc[k].z, h.z);
            h.w = fmaf(a, wc[k].w, h.w);
        }
        acc.x += fmaxf(h.x, 0.f);
        acc.y += fmaxf(h.y, 0.f);
        acc.z += fmaxf(h.z, 0.f);
        acc.w += fmaxf(h.w, 0.f);
        __syncwarp();
    }
    if (tid < DD) red[tid] = 0.f;
    __syncthreads();
    int f = lane * 4;
    atomicAdd(&red[f + 0], acc.x);
    atomicAdd(&red[f + 1], acc.y);
    atomicAdd(&red[f + 2], acc.z);
    atomicAdd(&red[f + 3], acc.w);
    __syncthreads();
    if (tid < DD) g_hsum[g * DD + tid] = red[tid];
}

// ---------------- final combine -------------------------------------------------------
__global__ void k_final(const float* __restrict__ We2, const float* __restrict__ be2,
                        float* __restrict__ out) {
    int g = blockIdx.x;
    int t = threadIdx.x;   // 128
    __shared__ float hm[DD];
    int ec = g_egptr[g + 1] - g_egptr[g];
    float inv_e = (ec > 0) ? (1.f / (float)ec) : 0.f;
    hm[t] = g_hsum[g * DD + t] * inv_e;
    __syncthreads();
    float acc = be2[t];
#pragma unroll 4
    for (int k = 0; k < DD; k++)
        acc = fmaf(hm[k], We2[k * DD + t], acc);
    if (ec == 0) acc = 0.f;
    int nc = g_ncnt[g];
    float gr = g_nsum[g * DD + t] / fmaxf((float)nc, 1.f);
    out[g * DD + t] = gr + acc;
}

// ---------------- launch ----------------------------------------------------------------
extern "C" void kernel_launch(void* const* d_in, const int* in_sizes, int n_in,
                              void* d_out, int out_size) {
    // Resolve pointers by size signature (robust to num_graphs slot & ordering drift).
    const float* x = 0;  const void* ei = 0;  const void* batch = 0;  const float* ea = 0;
    const float* w16k[3] = {0, 0, 0};   // W1, W2, We2 (in metadata order)
    const float* v128[12] = {0};        // b1,g1,bt1,m1,v1,b2,g2,bt2,m2,v2,be1,be2
    const float* We1 = 0;
    int n16k = 0, n128 = 0;
    for (int i = 0; i < n_in; i++) {
        long long sz = in_sizes[i];
        if      (sz == (long long)NN * DD) { if (!x) x = (const float*)d_in[i]; }
        else if (sz == 2LL * EE)           { if (!ei) ei = d_in[i]; }
        else if (sz == NN)                 { if (!batch) batch = d_in[i]; }
        else if (sz == (long long)EE * DEE){ if (!ea) ea = (const float*)d_in[i]; }
        else if (sz == DD * DD)            { if (n16k < 3) w16k[n16k++] = (const float*)d_in[i]; }
        else if (sz == DEE * DD)           { if (!We1) We1 = (const float*)d_in[i]; }
        else if (sz == DD)                 { if (n128 < 12) v128[n128++] = (const float*)d_in[i]; }
    }
    const float *W1 = w16k[0], *W2 = w16k[1], *We2 = w16k[2];
    const float *b1 = v128[0], *g1 = v128[1], *bt1 = v128[2], *m1 = v128[3], *v1 = v128[4];
    const float *b2 = v128[5], *g2 = v128[6], *bt2 = v128[7], *m2 = v128[8], *v2 = v128[9];
    const float *be1 = v128[10], *be2 = v128[11];
    float* out = (float*)d_out;

    const int nb1 = (NN + 1023) / 1024;   // 98

    k_detect<<<1, 256>>>((const int*)ei);
    k_init<<<256, 256>>>();
    k_hist_edges<<<(EE + 255) / 256, 256>>>(ei, batch);
    k_hist_nodes<<<(NN + 255) / 256, 256>>>(batch);
    k_scan1<<<nb1, 1024>>>();
    k_scan2<<<1, 128>>>(nb1);
    k_scan3<<<nb1, 1024>>>();
    k_scanG<<<1, 512>>>();
    k_scatter<<<(EE + 255) / 256, 256>>>(ei);

    // layer 1: g_bufA = x @ W1 ; g_bufB = BN(ReLU(gather(g_bufA)))
    k_gemm<true><<<(NN + 63) / 64, 256>>>(x, W1, NN);
    k_gather<<<(NN * 32 + 255) / 256, 256>>>(b1, g1, bt1, m1, v1);
    // layer 2
    k_gemm<false><<<(NN + 63) / 64, 256>>>(x, W2, NN);
    k_gather<<<(NN * 32 + 255) / 256, 256>>>(b2, g2, bt2, m2, v2);
    // pooling
    k_pool<<<(NN * 32 + 255) / 256, 256>>>(batch);
    // edge branch
    k_edgemlp<<<GG, 256>>>(ea, We1, be1);
    // combine
    k_final<<<GG, 128>>>(We2, be2, out);
}

// round 5
// speedup vs baseline: 1.0327x; 1.0327x over previous
#include <cuda_runtime.h>

#define NN 100000
#define DD 128
#define EE 1600000
#define DEE 16
#define GG 512
#define BN_EPS 1e-5f

typedef unsigned long long u64;

// ---------------- f32x2 packed helpers -----------------------------------------
__device__ __forceinline__ void ffma2(u64& d, u64 a, u64 b) {
    asm("fma.rn.f32x2 %0, %1, %2, %0;" : "+l"(d) : "l"(a), "l"(b));
}
__device__ __forceinline__ u64 pack_dup(float x) {
    u64 d; unsigned xi = __float_as_uint(x);
    asm("mov.b64 %0, {%1, %1};" : "=l"(d) : "r"(xi));
    return d;
}
__device__ __forceinline__ float2 unpack2(u64 v) {
    unsigned lo, hi;
    asm("mov.b64 {%0, %1}, %2;" : "=r"(lo), "=r"(hi) : "l"(v));
    return make_float2(__uint_as_float(lo), __uint_as_float(hi));
}

// ---------------- scratch (static device globals; no allocation) -----------------
__device__ __align__(16) float g_bufA[NN * DD];          // 51.2 MB
__device__ __align__(16) float g_bufB[NN * DD];          // 51.2 MB
__device__ int   g_deg[NN];
__device__ int   g_rowptr[NN + 1];
__device__ int   g_curn[NN];
__device__ int   g_csrsrc[EE];
__device__ int   g_ge[EE];
__device__ int   g_egcnt[GG];
__device__ int   g_egptr[GG + 1];
__device__ int   g_curg[GG];
__device__ int   g_egedge[EE];
__device__ int   g_ncnt[GG];
__device__ float g_dinv[NN];
__device__ float g_nsum[GG * DD];
__device__ float g_hsum[GG * DD];
__device__ int   g_blksums[128];
__device__ int   g_is64;

// ---------------- index helpers (dtype-agnostic) ----------------------------------
__device__ __forceinline__ int load_idx(const void* p, long long i) {
    if (g_is64) return (int)((const long long*)p)[i];
    return ((const int*)p)[i];
}
__device__ __forceinline__ int clampi(int v, int lo, int hi) {
    return v < lo ? lo : (v > hi ? hi : v);
}

// ---------------- dtype detection: int64 values <2^31 have zero odd words ----------
__global__ void k_detect(const int* __restrict__ w) {
    __shared__ int ok;
    if (threadIdx.x == 0) ok = 1;
    __syncthreads();
    int bad = 0;
    for (int i = threadIdx.x; i < 2048; i += blockDim.x)
        if (w[2 * i + 1] != 0) bad = 1;
    if (bad) atomicAnd(&ok, 0);
    __syncthreads();
    if (threadIdx.x == 0) g_is64 = ok;
}

// ---------------- init: zero accumulators/histograms --------------------------------
__global__ void k_init() {
    int i = blockIdx.x * blockDim.x + threadIdx.x;
    int stride = gridDim.x * blockDim.x;
    for (int j = i; j < NN; j += stride) g_deg[j] = 0;
    for (int j = i; j < GG; j += stride) { g_egcnt[j] = 0; g_ncnt[j] = 0; }
    for (int j = i; j < GG * DD; j += stride) { g_nsum[j] = 0.f; g_hsum[j] = 0.f; }
}

// ---------------- histograms ----------------------------------------------------------
__global__ void k_hist_edges(const void* __restrict__ ei,
                             const void* __restrict__ batch) {
    int e = blockIdx.x * blockDim.x + threadIdx.x;
    if (e >= EE) return;
    int s = clampi(load_idx(ei, e), 0, NN - 1);
    int d = clampi(load_idx(ei, (long long)EE + e), 0, NN - 1);
    atomicAdd(&g_deg[d], 1);
    int g = clampi(load_idx(batch, s), 0, GG - 1);
    g_ge[e] = g;
    atomicAdd(&g_egcnt[g], 1);
}

__global__ void k_hist_nodes(const void* __restrict__ batch) {
    int i = blockIdx.x * blockDim.x + threadIdx.x;
    if (i >= NN) return;
    int g = clampi(load_idx(batch, i), 0, GG - 1);
    atomicAdd(&g_ncnt[g], 1);
}

// ---------------- 3-phase exclusive scan over g_deg -> g_rowptr -----------------------
__global__ void k_scan1() {
    __shared__ int s[1024];
    int b = blockIdx.x, t = threadIdx.x;
    int i = b * 1024 + t;
    int v = (i < NN) ? g_deg[i] : 0;
    s[t] = v;
    __syncthreads();
    for (int off = 1; off < 1024; off <<= 1) {
        int x = (t >= off) ? s[t - off] : 0;
        __syncthreads();
        s[t] += x;
        __syncthreads();
    }
    if (i < NN) g_rowptr[i] = s[t] - v;
    if (t == 1023) g_blksums[b] = s[t];
}

__global__ void k_scan2(int nb) {
    __shared__ int s[128];
    int t = threadIdx.x;
    int v = (t < nb) ? g_blksums[t] : 0;
    s[t] = v;
    __syncthreads();
    for (int off = 1; off < 128; off <<= 1) {
        int x = (t >= off) ? s[t - off] : 0;
        __syncthreads();
        s[t] += x;
        __syncthreads();
    }
    g_blksums[t] = s[t] - v;
}

__global__ void k_scan3() {
    int b = blockIdx.x, t = threadIdx.x;
    int i = b * 1024 + t;
    if (i < NN) {
        int rp = g_rowptr[i] + g_blksums[b];
        g_rowptr[i] = rp;
        g_curn[i] = rp;
        g_dinv[i] = rsqrtf((float)(g_deg[i] + 1));   // +1 = self-loop
    }
    if (i == 0) g_rowptr[NN] = EE;
}

__global__ void k_scanG() {
    __shared__ int s[512];
    int t = threadIdx.x;
    int v = g_egcnt[t];
    s[t] = v;
    __syncthreads();
    for (int off = 1; off < 512; off <<= 1) {
        int x = (t >= off) ? s[t - off] : 0;
        __syncthreads();
        s[t] += x;
        __syncthreads();
    }
    int p = s[t] - v;
    g_egptr[t] = p;
    g_curg[t] = p;
    if (t == 0) g_egptr[GG] = EE;
}

// ---------------- CSR scatter ------------------------------------------------------------
__global__ void k_scatter(const void* __restrict__ ei) {
    int e = blockIdx.x * blockDim.x + threadIdx.x;
    if (e >= EE) return;
    int s = clampi(load_idx(ei, e), 0, NN - 1);
    int d = clampi(load_idx(ei, (long long)EE + e), 0, NN - 1);
    int p = atomicAdd(&g_curn[d], 1);
    if (p >= 0 && p < EE) g_csrsrc[p] = s;
    int g = g_ge[e];
    int p2 = atomicAdd(&g_curg[g], 1);
    if (p2 >= 0 && p2 < EE) g_egedge[p2] = e;
}

// ---------------- GEMM (FFMA2): g_bufA = X @ W ---------------------------------------------
// block: 256 threads, 64 rows x 128 cols. thread: 4 rows x 8 cols (4 col-pairs, f32x2).
template <bool FIRST>
__global__ void k_gemm(const float* __restrict__ Xext, const float* __restrict__ W,
                       int nrows) {
    const float* __restrict__ X = FIRST ? Xext : (const float*)g_bufB;
    float* __restrict__ Y = g_bufA;
    __shared__ __align__(16) float xs[32][64];    // transposed: xs[k][row]
    __shared__ __align__(16) float ws[32][128];
    int tid = threadIdx.x;
    int c = tid & 15;   // cols c*8 .. c*8+7
    int r = tid >> 4;   // rows r*4 .. r*4+3
    int row0 = blockIdx.x * 64;

    u64 acc2[4][4];
#pragma unroll
    for (int i = 0; i < 4; i++)
#pragma unroll
        for (int j = 0; j < 4; j++) acc2[i][j] = 0ull;

    for (int kc = 0; kc < 128; kc += 32) {
#pragma unroll
        for (int l = 0; l < 8; l++) {
            int idx = tid + l * 256;       // 2048 elems
            int rr = idx >> 5;
            int kk = idx & 31;
            int grow = row0 + rr;
            float v = 0.f;
            if (grow < nrows) v = X[grow * DD + kc + kk];
            xs[kk][rr] = v;
        }
#pragma unroll
        for (int l = 0; l < 16; l++) {
            int idx = tid + l * 256;       // 4096 elems
            int kk = idx >> 7;
            int cc = idx & 127;
            ws[kk][cc] = W[(kc + kk) * DD + cc];
        }
        __syncthreads();
#pragma unroll
        for (int k = 0; k < 32; k++) {
            float4 xv = *reinterpret_cast<float4*>(&xs[k][r * 4]);
            ulonglong2 w01 = *reinterpret_cast<ulonglong2*>(&ws[k][c * 8]);
            ulonglong2 w23 = *reinterpret_cast<ulonglong2*>(&ws[k][c * 8 + 4]);
            u64 wp[4] = {w01.x, w01.y, w23.x, w23.y};
            u64 xr2[4] = {pack_dup(xv.x), pack_dup(xv.y), pack_dup(xv.z), pack_dup(xv.w)};
#pragma unroll
            for (int i = 0; i < 4; i++)
#pragma unroll
                for (int j = 0; j < 4; j++)
                    ffma2(acc2[i][j], xr2[i], wp[j]);
        }
        __syncthreads();
    }
#pragma unroll
    for (int i = 0; i < 4; i++) {
        int grow = row0 + r * 4 + i;
        if (grow < nrows) {
            float2 p0 = unpack2(acc2[i][0]);
            float2 p1 = unpack2(acc2[i][1]);
            float2 p2 = unpack2(acc2[i][2]);
            float2 p3 = unpack2(acc2[i][3]);
            float4 o0 = make_float4(p0.x, p0.y, p1.x, p1.y);
            float4 o1 = make_float4(p2.x, p2.y, p3.x, p3.y);
            *reinterpret_cast<float4*>(&Y[grow * DD + c * 8]) = o0;
            *reinterpret_cast<float4*>(&Y[grow * DD + c * 8 + 4]) = o1;
        }
    }
}

// ---------------- gather + bias + BN(eval) + ReLU (+ optional fused pool) --------------------
template <bool POOL>
__global__ void k_gather(const float* __restrict__ B, const float* __restrict__ GA,
                         const float* __restrict__ BT, const float* __restrict__ M,
                         const float* __restrict__ V, const void* __restrict__ batch) {
    int warp = (blockIdx.x * blockDim.x + threadIdx.x) >> 5;
    int lane = threadIdx.x & 31;
    if (warp >= NN) return;
    int node = warp;
    float di = g_dinv[node];
    const float4* xw4 = reinterpret_cast<const float4*>((const float*)g_bufA);
    float4 a = xw4[node * 32 + lane];
    float w0 = di * di;
    float4 acc;
    acc.x = a.x * w0; acc.y = a.y * w0; acc.z = a.z * w0; acc.w = a.w * w0;
    int jb = g_rowptr[node], je = g_rowptr[node + 1];
    for (int j = jb; j < je; j++) {
        int s = g_csrsrc[j];
        float w = g_dinv[s] * di;
        float4 v4 = xw4[s * 32 + lane];
        acc.x = fmaf(v4.x, w, acc.x);
        acc.y = fmaf(v4.y, w, acc.y);
        acc.z = fmaf(v4.z, w, acc.z);
        acc.w = fmaf(v4.w, w, acc.w);
    }
    int f = lane * 4;
    float4 b4  = *reinterpret_cast<const float4*>(&B[f]);
    float4 g4  = *reinterpret_cast<const float4*>(&GA[f]);
    float4 bt4 = *reinterpret_cast<const float4*>(&BT[f]);
    float4 m4  = *reinterpret_cast<const float4*>(&M[f]);
    float4 vv4 = *reinterpret_cast<const float4*>(&V[f]);
    float4 o;
    o.x = fmaxf((acc.x + b4.x - m4.x) * rsqrtf(vv4.x + BN_EPS) * g4.x + bt4.x, 0.f);
    o.y = fmaxf((acc.y + b4.y - m4.y) * rsqrtf(vv4.y + BN_EPS) * g4.y + bt4.y, 0.f);
    o.z = fmaxf((acc.z + b4.z - m4.z) * rsqrtf(vv4.z + BN_EPS) * g4.z + bt4.z, 0.f);
    o.w = fmaxf((acc.w + b4.w - m4.w) * rsqrtf(vv4.w + BN_EPS) * g4.w + bt4.w, 0.f);
    float4* out4 = reinterpret_cast<float4*>((float*)g_bufB);
    out4[node * 32 + lane] = o;
    if (POOL) {
        int g = clampi(load_idx(batch, node), 0, GG - 1);
        int base = g * DD + f;
        atomicAdd(&g_nsum[base + 0], o.x);
        atomicAdd(&g_nsum[base + 1], o.y);
        atomicAdd(&g_nsum[base + 2], o.z);
        atomicAdd(&g_nsum[base + 3], o.w);
    }
}

// ---------------- edge MLP first layer, summed per graph (FFMA2, 4 blocks/graph) --------------
#define EBLK 4
__global__ void k_edgemlp(const float* __restrict__ EA, const float* __restrict__ W1e,
                          const float* __restrict__ B1e) {
    int g = blockIdx.x >> 2;          // graph
    int q = blockIdx.x & (EBLK - 1);  // quarter
    int tid = threadIdx.x, warp = tid >> 5, lane = tid & 31;
    __shared__ float eas[8][16];
    __shared__ float red[DD];
    ulonglong2 wc[16];                // two f32x2 pairs per k (4 output cols)
#pragma unroll
    for (int k = 0; k < 16; k++)
        wc[k] = *reinterpret_cast<const ulonglong2*>(&W1e[k * DD + lane * 4]);
    ulonglong2 b2 = *reinterpret_cast<const ulonglong2*>(&B1e[lane * 4]);

    int gb = g_egptr[g], ge = g_egptr[g + 1];
    int cnt = ge - gb;
    int per = (cnt + EBLK - 1) / EBLK;
    int jb = gb + q * per;
    int je = min(jb + per, ge);

    float4 acc = make_float4(0.f, 0.f, 0.f, 0.f);
    for (int j = jb + warp; j < je; j += 8) {
        int e = g_egedge[j];
        if (lane < 16) eas[warp][lane] = EA[(long long)e * DEE + lane];
        __syncwarp();
        u64 h0 = b2.x, h1 = b2.y;
#pragma unroll
        for (int k = 0; k < 16; k++) {
            u64 a2 = pack_dup(eas[warp][k]);
            ffma2(h0, a2, wc[k].x);
            ffma2(h1, a2, wc[k].y);
        }
        float2 u0 = unpack2(h0), u1 = unpack2(h1);
        acc.x += fmaxf(u0.x, 0.f);
        acc.y += fmaxf(u0.y, 0.f);
        acc.z += fmaxf(u1.x, 0.f);
        acc.w += fmaxf(u1.y, 0.f);
        __syncwarp();
    }
    if (tid < DD) red[tid] = 0.f;
    __syncthreads();
    int f = lane * 4;
    atomicAdd(&red[f + 0], acc.x);
    atomicAdd(&red[f + 1], acc.y);
    atomicAdd(&red[f + 2], acc.z);
    atomicAdd(&red[f + 3], acc.w);
    __syncthreads();
    if (tid < DD) atomicAdd(&g_hsum[g * DD + tid], red[tid]);
}

// ---------------- final combine ---------------------------------------------------------------
__global__ void k_final(const float* __restrict__ We2, const float* __restrict__ be2,
                        float* __restrict__ out) {
    int g = blockIdx.x;
    int t = threadIdx.x;   // 128
    __shared__ float hm[DD];
    int ec = g_egptr[g + 1] - g_egptr[g];
    float inv_e = (ec > 0) ? (1.f / (float)ec) : 0.f;
    hm[t] = g_hsum[g * DD + t] * inv_e;
    __syncthreads();
    float acc = be2[t];
#pragma unroll 4
    for (int k = 0; k < DD; k++)
        acc = fmaf(hm[k], We2[k * DD + t], acc);
    if (ec == 0) acc = 0.f;
    int nc = g_ncnt[g];
    float gr = g_nsum[g * DD + t] / fmaxf((float)nc, 1.f);
    out[g * DD + t] = gr + acc;
}

// ---------------- launch ------------------------------------------------------------------------
extern "C" void kernel_launch(void* const* d_in, const int* in_sizes, int n_in,
                              void* d_out, int out_size) {
    // Resolve pointers by size signature (robust to num_graphs slot & ordering drift).
    const float* x = 0;  const void* ei = 0;  const void* batch = 0;  const float* ea = 0;
    const float* w16k[3] = {0, 0, 0};   // W1, W2, We2 (in metadata order)
    const float* v128[12] = {0};        // b1,g1,bt1,m1,v1,b2,g2,bt2,m2,v2,be1,be2
    const float* We1 = 0;
    int n16k = 0, n128 = 0;
    for (int i = 0; i < n_in; i++) {
        long long sz = in_sizes[i];
        if      (sz == (long long)NN * DD) { if (!x) x = (const float*)d_in[i]; }
        else if (sz == 2LL * EE)           { if (!ei) ei = d_in[i]; }
        else if (sz == NN)                 { if (!batch) batch = d_in[i]; }
        else if (sz == (long long)EE * DEE){ if (!ea) ea = (const float*)d_in[i]; }
        else if (sz == DD * DD)            { if (n16k < 3) w16k[n16k++] = (const float*)d_in[i]; }
        else if (sz == DEE * DD)           { if (!We1) We1 = (const float*)d_in[i]; }
        else if (sz == DD)                 { if (n128 < 12) v128[n128++] = (const float*)d_in[i]; }
    }
    const float *W1 = w16k[0], *W2 = w16k[1], *We2 = w16k[2];
    const float *b1 = v128[0], *g1 = v128[1], *bt1 = v128[2], *m1 = v128[3], *v1 = v128[4];
    const float *b2 = v128[5], *g2 = v128[6], *bt2 = v128[7], *m2 = v128[8], *v2 = v128[9];
    const float *be1 = v128[10], *be2 = v128[11];
    float* out = (float*)d_out;

    const int nb1 = (NN + 1023) / 1024;   // 98

    k_detect<<<1, 256>>>((const int*)ei);
    k_init<<<256, 256>>>();
    k_hist_edges<<<(EE + 255) / 256, 256>>>(ei, batch);
    k_hist_nodes<<<(NN + 255) / 256, 256>>>(batch);
    k_scan1<<<nb1, 1024>>>();
    k_scan2<<<1, 128>>>(nb1);
    k_scan3<<<nb1, 1024>>>();
    k_scanG<<<1, 512>>>();
    k_scatter<<<(EE + 255) / 256, 256>>>(ei);

    // layer 1: g_bufA = x @ W1 ; g_bufB = BN(ReLU(gather(g_bufA)))
    k_gemm<true><<<(NN + 63) / 64, 256>>>(x, W1, NN);
    k_gather<false><<<(NN * 32 + 255) / 256, 256>>>(b1, g1, bt1, m1, v1, batch);
    // layer 2 (+ fused mean-pool accumulation)
    k_gemm<false><<<(NN + 63) / 64, 256>>>(x, W2, NN);
    k_gather<true><<<(NN * 32 + 255) / 256, 256>>>(b2, g2, bt2, m2, v2, batch);
    // edge branch (4 blocks per graph)
    k_edgemlp<<<GG * EBLK, 256>>>(ea, We1, be1);
    // combine
    k_final<<<GG, 128>>>(We2, be2, out);
}

// round 6
// speedup vs baseline: 1.1012x; 1.0663x over previous
#include <cuda_runtime.h>

#define NN 100000
#define DD 128
#define EE 1600000
#define DEE 16
#define GG 512
#define BN_EPS 1e-5f

typedef unsigned long long u64;

// ---------------- f32x2 packed helpers -----------------------------------------
__device__ __forceinline__ void ffma2(u64& d, u64 a, u64 b) {
    asm("fma.rn.f32x2 %0, %1, %2, %0;" : "+l"(d) : "l"(a), "l"(b));
}
__device__ __forceinline__ u64 pack_dup(float x) {
    u64 d; unsigned xi = __float_as_uint(x);
    asm("mov.b64 %0, {%1, %1};" : "=l"(d) : "r"(xi));
    return d;
}
__device__ __forceinline__ float2 unpack2(u64 v) {
    unsigned lo, hi;
    asm("mov.b64 {%0, %1}, %2;" : "=r"(lo), "=r"(hi) : "l"(v));
    return make_float2(__uint_as_float(lo), __uint_as_float(hi));
}

// ---------------- scratch (static device globals; no allocation) -----------------
__device__ __align__(16) float g_bufA[NN * DD];          // 51.2 MB
__device__ __align__(16) float g_bufB[NN * DD];          // 51.2 MB
__device__ int   g_deg[NN];
__device__ int   g_rowptr[NN + 1];
__device__ int   g_curn[NN];
__device__ int   g_csrsrc[EE];
__device__ int   g_ge[EE];
__device__ int   g_egcnt[GG];
__device__ int   g_egptr[GG + 1];
__device__ int   g_curg[GG];
__device__ int   g_egedge[EE];
__device__ int   g_ncnt[GG];
__device__ float g_dinv[NN];
__device__ float g_nsum[GG * DD];
__device__ float g_hsum[GG * DD];
__device__ int   g_blksums[128];
__device__ int   g_is64;

// ---------------- index helpers (dtype-agnostic) ----------------------------------
__device__ __forceinline__ int load_idx(const void* p, long long i) {
    if (g_is64) return (int)((const long long*)p)[i];
    return ((const int*)p)[i];
}
__device__ __forceinline__ int clampi(int v, int lo, int hi) {
    return v < lo ? lo : (v > hi ? hi : v);
}

// ---------------- dtype detection: int64 values <2^31 have zero odd words ----------
__global__ void k_detect(const int* __restrict__ w) {
    __shared__ int ok;
    if (threadIdx.x == 0) ok = 1;
    __syncthreads();
    int bad = 0;
    for (int i = threadIdx.x; i < 2048; i += blockDim.x)
        if (w[2 * i + 1] != 0) bad = 1;
    if (bad) atomicAnd(&ok, 0);
    __syncthreads();
    if (threadIdx.x == 0) g_is64 = ok;
}

// ---------------- init: zero accumulators/histograms --------------------------------
__global__ void k_init() {
    int i = blockIdx.x * blockDim.x + threadIdx.x;
    int stride = gridDim.x * blockDim.x;
    for (int j = i; j < NN; j += stride) g_deg[j] = 0;
    for (int j = i; j < GG; j += stride) { g_egcnt[j] = 0; g_ncnt[j] = 0; }
    for (int j = i; j < GG * DD; j += stride) { g_nsum[j] = 0.f; g_hsum[j] = 0.f; }
}

// ---------------- histograms ----------------------------------------------------------
__global__ void k_hist_edges(const void* __restrict__ ei,
                             const void* __restrict__ batch) {
    int e = blockIdx.x * blockDim.x + threadIdx.x;
    if (e >= EE) return;
    int s = clampi(load_idx(ei, e), 0, NN - 1);
    int d = clampi(load_idx(ei, (long long)EE + e), 0, NN - 1);
    atomicAdd(&g_deg[d], 1);
    int g = clampi(load_idx(batch, s), 0, GG - 1);
    g_ge[e] = g;
    atomicAdd(&g_egcnt[g], 1);
}

__global__ void k_hist_nodes(const void* __restrict__ batch) {
    int i = blockIdx.x * blockDim.x + threadIdx.x;
    if (i >= NN) return;
    int g = clampi(load_idx(batch, i), 0, GG - 1);
    atomicAdd(&g_ncnt[g], 1);
}

// ---------------- 3-phase exclusive scan over g_deg -> g_rowptr -----------------------
__global__ void k_scan1() {
    __shared__ int s[1024];
    int b = blockIdx.x, t = threadIdx.x;
    int i = b * 1024 + t;
    int v = (i < NN) ? g_deg[i] : 0;
    s[t] = v;
    __syncthreads();
    for (int off = 1; off < 1024; off <<= 1) {
        int x = (t >= off) ? s[t - off] : 0;
        __syncthreads();
        s[t] += x;
        __syncthreads();
    }
    if (i < NN) g_rowptr[i] = s[t] - v;
    if (t == 1023) g_blksums[b] = s[t];
}

__global__ void k_scan2(int nb) {
    __shared__ int s[128];
    int t = threadIdx.x;
    int v = (t < nb) ? g_blksums[t] : 0;
    s[t] = v;
    __syncthreads();
    for (int off = 1; off < 128; off <<= 1) {
        int x = (t >= off) ? s[t - off] : 0;
        __syncthreads();
        s[t] += x;
        __syncthreads();
    }
    g_blksums[t] = s[t] - v;
}

__global__ void k_scan3() {
    int b = blockIdx.x, t = threadIdx.x;
    int i = b * 1024 + t;
    if (i < NN) {
        int rp = g_rowptr[i] + g_blksums[b];
        g_rowptr[i] = rp;
        g_curn[i] = rp;
        g_dinv[i] = rsqrtf((float)(g_deg[i] + 1));   // +1 = self-loop
    }
    if (i == 0) g_rowptr[NN] = EE;
}

__global__ void k_scanG() {
    __shared__ int s[512];
    int t = threadIdx.x;
    int v = g_egcnt[t];
    s[t] = v;
    __syncthreads();
    for (int off = 1; off < 512; off <<= 1) {
        int x = (t >= off) ? s[t - off] : 0;
        __syncthreads();
        s[t] += x;
        __syncthreads();
    }
    int p = s[t] - v;
    g_egptr[t] = p;
    g_curg[t] = p;
    if (t == 0) g_egptr[GG] = EE;
}

// ---------------- CSR scatter ------------------------------------------------------------
__global__ void k_scatter(const void* __restrict__ ei) {
    int e = blockIdx.x * blockDim.x + threadIdx.x;
    if (e >= EE) return;
    int s = clampi(load_idx(ei, e), 0, NN - 1);
    int d = clampi(load_idx(ei, (long long)EE + e), 0, NN - 1);
    int p = atomicAdd(&g_curn[d], 1);
    if (p >= 0 && p < EE) g_csrsrc[p] = s;
    int g = g_ge[e];
    int p2 = atomicAdd(&g_curg[g], 1);
    if (p2 >= 0 && p2 < EE) g_egedge[p2] = e;
}

// ---------------- scale g_bufA rows by dinv (layer-1 only) --------------------------------
__global__ void k_scale() {
    int i = blockIdx.x * blockDim.x + threadIdx.x;   // over NN*32 float4
    if (i >= NN * 32) return;
    int node = i >> 5;
    float4* p = reinterpret_cast<float4*>((float*)g_bufA);
    float4 v = p[i];
    float d = g_dinv[node];
    v.x *= d; v.y *= d; v.z *= d; v.w *= d;
    p[i] = v;
}

// ---------------- GEMM (FFMA2): g_bufA = X @ W  [optionally row-scaled by dinv] -------------
// block: 256 threads, 64 rows x 128 cols. thread: 4 rows x 8 cols (4 col-pairs, f32x2).
template <bool FIRST, bool SCALE>
__global__ void k_gemm(const float* __restrict__ Xext, const float* __restrict__ W,
                       int nrows) {
    const float* __restrict__ X = FIRST ? Xext : (const float*)g_bufB;
    float* __restrict__ Y = g_bufA;
    __shared__ __align__(16) float xs[32][64];    // transposed: xs[k][row]
    __shared__ __align__(16) float ws[32][128];
    int tid = threadIdx.x;
    int c = tid & 15;   // cols c*8 .. c*8+7
    int r = tid >> 4;   // rows r*4 .. r*4+3
    int row0 = blockIdx.x * 64;

    u64 acc2[4][4];
#pragma unroll
    for (int i = 0; i < 4; i++)
#pragma unroll
        for (int j = 0; j < 4; j++) acc2[i][j] = 0ull;

    for (int kc = 0; kc < 128; kc += 32) {
#pragma unroll
        for (int l = 0; l < 8; l++) {
            int idx = tid + l * 256;       // 2048 elems
            int rr = idx >> 5;
            int kk = idx & 31;
            int grow = row0 + rr;
            float v = 0.f;
            if (grow < nrows) v = X[grow * DD + kc + kk];
            xs[kk][rr] = v;
        }
#pragma unroll
        for (int l = 0; l < 16; l++) {
            int idx = tid + l * 256;       // 4096 elems
            int kk = idx >> 7;
            int cc = idx & 127;
            ws[kk][cc] = W[(kc + kk) * DD + cc];
        }
        __syncthreads();
#pragma unroll
        for (int k = 0; k < 32; k++) {
            float4 xv = *reinterpret_cast<float4*>(&xs[k][r * 4]);
            ulonglong2 w01 = *reinterpret_cast<ulonglong2*>(&ws[k][c * 8]);
            ulonglong2 w23 = *reinterpret_cast<ulonglong2*>(&ws[k][c * 8 + 4]);
            u64 wp[4] = {w01.x, w01.y, w23.x, w23.y};
            u64 xr2[4] = {pack_dup(xv.x), pack_dup(xv.y), pack_dup(xv.z), pack_dup(xv.w)};
#pragma unroll
            for (int i = 0; i < 4; i++)
#pragma unroll
                for (int j = 0; j < 4; j++)
                    ffma2(acc2[i][j], xr2[i], wp[j]);
        }
        __syncthreads();
    }
#pragma unroll
    for (int i = 0; i < 4; i++) {
        int grow = row0 + r * 4 + i;
        if (grow < nrows) {
            float d = SCALE ? g_dinv[grow] : 1.f;
            float2 p0 = unpack2(acc2[i][0]);
            float2 p1 = unpack2(acc2[i][1]);
            float2 p2 = unpack2(acc2[i][2]);
            float2 p3 = unpack2(acc2[i][3]);
            float4 o0 = make_float4(p0.x * d, p0.y * d, p1.x * d, p1.y * d);
            float4 o1 = make_float4(p2.x * d, p2.y * d, p3.x * d, p3.y * d);
            *reinterpret_cast<float4*>(&Y[grow * DD + c * 8]) = o0;
            *reinterpret_cast<float4*>(&Y[grow * DD + c * 8 + 4]) = o1;
        }
    }
}

// ---------------- gather + bias + BN(eval) + ReLU (+ optional fused pool) --------------------
// g_bufA holds pre-scaled xw' = xw * dinv. result = di * (xw'[node] + sum xw'[nbr]).
template <bool POOL>
__global__ void k_gather(const float* __restrict__ B, const float* __restrict__ GA,
                         const float* __restrict__ BT, const float* __restrict__ M,
                         const float* __restrict__ V, const void* __restrict__ batch) {
    int warp = (blockIdx.x * blockDim.x + threadIdx.x) >> 5;
    int lane = threadIdx.x & 31;
    if (warp >= NN) return;
    int node = warp;
    float di = g_dinv[node];
    const float4* xw4 = reinterpret_cast<const float4*>((const float*)g_bufA);
    float4 a0 = xw4[node * 32 + lane];   // self term (already * dinv_node)
    float4 a1 = make_float4(0.f, 0.f, 0.f, 0.f);
    float4 a2 = make_float4(0.f, 0.f, 0.f, 0.f);
    float4 a3 = make_float4(0.f, 0.f, 0.f, 0.f);
    int jb = g_rowptr[node], je = g_rowptr[node + 1];
    int j = jb;
    for (; j + 3 < je; j += 4) {
        int s0 = g_csrsrc[j + 0];
        int s1 = g_csrsrc[j + 1];
        int s2 = g_csrsrc[j + 2];
        int s3 = g_csrsrc[j + 3];
        float4 v0 = xw4[s0 * 32 + lane];
        float4 v1 = xw4[s1 * 32 + lane];
        float4 v2 = xw4[s2 * 32 + lane];
        float4 v3 = xw4[s3 * 32 + lane];
        a0.x += v0.x; a0.y += v0.y; a0.z += v0.z; a0.w += v0.w;
        a1.x += v1.x; a1.y += v1.y; a1.z += v1.z; a1.w += v1.w;
        a2.x += v2.x; a2.y += v2.y; a2.z += v2.z; a2.w += v2.w;
        a3.x += v3.x; a3.y += v3.y; a3.z += v3.z; a3.w += v3.w;
    }
    for (; j < je; j++) {
        int s = g_csrsrc[j];
        float4 v = xw4[s * 32 + lane];
        a0.x += v.x; a0.y += v.y; a0.z += v.z; a0.w += v.w;
    }
    float4 acc;
    acc.x = (a0.x + a1.x) + (a2.x + a3.x);
    acc.y = (a0.y + a1.y) + (a2.y + a3.y);
    acc.z = (a0.z + a1.z) + (a2.z + a3.z);
    acc.w = (a0.w + a1.w) + (a2.w + a3.w);
    int f = lane * 4;
    float4 b4  = *reinterpret_cast<const float4*>(&B[f]);
    float4 g4  = *reinterpret_cast<const float4*>(&GA[f]);
    float4 bt4 = *reinterpret_cast<const float4*>(&BT[f]);
    float4 m4  = *reinterpret_cast<const float4*>(&M[f]);
    float4 vv4 = *reinterpret_cast<const float4*>(&V[f]);
    float4 o;
    o.x = fmaxf((acc.x * di + b4.x - m4.x) * rsqrtf(vv4.x + BN_EPS) * g4.x + bt4.x, 0.f);
    o.y = fmaxf((acc.y * di + b4.y - m4.y) * rsqrtf(vv4.y + BN_EPS) * g4.y + bt4.y, 0.f);
    o.z = fmaxf((acc.z * di + b4.z - m4.z) * rsqrtf(vv4.z + BN_EPS) * g4.z + bt4.z, 0.f);
    o.w = fmaxf((acc.w * di + b4.w - m4.w) * rsqrtf(vv4.w + BN_EPS) * g4.w + bt4.w, 0.f);
    float4* out4 = reinterpret_cast<float4*>((float*)g_bufB);
    out4[node * 32 + lane] = o;
    if (POOL) {
        int g = clampi(load_idx(batch, node), 0, GG - 1);
        int base = g * DD + f;
        atomicAdd(&g_nsum[base + 0], o.x);
        atomicAdd(&g_nsum[base + 1], o.y);
        atomicAdd(&g_nsum[base + 2], o.z);
        atomicAdd(&g_nsum[base + 3], o.w);
    }
}

// ---------------- edge MLP first layer, summed per graph (FFMA2, 2-edge ILP) -----------------
#define EBLK 4
__global__ void k_edgemlp(const float* __restrict__ EA, const float* __restrict__ W1e,
                          const float* __restrict__ B1e) {
    int g = blockIdx.x >> 2;          // graph
    int q = blockIdx.x & (EBLK - 1);  // quarter
    int tid = threadIdx.x, warp = tid >> 5, lane = tid & 31;
    __shared__ float eas[8][2][16];
    __shared__ float red[DD];
    ulonglong2 wc[16];                // two f32x2 pairs per k (4 output cols)
#pragma unroll
    for (int k = 0; k < 16; k++)
        wc[k] = *reinterpret_cast<const ulonglong2*>(&W1e[k * DD + lane * 4]);
    ulonglong2 b2 = *reinterpret_cast<const ulonglong2*>(&B1e[lane * 4]);

    int gb = g_egptr[g], ge = g_egptr[g + 1];
    int cnt = ge - gb;
    int per = (cnt + EBLK - 1) / EBLK;
    int jb = gb + q * per;
    int je = min(jb + per, ge);

    float4 acc = make_float4(0.f, 0.f, 0.f, 0.f);
    for (int j = jb + warp; j < je; j += 16) {
        int j2 = j + 8;
        bool has2 = (j2 < je);
        int e0 = g_egedge[j];
        int e1 = has2 ? g_egedge[j2] : e0;
        if (lane < 16) eas[warp][0][lane] = EA[(long long)e0 * DEE + lane];
        else           eas[warp][1][lane - 16] = EA[(long long)e1 * DEE + (lane - 16)];
        __syncwarp();
        u64 h0 = b2.x, h1 = b2.y, h2 = b2.x, h3 = b2.y;
#pragma unroll
        for (int k = 0; k < 16; k++) {
            u64 p0 = pack_dup(eas[warp][0][k]);
            u64 p1 = pack_dup(eas[warp][1][k]);
            ffma2(h0, p0, wc[k].x);
            ffma2(h1, p0, wc[k].y);
            ffma2(h2, p1, wc[k].x);
            ffma2(h3, p1, wc[k].y);
        }
        float2 u0 = unpack2(h0), u1 = unpack2(h1);
        acc.x += fmaxf(u0.x, 0.f);
        acc.y += fmaxf(u0.y, 0.f);
        acc.z += fmaxf(u1.x, 0.f);
        acc.w += fmaxf(u1.y, 0.f);
        if (has2) {
            float2 u2 = unpack2(h2), u3 = unpack2(h3);
            acc.x += fmaxf(u2.x, 0.f);
            acc.y += fmaxf(u2.y, 0.f);
            acc.z += fmaxf(u3.x, 0.f);
            acc.w += fmaxf(u3.y, 0.f);
        }
        __syncwarp();
    }
    if (tid < DD) red[tid] = 0.f;
    __syncthreads();
    int f = lane * 4;
    atomicAdd(&red[f + 0], acc.x);
    atomicAdd(&red[f + 1], acc.y);
    atomicAdd(&red[f + 2], acc.z);
    atomicAdd(&red[f + 3], acc.w);
    __syncthreads();
    if (tid < DD) atomicAdd(&g_hsum[g * DD + tid], red[tid]);
}

// ---------------- final combine ---------------------------------------------------------------
__global__ void k_final(const float* __restrict__ We2, const float* __restrict__ be2,
                        float* __restrict__ out) {
    int g = blockIdx.x;
    int t = threadIdx.x;   // 128
    __shared__ float hm[DD];
    int ec = g_egptr[g + 1] - g_egptr[g];
    float inv_e = (ec > 0) ? (1.f / (float)ec) : 0.f;
    hm[t] = g_hsum[g * DD + t] * inv_e;
    __syncthreads();
    float acc = be2[t];
#pragma unroll 4
    for (int k = 0; k < DD; k++)
        acc = fmaf(hm[k], We2[k * DD + t], acc);
    if (ec == 0) acc = 0.f;
    int nc = g_ncnt[g];
    float gr = g_nsum[g * DD + t] / fmaxf((float)nc, 1.f);
    out[g * DD + t] = gr + acc;
}

// ---------------- launch ------------------------------------------------------------------------
extern "C" void kernel_launch(void* const* d_in, const int* in_sizes, int n_in,
                              void* d_out, int out_size) {
    // Resolve pointers by size signature.
    const float* x = 0;  const void* ei = 0;  const void* batch = 0;  const float* ea = 0;
    const float* w16k[3] = {0, 0, 0};   // W1, W2, We2 (in metadata order)
    const float* v128[12] = {0};        // b1,g1,bt1,m1,v1,b2,g2,bt2,m2,v2,be1,be2
    const float* We1 = 0;
    int n16k = 0, n128 = 0;
    for (int i = 0; i < n_in; i++) {
        long long sz = in_sizes[i];
        if      (sz == (long long)NN * DD) { if (!x) x = (const float*)d_in[i]; }
        else if (sz == 2LL * EE)           { if (!ei) ei = d_in[i]; }
        else if (sz == NN)                 { if (!batch) batch = d_in[i]; }
        else if (sz == (long long)EE * DEE){ if (!ea) ea = (const float*)d_in[i]; }
        else if (sz == DD * DD)            { if (n16k < 3) w16k[n16k++] = (const float*)d_in[i]; }
        else if (sz == DEE * DD)           { if (!We1) We1 = (const float*)d_in[i]; }
        else if (sz == DD)                 { if (n128 < 12) v128[n128++] = (const float*)d_in[i]; }
    }
    const float *W1 = w16k[0], *W2 = w16k[1], *We2 = w16k[2];
    const float *b1 = v128[0], *g1 = v128[1], *bt1 = v128[2], *m1 = v128[3], *v1 = v128[4];
    const float *b2 = v128[5], *g2 = v128[6], *bt2 = v128[7], *m2 = v128[8], *v2 = v128[9];
    const float *be1 = v128[10], *be2 = v128[11];
    float* out = (float*)d_out;

    const int nb1 = (NN + 1023) / 1024;   // 98

    k_detect<<<1, 256>>>((const int*)ei);                       // 1
    k_init<<<256, 256>>>();                                     // 2
    k_hist_edges<<<(EE + 255) / 256, 256>>>(ei, batch);         // 3
    // layer-1 GEMM (depends only on x, W1) -- placed at launch #4 = ncu's profiled slot
    k_gemm<true, false><<<(NN + 63) / 64, 256>>>(x, W1, NN);    // 4  [profiled]
    k_hist_nodes<<<(NN + 255) / 256, 256>>>(batch);             // 5
    k_scan1<<<nb1, 1024>>>();
    k_scan2<<<1, 128>>>(nb1);
    k_scan3<<<nb1, 1024>>>();
    k_scanG<<<1, 512>>>();
    k_scatter<<<(EE + 255) / 256, 256>>>(ei);
    // pre-scale layer-1 xw by dinv (layer-2 GEMM fuses this into its epilogue)
    k_scale<<<(NN * 32 + 255) / 256, 256>>>();

    // layer 1 aggregate: g_bufB = BN(ReLU(di * (sum of scaled rows)))
    k_gather<false><<<(NN * 32 + 255) / 256, 256>>>(b1, g1, bt1, m1, v1, batch);
    // layer 2 (GEMM output pre-scaled by dinv; gather fuses mean-pool accumulation)
    k_gemm<false, true><<<(NN + 63) / 64, 256>>>(x, W2, NN);
    k_gather<true><<<(NN * 32 + 255) / 256, 256>>>(b2, g2, bt2, m2, v2, batch);
    // edge branch (4 blocks per graph, 2-edge ILP)
    k_edgemlp<<<GG * EBLK, 256>>>(ea, We1, be1);
    // combine
    k_final<<<GG, 128>>>(We2, be2, out);
}

// round 7
// speedup vs baseline: 1.2835x; 1.1655x over previous
#include <cuda_runtime.h>

#define NN 100000
#define DD 128
#define EE 1600000
#define DEE 16
#define GG 512
#define BN_EPS 1e-5f

typedef unsigned long long u64;

// ---------------- f32x2 packed helpers -----------------------------------------
__device__ __forceinline__ void ffma2(u64& d, u64 a, u64 b) {
    asm("fma.rn.f32x2 %0, %1, %2, %0;" : "+l"(d) : "l"(a), "l"(b));
}
__device__ __forceinline__ u64 pack_dup(float x) {
    u64 d; unsigned xi = __float_as_uint(x);
    asm("mov.b64 %0, {%1, %1};" : "=l"(d) : "r"(xi));
    return d;
}
__device__ __forceinline__ float2 unpack2(u64 v) {
    unsigned lo, hi;
    asm("mov.b64 {%0, %1}, %2;" : "=r"(lo), "=r"(hi) : "l"(v));
    return make_float2(__uint_as_float(lo), __uint_as_float(hi));
}

// ---------------- scratch (static device globals; no allocation) -----------------
__device__ __align__(16) float g_bufA[NN * DD];          // 51.2 MB
__device__ __align__(16) float g_bufB[NN * DD];          // 51.2 MB
__device__ int   g_deg[NN];
__device__ int   g_rowptr[NN + 1];
__device__ int   g_curn[NN];
__device__ int   g_csrsrc[EE];
__device__ int   g_ge[EE];
__device__ int   g_egcnt[GG];
__device__ int   g_egptr[GG + 1];
__device__ int   g_curg[GG];
__device__ int   g_egedge[EE];
__device__ int   g_ncnt[GG];
__device__ float g_dinv[NN];
__device__ float g_nsum[GG * DD];
__device__ float g_hsum[GG * DD];
__device__ int   g_blksums[128];
__device__ int   g_is64;

// ---------------- index helpers (dtype-agnostic) ----------------------------------
__device__ __forceinline__ int load_idx(const void* p, long long i) {
    if (g_is64) return (int)((const long long*)p)[i];
    return ((const int*)p)[i];
}
__device__ __forceinline__ int clampi(int v, int lo, int hi) {
    return v < lo ? lo : (v > hi ? hi : v);
}

// ---------------- dtype detection: int64 values <2^31 have zero odd words ----------
__global__ void k_detect(const int* __restrict__ w) {
    __shared__ int ok;
    if (threadIdx.x == 0) ok = 1;
    __syncthreads();
    int bad = 0;
    for (int i = threadIdx.x; i < 2048; i += blockDim.x)
        if (w[2 * i + 1] != 0) bad = 1;
    if (bad) atomicAnd(&ok, 0);
    __syncthreads();
    if (threadIdx.x == 0) g_is64 = ok;
}

// ---------------- init: zero accumulators/histograms --------------------------------
__global__ void k_init() {
    int i = blockIdx.x * blockDim.x + threadIdx.x;
    int stride = gridDim.x * blockDim.x;
    for (int j = i; j < NN; j += stride) g_deg[j] = 0;
    for (int j = i; j < GG; j += stride) { g_egcnt[j] = 0; g_ncnt[j] = 0; }
    for (int j = i; j < GG * DD; j += stride) { g_nsum[j] = 0.f; g_hsum[j] = 0.f; }
}

// ---------------- histograms ----------------------------------------------------------
__global__ void k_hist_edges(const void* __restrict__ ei,
                             const void* __restrict__ batch) {
    int e = blockIdx.x * blockDim.x + threadIdx.x;
    if (e >= EE) return;
    int s = clampi(load_idx(ei, e), 0, NN - 1);
    int d = clampi(load_idx(ei, (long long)EE + e), 0, NN - 1);
    atomicAdd(&g_deg[d], 1);
    int g = clampi(load_idx(batch, s), 0, GG - 1);
    g_ge[e] = g;
    atomicAdd(&g_egcnt[g], 1);
}

__global__ void k_hist_nodes(const void* __restrict__ batch) {
    int i = blockIdx.x * blockDim.x + threadIdx.x;
    if (i >= NN) return;
    int g = clampi(load_idx(batch, i), 0, GG - 1);
    atomicAdd(&g_ncnt[g], 1);
}

// ---------------- 3-phase exclusive scan over g_deg -> g_rowptr -----------------------
__global__ void k_scan1() {
    __shared__ int s[1024];
    int b = blockIdx.x, t = threadIdx.x;
    int i = b * 1024 + t;
    int v = (i < NN) ? g_deg[i] : 0;
    s[t] = v;
    __syncthreads();
    for (int off = 1; off < 1024; off <<= 1) {
        int x = (t >= off) ? s[t - off] : 0;
        __syncthreads();
        s[t] += x;
        __syncthreads();
    }
    if (i < NN) g_rowptr[i] = s[t] - v;
    if (t == 1023) g_blksums[b] = s[t];
}

__global__ void k_scan2(int nb) {
    __shared__ int s[128];
    int t = threadIdx.x;
    int v = (t < nb) ? g_blksums[t] : 0;
    s[t] = v;
    __syncthreads();
    for (int off = 1; off < 128; off <<= 1) {
        int x = (t >= off) ? s[t - off] : 0;
        __syncthreads();
        s[t] += x;
        __syncthreads();
    }
    g_blksums[t] = s[t] - v;
}

__global__ void k_scan3() {
    int b = blockIdx.x, t = threadIdx.x;
    int i = b * 1024 + t;
    if (i < NN) {
        int rp = g_rowptr[i] + g_blksums[b];
        g_rowptr[i] = rp;
        g_curn[i] = rp;
        g_dinv[i] = rsqrtf((float)(g_deg[i] + 1));   // +1 = self-loop
    }
    if (i == 0) g_rowptr[NN] = EE;
}

__global__ void k_scanG() {
    __shared__ int s[512];
    int t = threadIdx.x;
    int v = g_egcnt[t];
    s[t] = v;
    __syncthreads();
    for (int off = 1; off < 512; off <<= 1) {
        int x = (t >= off) ? s[t - off] : 0;
        __syncthreads();
        s[t] += x;
        __syncthreads();
    }
    int p = s[t] - v;
    g_egptr[t] = p;
    g_curg[t] = p;
    if (t == 0) g_egptr[GG] = EE;
}

// ---------------- CSR scatter ------------------------------------------------------------
__global__ void k_scatter(const void* __restrict__ ei) {
    int e = blockIdx.x * blockDim.x + threadIdx.x;
    if (e >= EE) return;
    int s = clampi(load_idx(ei, e), 0, NN - 1);
    int d = clampi(load_idx(ei, (long long)EE + e), 0, NN - 1);
    int p = atomicAdd(&g_curn[d], 1);
    if (p >= 0 && p < EE) g_csrsrc[p] = s;
    int g = g_ge[e];
    int p2 = atomicAdd(&g_curg[g], 1);
    if (p2 >= 0 && p2 < EE) g_egedge[p2] = e;
}

// ---------------- scale g_bufA rows by dinv (layer-1 only) --------------------------------
__global__ void k_scale() {
    int i = blockIdx.x * blockDim.x + threadIdx.x;   // over NN*32 float4
    if (i >= NN * 32) return;
    int node = i >> 5;
    float4* p = reinterpret_cast<float4*>((float*)g_bufA);
    float4 v = p[i];
    float d = g_dinv[node];
    v.x *= d; v.y *= d; v.z *= d; v.w *= d;
    p[i] = v;
}

// ---------------- GEMM (FFMA2, 8x8 regtile): g_bufA = X @ W  [opt row-scaled] -------------
// block: 256 threads, 128 rows x 128 cols. thread: 8 rows x 8 cols. KC=16.
#define XPAD 132
template <bool FIRST, bool SCALE>
__global__ void __launch_bounds__(256, 2)
k_gemm(const float* __restrict__ Xext, const float* __restrict__ W, int nrows) {
    const float* __restrict__ X = FIRST ? Xext : (const float*)g_bufB;
    float* __restrict__ Y = g_bufA;
    __shared__ __align__(16) float xs[16][XPAD];   // transposed: xs[k][row], padded row
    __shared__ __align__(16) float ws[16][128];
    int tid = threadIdx.x;
    int c = tid & 15;   // cols c*8 .. c*8+7
    int r = tid >> 4;   // rows r*8 .. r*8+7
    int row0 = blockIdx.x * 128;

    u64 acc2[8][4];
#pragma unroll
    for (int i = 0; i < 8; i++)
#pragma unroll
        for (int j = 0; j < 4; j++) acc2[i][j] = 0ull;

    // X load indexing: idx = l*256 + tid; rr = idx>>2 (0..127), kq = idx&3 (float4 of 16 k)
    int x_kq = tid & 3;
    int x_rr0 = tid >> 2;       // + l*64

    for (int kc = 0; kc < 128; kc += 16) {
        // load X tile: 128 rows x 16 k = 512 float4, 2 per thread
#pragma unroll
        for (int l = 0; l < 2; l++) {
            int rr = x_rr0 + l * 64;
            int grow = row0 + rr;
            float4 v = make_float4(0.f, 0.f, 0.f, 0.f);
            if (grow < nrows)
                v = *reinterpret_cast<const float4*>(&X[grow * DD + kc + x_kq * 4]);
            xs[x_kq * 4 + 0][rr] = v.x;
            xs[x_kq * 4 + 1][rr] = v.y;
            xs[x_kq * 4 + 2][rr] = v.z;
            xs[x_kq * 4 + 3][rr] = v.w;
        }
        // load W tile: 16 k x 128 cols = 2048 floats, 8 per thread (coalesced)
#pragma unroll
        for (int l = 0; l < 8; l++) {
            int idx = tid + l * 256;
            int kk = idx >> 7;
            int cc = idx & 127;
            ws[kk][cc] = W[(kc + kk) * DD + cc];
        }
        __syncthreads();
#pragma unroll
        for (int k = 0; k < 16; k++) {
            float4 xa = *reinterpret_cast<float4*>(&xs[k][r * 8]);
            float4 xb = *reinterpret_cast<float4*>(&xs[k][r * 8 + 4]);
            ulonglong2 w01 = *reinterpret_cast<ulonglong2*>(&ws[k][c * 8]);
            ulonglong2 w23 = *reinterpret_cast<ulonglong2*>(&ws[k][c * 8 + 4]);
            u64 wp[4] = {w01.x, w01.y, w23.x, w23.y};
            u64 xr2[8] = {pack_dup(xa.x), pack_dup(xa.y), pack_dup(xa.z), pack_dup(xa.w),
                          pack_dup(xb.x), pack_dup(xb.y), pack_dup(xb.z), pack_dup(xb.w)};
#pragma unroll
            for (int i = 0; i < 8; i++)
#pragma unroll
                for (int j = 0; j < 4; j++)
                    ffma2(acc2[i][j], xr2[i], wp[j]);
        }
        __syncthreads();
    }
#pragma unroll
    for (int i = 0; i < 8; i++) {
        int grow = row0 + r * 8 + i;
        if (grow < nrows) {
            float d = SCALE ? g_dinv[grow] : 1.f;
            float2 p0 = unpack2(acc2[i][0]);
            float2 p1 = unpack2(acc2[i][1]);
            float2 p2 = unpack2(acc2[i][2]);
            float2 p3 = unpack2(acc2[i][3]);
            float4 o0 = make_float4(p0.x * d, p0.y * d, p1.x * d, p1.y * d);
            float4 o1 = make_float4(p2.x * d, p2.y * d, p3.x * d, p3.y * d);
            *reinterpret_cast<float4*>(&Y[grow * DD + c * 8]) = o0;
            *reinterpret_cast<float4*>(&Y[grow * DD + c * 8 + 4]) = o1;
        }
    }
}

// ---------------- gather + bias + BN(eval) + ReLU (+ optional fused pool) --------------------
// g_bufA holds pre-scaled xw' = xw * dinv. result = di * (xw'[node] + sum xw'[nbr]).
template <bool POOL>
__global__ void k_gather(const float* __restrict__ B, const float* __restrict__ GA,
                         const float* __restrict__ BT, const float* __restrict__ M,
                         const float* __restrict__ V, const void* __restrict__ batch) {
    int warp = (blockIdx.x * blockDim.x + threadIdx.x) >> 5;
    int lane = threadIdx.x & 31;
    if (warp >= NN) return;
    int node = warp;
    float di = g_dinv[node];
    const float4* xw4 = reinterpret_cast<const float4*>((const float*)g_bufA);
    float4 a0 = xw4[node * 32 + lane];   // self term (already * dinv_node)
    float4 a1 = make_float4(0.f, 0.f, 0.f, 0.f);
    float4 a2 = make_float4(0.f, 0.f, 0.f, 0.f);
    float4 a3 = make_float4(0.f, 0.f, 0.f, 0.f);
    int jb = g_rowptr[node], je = g_rowptr[node + 1];
    int j = jb;
    for (; j + 3 < je; j += 4) {
        int s0 = g_csrsrc[j + 0];
        int s1 = g_csrsrc[j + 1];
        int s2 = g_csrsrc[j + 2];
        int s3 = g_csrsrc[j + 3];
        float4 v0 = xw4[s0 * 32 + lane];
        float4 v1 = xw4[s1 * 32 + lane];
        float4 v2 = xw4[s2 * 32 + lane];
        float4 v3 = xw4[s3 * 32 + lane];
        a0.x += v0.x; a0.y += v0.y; a0.z += v0.z; a0.w += v0.w;
        a1.x += v1.x; a1.y += v1.y; a1.z += v1.z; a1.w += v1.w;
        a2.x += v2.x; a2.y += v2.y; a2.z += v2.z; a2.w += v2.w;
        a3.x += v3.x; a3.y += v3.y; a3.z += v3.z; a3.w += v3.w;
    }
    for (; j < je; j++) {
        int s = g_csrsrc[j];
        float4 v = xw4[s * 32 + lane];
        a0.x += v.x; a0.y += v.y; a0.z += v.z; a0.w += v.w;
    }
    float4 acc;
    acc.x = (a0.x + a1.x) + (a2.x + a3.x);
    acc.y = (a0.y + a1.y) + (a2.y + a3.y);
    acc.z = (a0.z + a1.z) + (a2.z + a3.z);
    acc.w = (a0.w + a1.w) + (a2.w + a3.w);
    int f = lane * 4;
    float4 b4  = *reinterpret_cast<const float4*>(&B[f]);
    float4 g4  = *reinterpret_cast<const float4*>(&GA[f]);
    float4 bt4 = *reinterpret_cast<const float4*>(&BT[f]);
    float4 m4  = *reinterpret_cast<const float4*>(&M[f]);
    float4 vv4 = *reinterpret_cast<const float4*>(&V[f]);
    float4 o;
    o.x = fmaxf((acc.x * di + b4.x - m4.x) * rsqrtf(vv4.x + BN_EPS) * g4.x + bt4.x, 0.f);
    o.y = fmaxf((acc.y * di + b4.y - m4.y) * rsqrtf(vv4.y + BN_EPS) * g4.y + bt4.y, 0.f);
    o.z = fmaxf((acc.z * di + b4.z - m4.z) * rsqrtf(vv4.z + BN_EPS) * g4.z + bt4.z, 0.f);
    o.w = fmaxf((acc.w * di + b4.w - m4.w) * rsqrtf(vv4.w + BN_EPS) * g4.w + bt4.w, 0.f);
    float4* out4 = reinterpret_cast<float4*>((float*)g_bufB);
    out4[node * 32 + lane] = o;
    if (POOL) {
        int g = clampi(load_idx(batch, node), 0, GG - 1);
        int base = g * DD + f;
        atomicAdd(&g_nsum[base + 0], o.x);
        atomicAdd(&g_nsum[base + 1], o.y);
        atomicAdd(&g_nsum[base + 2], o.z);
        atomicAdd(&g_nsum[base + 3], o.w);
    }
}

// ---------------- edge MLP first layer, summed per graph (FFMA2, 2-edge ILP) -----------------
#define EBLK 4
__global__ void k_edgemlp(const float* __restrict__ EA, const float* __restrict__ W1e,
                          const float* __restrict__ B1e) {
    int g = blockIdx.x >> 2;          // graph
    int q = blockIdx.x & (EBLK - 1);  // quarter
    int tid = threadIdx.x, warp = tid >> 5, lane = tid & 31;
    __shared__ float eas[8][2][16];
    __shared__ float red[DD];
    ulonglong2 wc[16];                // two f32x2 pairs per k (4 output cols)
#pragma unroll
    for (int k = 0; k < 16; k++)
        wc[k] = *reinterpret_cast<const ulonglong2*>(&W1e[k * DD + lane * 4]);
    ulonglong2 b2 = *reinterpret_cast<const ulonglong2*>(&B1e[lane * 4]);

    int gb = g_egptr[g], ge = g_egptr[g + 1];
    int cnt = ge - gb;
    int per = (cnt + EBLK - 1) / EBLK;
    int jb = gb + q * per;
    int je = min(jb + per, ge);

    float4 acc = make_float4(0.f, 0.f, 0.f, 0.f);
    for (int j = jb + warp; j < je; j += 16) {
        int j2 = j + 8;
        bool has2 = (j2 < je);
        int e0 = g_egedge[j];
        int e1 = has2 ? g_egedge[j2] : e0;
        if (lane < 16) eas[warp][0][lane] = EA[(long long)e0 * DEE + lane];
        else           eas[warp][1][lane - 16] = EA[(long long)e1 * DEE + (lane - 16)];
        __syncwarp();
        u64 h0 = b2.x, h1 = b2.y, h2 = b2.x, h3 = b2.y;
#pragma unroll
        for (int k = 0; k < 16; k++) {
            u64 p0 = pack_dup(eas[warp][0][k]);
            u64 p1 = pack_dup(eas[warp][1][k]);
            ffma2(h0, p0, wc[k].x);
            ffma2(h1, p0, wc[k].y);
            ffma2(h2, p1, wc[k].x);
            ffma2(h3, p1, wc[k].y);
        }
        float2 u0 = unpack2(h0), u1 = unpack2(h1);
        acc.x += fmaxf(u0.x, 0.f);
        acc.y += fmaxf(u0.y, 0.f);
        acc.z += fmaxf(u1.x, 0.f);
        acc.w += fmaxf(u1.y, 0.f);
        if (has2) {
            float2 u2 = unpack2(h2), u3 = unpack2(h3);
            acc.x += fmaxf(u2.x, 0.f);
            acc.y += fmaxf(u2.y, 0.f);
            acc.z += fmaxf(u3.x, 0.f);
            acc.w += fmaxf(u3.y, 0.f);
        }
        __syncwarp();
    }
    if (tid < DD) red[tid] = 0.f;
    __syncthreads();
    int f = lane * 4;
    atomicAdd(&red[f + 0], acc.x);
    atomicAdd(&red[f + 1], acc.y);
    atomicAdd(&red[f + 2], acc.z);
    atomicAdd(&red[f + 3], acc.w);
    __syncthreads();
    if (tid < DD) atomicAdd(&g_hsum[g * DD + tid], red[tid]);
}

// ---------------- final combine ---------------------------------------------------------------
__global__ void k_final(const float* __restrict__ We2, const float* __restrict__ be2,
                        float* __restrict__ out) {
    int g = blockIdx.x;
    int t = threadIdx.x;   // 128
    __shared__ float hm[DD];
    int ec = g_egptr[g + 1] - g_egptr[g];
    float inv_e = (ec > 0) ? (1.f / (float)ec) : 0.f;
    hm[t] = g_hsum[g * DD + t] * inv_e;
    __syncthreads();
    float acc = be2[t];
#pragma unroll 4
    for (int k = 0; k < DD; k++)
        acc = fmaf(hm[k], We2[k * DD + t], acc);
    if (ec == 0) acc = 0.f;
    int nc = g_ncnt[g];
    float gr = g_nsum[g * DD + t] / fmaxf((float)nc, 1.f);
    out[g * DD + t] = gr + acc;
}

// ---------------- launch ------------------------------------------------------------------------
extern "C" void kernel_launch(void* const* d_in, const int* in_sizes, int n_in,
                              void* d_out, int out_size) {
    // Resolve pointers by size signature.
    const float* x = 0;  const void* ei = 0;  const void* batch = 0;  const float* ea = 0;
    const float* w16k[3] = {0, 0, 0};   // W1, W2, We2 (in metadata order)
    const float* v128[12] = {0};        // b1,g1,bt1,m1,v1,b2,g2,bt2,m2,v2,be1,be2
    const float* We1 = 0;
    int n16k = 0, n128 = 0;
    for (int i = 0; i < n_in; i++) {
        long long sz = in_sizes[i];
        if      (sz == (long long)NN * DD) { if (!x) x = (const float*)d_in[i]; }
        else if (sz == 2LL * EE)           { if (!ei) ei = d_in[i]; }
        else if (sz == NN)                 { if (!batch) batch = d_in[i]; }
        else if (sz == (long long)EE * DEE){ if (!ea) ea = (const float*)d_in[i]; }
        else if (sz == DD * DD)            { if (n16k < 3) w16k[n16k++] = (const float*)d_in[i]; }
        else if (sz == DEE * DD)           { if (!We1) We1 = (const float*)d_in[i]; }
        else if (sz == DD)                 { if (n128 < 12) v128[n128++] = (const float*)d_in[i]; }
    }
    const float *W1 = w16k[0], *W2 = w16k[1], *We2 = w16k[2];
    const float *b1 = v128[0], *g1 = v128[1], *bt1 = v128[2], *m1 = v128[3], *v1 = v128[4];
    const float *b2 = v128[5], *g2 = v128[6], *bt2 = v128[7], *m2 = v128[8], *v2 = v128[9];
    const float *be1 = v128[10], *be2 = v128[11];
    float* out = (float*)d_out;

    const int nb1 = (NN + 1023) / 1024;   // 98

    k_detect<<<1, 256>>>((const int*)ei);                        // 1
    k_init<<<256, 256>>>();                                      // 2
    k_hist_edges<<<(EE + 255) / 256, 256>>>(ei, batch);          // 3
    // layer-1 GEMM at launch #4 = ncu's profiled slot
    k_gemm<true, false><<<(NN + 127) / 128, 256>>>(x, W1, NN);   // 4  [profiled]
    k_hist_nodes<<<(NN + 255) / 256, 256>>>(batch);              // 5
    k_scan1<<<nb1, 1024>>>();
    k_scan2<<<1, 128>>>(nb1);
    k_scan3<<<nb1, 1024>>>();
    k_scanG<<<1, 512>>>();
    k_scatter<<<(EE + 255) / 256, 256>>>(ei);
    // pre-scale layer-1 xw by dinv (layer-2 GEMM fuses this into its epilogue)
    k_scale<<<(NN * 32 + 255) / 256, 256>>>();

    // layer 1 aggregate
    k_gather<false><<<(NN * 32 + 255) / 256, 256>>>(b1, g1, bt1, m1, v1, batch);
    // layer 2 (GEMM output pre-scaled by dinv; gather fuses mean-pool accumulation)
    k_gemm<false, true><<<(NN + 127) / 128, 256>>>(x, W2, NN);
    k_gather<true><<<(NN * 32 + 255) / 256, 256>>>(b2, g2, bt2, m2, v2, batch);
    // edge branch (4 blocks per graph, 2-edge ILP)
    k_edgemlp<<<GG * EBLK, 256>>>(ea, We1, be1);
    // combine
    k_final<<<GG, 128>>>(We2, be2, out);
}

// round 8
// speedup vs baseline: 1.3545x; 1.0553x over previous
#include <cuda_runtime.h>

#define NN 100000
#define DD 128
#define EE 1600000
#define DEE 16
#define GG 512
#define BN_EPS 1e-5f

typedef unsigned long long u64;

// ---------------- f32x2 packed helpers -----------------------------------------
__device__ __forceinline__ void ffma2(u64& d, u64 a, u64 b) {
    asm("fma.rn.f32x2 %0, %1, %2, %0;" : "+l"(d) : "l"(a), "l"(b));
}
__device__ __forceinline__ u64 pack_dup(float x) {
    u64 d; unsigned xi = __float_as_uint(x);
    asm("mov.b64 %0, {%1, %1};" : "=l"(d) : "r"(xi));
    return d;
}
__device__ __forceinline__ float2 unpack2(u64 v) {
    unsigned lo, hi;
    asm("mov.b64 {%0, %1}, %2;" : "=r"(lo), "=r"(hi) : "l"(v));
    return make_float2(__uint_as_float(lo), __uint_as_float(hi));
}

// ---------------- scratch (static device globals; no allocation) -----------------
__device__ __align__(16) float g_bufA[NN * DD];          // 51.2 MB
__device__ __align__(16) float g_bufB[NN * DD];          // 51.2 MB
__device__ int   g_deg[NN];
__device__ int   g_rowptr[NN + 1];
__device__ int   g_curn[NN];
__device__ int   g_csrsrc[EE];
__device__ int   g_tmpsrc[EE];
__device__ int   g_ge[EE];                // packed: dst | graph<<17
__device__ int   g_egcnt[GG];
__device__ int   g_egptr[GG + 1];
__device__ int   g_nptr[GG + 1];
__device__ int   g_curg[GG];
__device__ int   g_egedge[EE];
__device__ int   g_ncnt[GG];
__device__ float g_dinv[NN];
__device__ float g_hsum[GG * DD];
__device__ int   g_blksums[128];
__device__ int   g_is64;

// ---------------- index helpers (dtype-agnostic) ----------------------------------
__device__ __forceinline__ int load_idx(const void* p, long long i) {
    if (g_is64) return (int)((const long long*)p)[i];
    return ((const int*)p)[i];
}
__device__ __forceinline__ int clampi(int v, int lo, int hi) {
    return v < lo ? lo : (v > hi ? hi : v);
}

// ---------------- dtype detection: int64 values <2^31 have zero odd words ----------
__global__ void k_detect(const int* __restrict__ w) {
    __shared__ int ok;
    if (threadIdx.x == 0) ok = 1;
    __syncthreads();
    int bad = 0;
    for (int i = threadIdx.x; i < 2048; i += blockDim.x)
        if (w[2 * i + 1] != 0) bad = 1;
    if (bad) atomicAnd(&ok, 0);
    __syncthreads();
    if (threadIdx.x == 0) g_is64 = ok;
}

// ---------------- init: zero accumulators/histograms --------------------------------
__global__ void k_init() {
    int i = blockIdx.x * blockDim.x + threadIdx.x;
    int stride = gridDim.x * blockDim.x;
    for (int j = i; j < NN; j += stride) g_deg[j] = 0;
    for (int j = i; j < GG; j += stride) { g_egcnt[j] = 0; g_ncnt[j] = 0; }
    for (int j = i; j < GG * DD; j += stride) g_hsum[j] = 0.f;
}

// ---------------- histograms ----------------------------------------------------------
// also caches src (g_tmpsrc) and packed dst|graph (g_ge) for the scatter pass
__global__ void k_hist_edges(const void* __restrict__ ei,
                             const void* __restrict__ batch) {
    int e = blockIdx.x * blockDim.x + threadIdx.x;
    if (e >= EE) return;
    int s = clampi(load_idx(ei, e), 0, NN - 1);
    int d = clampi(load_idx(ei, (long long)EE + e), 0, NN - 1);
    atomicAdd(&g_deg[d], 1);
    int g = clampi(load_idx(batch, s), 0, GG - 1);
    g_tmpsrc[e] = s;
    g_ge[e] = d | (g << 17);
    atomicAdd(&g_egcnt[g], 1);
}

__global__ void k_hist_nodes(const void* __restrict__ batch) {
    int i = blockIdx.x * blockDim.x + threadIdx.x;
    if (i >= NN) return;
    int g = clampi(load_idx(batch, i), 0, GG - 1);
    atomicAdd(&g_ncnt[g], 1);
}

// ---------------- 3-phase exclusive scan over g_deg -> g_rowptr -----------------------
__global__ void k_scan1() {
    __shared__ int s[1024];
    int b = blockIdx.x, t = threadIdx.x;
    int i = b * 1024 + t;
    int v = (i < NN) ? g_deg[i] : 0;
    s[t] = v;
    __syncthreads();
    for (int off = 1; off < 1024; off <<= 1) {
        int x = (t >= off) ? s[t - off] : 0;
        __syncthreads();
        s[t] += x;
        __syncthreads();
    }
    if (i < NN) g_rowptr[i] = s[t] - v;
    if (t == 1023) g_blksums[b] = s[t];
}

__global__ void k_scan2(int nb) {
    __shared__ int s[128];
    int t = threadIdx.x;
    int v = (t < nb) ? g_blksums[t] : 0;
    s[t] = v;
    __syncthreads();
    for (int off = 1; off < 128; off <<= 1) {
        int x = (t >= off) ? s[t - off] : 0;
        __syncthreads();
        s[t] += x;
        __syncthreads();
    }
    g_blksums[t] = s[t] - v;
}

__global__ void k_scan3() {
    int b = blockIdx.x, t = threadIdx.x;
    int i = b * 1024 + t;
    if (i < NN) {
        int rp = g_rowptr[i] + g_blksums[b];
        g_rowptr[i] = rp;
        g_curn[i] = rp;
        g_dinv[i] = rsqrtf((float)(g_deg[i] + 1));   // +1 = self-loop
    }
    if (i == 0) g_rowptr[NN] = EE;
}

// scan egcnt -> egptr/curg, and ncnt -> nptr (both 512 wide)
__global__ void k_scanG() {
    __shared__ int s[512];
    int t = threadIdx.x;
    int v = g_egcnt[t];
    s[t] = v;
    __syncthreads();
    for (int off = 1; off < 512; off <<= 1) {
        int x = (t >= off) ? s[t - off] : 0;
        __syncthreads();
        s[t] += x;
        __syncthreads();
    }
    int p = s[t] - v;
    g_egptr[t] = p;
    g_curg[t] = p;
    if (t == 0) g_egptr[GG] = EE;
    __syncthreads();
    int v2 = g_ncnt[t];
    s[t] = v2;
    __syncthreads();
    for (int off = 1; off < 512; off <<= 1) {
        int x = (t >= off) ? s[t - off] : 0;
        __syncthreads();
        s[t] += x;
        __syncthreads();
    }
    g_nptr[t] = s[t] - v2;
    if (t == 0) g_nptr[GG] = NN;
}

// ---------------- CSR scatter (reads cached int32 arrays, not int64 inputs) ----------------
__global__ void k_scatter() {
    int e = blockIdx.x * blockDim.x + threadIdx.x;
    if (e >= EE) return;
    int s = g_tmpsrc[e];
    int pk = g_ge[e];
    int d = pk & 131071;
    int g = pk >> 17;
    int p = atomicAdd(&g_curn[d], 1);
    if (p >= 0 && p < EE) g_csrsrc[p] = s;
    int p2 = atomicAdd(&g_curg[g], 1);
    if (p2 >= 0 && p2 < EE) g_egedge[p2] = e;
}

// ---------------- GEMM (FFMA2, 8x8 regtile, double-buffered): g_bufA = (X @ W) * dinv ------
#define XPAD 132
template <bool FIRST, bool SCALE>
__global__ void __launch_bounds__(256, 2)
k_gemm(const float* __restrict__ Xext, const float* __restrict__ W, int nrows) {
    const float* __restrict__ X = FIRST ? Xext : (const float*)g_bufB;
    float* __restrict__ Y = g_bufA;
    __shared__ __align__(16) float xs[2][16][XPAD];
    __shared__ __align__(16) float ws[2][16][128];
    int tid = threadIdx.x;
    int c = tid & 15;   // cols c*8 .. c*8+7
    int r = tid >> 4;   // rows r*8 .. r*8+7
    int row0 = blockIdx.x * 128;

    int x_kq = tid & 3;
    int x_rr0 = tid >> 2;

    u64 acc2[8][4];
#pragma unroll
    for (int i = 0; i < 8; i++)
#pragma unroll
        for (int j = 0; j < 4; j++) acc2[i][j] = 0ull;

    // prologue: load tile 0 into buffer 0
#pragma unroll
    for (int l = 0; l < 2; l++) {
        int rr = x_rr0 + l * 64;
        int grow = row0 + rr;
        float4 v = make_float4(0.f, 0.f, 0.f, 0.f);
        if (grow < nrows)
            v = *reinterpret_cast<const float4*>(&X[grow * DD + x_kq * 4]);
        xs[0][x_kq * 4 + 0][rr] = v.x;
        xs[0][x_kq * 4 + 1][rr] = v.y;
        xs[0][x_kq * 4 + 2][rr] = v.z;
        xs[0][x_kq * 4 + 3][rr] = v.w;
    }
#pragma unroll
    for (int l = 0; l < 8; l++) {
        int idx = tid + l * 256;
        ws[0][idx >> 7][idx & 127] = W[(idx >> 7) * DD + (idx & 127)];
    }
    __syncthreads();

    for (int it = 0; it < 8; it++) {
        int cur = it & 1;
        float4 nx[2];
        float nw[8];
        if (it < 7) {
            int kc = (it + 1) * 16;
#pragma unroll
            for (int l = 0; l < 2; l++) {
                int rr = x_rr0 + l * 64;
                int grow = row0 + rr;
                nx[l] = make_float4(0.f, 0.f, 0.f, 0.f);
                if (grow < nrows)
                    nx[l] = *reinterpret_cast<const float4*>(&X[grow * DD + kc + x_kq * 4]);
            }
#pragma unroll
            for (int l = 0; l < 8; l++) {
                int idx = tid + l * 256;
                nw[l] = W[(kc + (idx >> 7)) * DD + (idx & 127)];
            }
        }
#pragma unroll
        for (int k = 0; k < 16; k++) {
            float4 xa = *reinterpret_cast<float4*>(&xs[cur][k][r * 8]);
            float4 xb = *reinterpret_cast<float4*>(&xs[cur][k][r * 8 + 4]);
            ulonglong2 w01 = *reinterpret_cast<ulonglong2*>(&ws[cur][k][c * 8]);
            ulonglong2 w23 = *reinterpret_cast<ulonglong2*>(&ws[cur][k][c * 8 + 4]);
            u64 wp[4] = {w01.x, w01.y, w23.x, w23.y};
            u64 xr2[8] = {pack_dup(xa.x), pack_dup(xa.y), pack_dup(xa.z), pack_dup(xa.w),
                          pack_dup(xb.x), pack_dup(xb.y), pack_dup(xb.z), pack_dup(xb.w)};
#pragma unroll
            for (int i = 0; i < 8; i++)
#pragma unroll
                for (int j = 0; j < 4; j++)
                    ffma2(acc2[i][j], xr2[i], wp[j]);
        }
        if (it < 7) {
            int nxt = cur ^ 1;
#pragma unroll
            for (int l = 0; l < 2; l++) {
                int rr = x_rr0 + l * 64;
                xs[nxt][x_kq * 4 + 0][rr] = nx[l].x;
                xs[nxt][x_kq * 4 + 1][rr] = nx[l].y;
                xs[nxt][x_kq * 4 + 2][rr] = nx[l].z;
                xs[nxt][x_kq * 4 + 3][rr] = nx[l].w;
            }
#pragma unroll
            for (int l = 0; l < 8; l++) {
                int idx = tid + l * 256;
                ws[nxt][idx >> 7][idx & 127] = nw[l];
            }
        }
        __syncthreads();
    }
#pragma unroll
    for (int i = 0; i < 8; i++) {
        int grow = row0 + r * 8 + i;
        if (grow < nrows) {
            float d = SCALE ? g_dinv[grow] : 1.f;
            float2 p0 = unpack2(acc2[i][0]);
            float2 p1 = unpack2(acc2[i][1]);
            float2 p2 = unpack2(acc2[i][2]);
            float2 p3 = unpack2(acc2[i][3]);
            float4 o0 = make_float4(p0.x * d, p0.y * d, p1.x * d, p1.y * d);
            float4 o1 = make_float4(p2.x * d, p2.y * d, p3.x * d, p3.y * d);
            *reinterpret_cast<float4*>(&Y[grow * DD + c * 8]) = o0;
            *reinterpret_cast<float4*>(&Y[grow * DD + c * 8 + 4]) = o1;
        }
    }
}

// ---------------- gather + bias + BN(eval) + ReLU ----------------------------------
// g_bufA holds pre-scaled xw' = xw * dinv. result = di * (xw'[node] + sum xw'[nbr]).
__global__ void k_gather(const float* __restrict__ B, const float* __restrict__ GA,
                         const float* __restrict__ BT, const float* __restrict__ M,
                         const float* __restrict__ V) {
    int warp = (blockIdx.x * blockDim.x + threadIdx.x) >> 5;
    int lane = threadIdx.x & 31;
    if (warp >= NN) return;
    int node = warp;
    float di = g_dinv[node];
    const float4* xw4 = reinterpret_cast<const float4*>((const float*)g_bufA);
    float4 a0 = xw4[node * 32 + lane];   // self term (already * dinv_node)
    float4 a1 = make_float4(0.f, 0.f, 0.f, 0.f);
    float4 a2 = make_float4(0.f, 0.f, 0.f, 0.f);
    float4 a3 = make_float4(0.f, 0.f, 0.f, 0.f);
    int jb = g_rowptr[node], je = g_rowptr[node + 1];
    int j = jb;
    for (; j + 3 < je; j += 4) {
        int s0 = g_csrsrc[j + 0];
        int s1 = g_csrsrc[j + 1];
        int s2 = g_csrsrc[j + 2];
        int s3 = g_csrsrc[j + 3];
        float4 v0 = xw4[s0 * 32 + lane];
        float4 v1 = xw4[s1 * 32 + lane];
        float4 v2 = xw4[s2 * 32 + lane];
        float4 v3 = xw4[s3 * 32 + lane];
        a0.x += v0.x; a0.y += v0.y; a0.z += v0.z; a0.w += v0.w;
        a1.x += v1.x; a1.y += v1.y; a1.z += v1.z; a1.w += v1.w;
        a2.x += v2.x; a2.y += v2.y; a2.z += v2.z; a2.w += v2.w;
        a3.x += v3.x; a3.y += v3.y; a3.z += v3.z; a3.w += v3.w;
    }
    for (; j < je; j++) {
        int s = g_csrsrc[j];
        float4 v = xw4[s * 32 + lane];
        a0.x += v.x; a0.y += v.y; a0.z += v.z; a0.w += v.w;
    }
    float4 acc;
    acc.x = (a0.x + a1.x) + (a2.x + a3.x);
    acc.y = (a0.y + a1.y) + (a2.y + a3.y);
    acc.z = (a0.z + a1.z) + (a2.z + a3.z);
    acc.w = (a0.w + a1.w) + (a2.w + a3.w);
    int f = lane * 4;
    float4 b4  = *reinterpret_cast<const float4*>(&B[f]);
    float4 g4  = *reinterpret_cast<const float4*>(&GA[f]);
    float4 bt4 = *reinterpret_cast<const float4*>(&BT[f]);
    float4 m4  = *reinterpret_cast<const float4*>(&M[f]);
    float4 vv4 = *reinterpret_cast<const float4*>(&V[f]);
    float4 o;
    o.x = fmaxf((acc.x * di + b4.x - m4.x) * rsqrtf(vv4.x + BN_EPS) * g4.x + bt4.x, 0.f);
    o.y = fmaxf((acc.y * di + b4.y - m4.y) * rsqrtf(vv4.y + BN_EPS) * g4.y + bt4.y, 0.f);
    o.z = fmaxf((acc.z * di + b4.z - m4.z) * rsqrtf(vv4.z + BN_EPS) * g4.z + bt4.z, 0.f);
    o.w = fmaxf((acc.w * di + b4.w - m4.w) * rsqrtf(vv4.w + BN_EPS) * g4.w + bt4.w, 0.f);
    float4* out4 = reinterpret_cast<float4*>((float*)g_bufB);
    out4[node * 32 + lane] = o;
}

// ---------------- edge MLP first layer, summed per graph (FFMA2, 2-edge ILP) -----------------
#define EBLK 8
__global__ void k_edgemlp(const float* __restrict__ EA, const float* __restrict__ W1e,
                          const float* __restrict__ B1e) {
    int g = blockIdx.x >> 3;          // graph
    int q = blockIdx.x & (EBLK - 1);  // slice
    int tid = threadIdx.x, warp = tid >> 5, lane = tid & 31;
    __shared__ float eas[8][2][16];
    __shared__ float red[DD];
    ulonglong2 wc[16];                // two f32x2 pairs per k (4 output cols)
#pragma unroll
    for (int k = 0; k < 16; k++)
        wc[k] = *reinterpret_cast<const ulonglong2*>(&W1e[k * DD + lane * 4]);
    ulonglong2 b2 = *reinterpret_cast<const ulonglong2*>(&B1e[lane * 4]);

    int gb = g_egptr[g], ge = g_egptr[g + 1];
    int cnt = ge - gb;
    int per = (cnt + EBLK - 1) / EBLK;
    int jb = gb + q * per;
    int je = min(jb + per, ge);

    float4 acc = make_float4(0.f, 0.f, 0.f, 0.f);
    for (int j = jb + warp; j < je; j += 16) {
        int j2 = j + 8;
        bool has2 = (j2 < je);
        int e0 = g_egedge[j];
        int e1 = has2 ? g_egedge[j2] : e0;
        if (lane < 16) eas[warp][0][lane] = EA[(long long)e0 * DEE + lane];
        else           eas[warp][1][lane - 16] = EA[(long long)e1 * DEE + (lane - 16)];
        __syncwarp();
        u64 h0 = b2.x, h1 = b2.y, h2 = b2.x, h3 = b2.y;
#pragma unroll
        for (int k = 0; k < 16; k++) {
            u64 p0 = pack_dup(eas[warp][0][k]);
            u64 p1 = pack_dup(eas[warp][1][k]);
            ffma2(h0, p0, wc[k].x);
            ffma2(h1, p0, wc[k].y);
            ffma2(h2, p1, wc[k].x);
            ffma2(h3, p1, wc[k].y);
        }
        float2 u0 = unpack2(h0), u1 = unpack2(h1);
        acc.x += fmaxf(u0.x, 0.f);
        acc.y += fmaxf(u0.y, 0.f);
        acc.z += fmaxf(u1.x, 0.f);
        acc.w += fmaxf(u1.y, 0.f);
        if (has2) {
            float2 u2 = unpack2(h2), u3 = unpack2(h3);
            acc.x += fmaxf(u2.x, 0.f);
            acc.y += fmaxf(u2.y, 0.f);
            acc.z += fmaxf(u3.x, 0.f);
            acc.w += fmaxf(u3.y, 0.f);
        }
        __syncwarp();
    }
    if (tid < DD) red[tid] = 0.f;
    __syncthreads();
    int f = lane * 4;
    atomicAdd(&red[f + 0], acc.x);
    atomicAdd(&red[f + 1], acc.y);
    atomicAdd(&red[f + 2], acc.z);
    atomicAdd(&red[f + 3], acc.w);
    __syncthreads();
    if (tid < DD) atomicAdd(&g_hsum[g * DD + tid], red[tid]);
}

// ---------------- final combine: node segment-mean + edge GEMM ----------------------------
__global__ void k_final(const float* __restrict__ We2, const float* __restrict__ be2,
                        float* __restrict__ out) {
    int g = blockIdx.x;
    int t = threadIdx.x;   // 128
    __shared__ float hm[DD];
    int ec = g_egptr[g + 1] - g_egptr[g];
    float inv_e = (ec > 0) ? (1.f / (float)ec) : 0.f;
    hm[t] = g_hsum[g * DD + t] * inv_e;

    // segmented node sum (batch sorted => contiguous rows)
    int ns = g_nptr[g], ne = g_nptr[g + 1];
    const float* __restrict__ H = (const float*)g_bufB;
    float a0 = 0.f, a1 = 0.f, a2 = 0.f, a3 = 0.f;
    int rr = ns;
    for (; rr + 3 < ne; rr += 4) {
        a0 += H[(long long)rr * DD + t];
        a1 += H[(long long)(rr + 1) * DD + t];
        a2 += H[(long long)(rr + 2) * DD + t];
        a3 += H[(long long)(rr + 3) * DD + t];
    }
    for (; rr < ne; rr++) a0 += H[(long long)rr * DD + t];
    float nsumv = (a0 + a1) + (a2 + a3);

    __syncthreads();
    float acc = be2[t];
#pragma unroll 4
    for (int k = 0; k < DD; k++)
        acc = fmaf(hm[k], We2[k * DD + t], acc);
    if (ec == 0) acc = 0.f;
    int nc = ne - ns;
    float gr = nsumv / fmaxf((float)nc, 1.f);
    out[g * DD + t] = gr + acc;
}

// ---------------- launch ------------------------------------------------------------------------
extern "C" void kernel_launch(void* const* d_in, const int* in_sizes, int n_in,
                              void* d_out, int out_size) {
    // Resolve pointers by size signature.
    const float* x = 0;  const void* ei = 0;  const void* batch = 0;  const float* ea = 0;
    const float* w16k[3] = {0, 0, 0};   // W1, W2, We2 (in metadata order)
    const float* v128[12] = {0};        // b1,g1,bt1,m1,v1,b2,g2,bt2,m2,v2,be1,be2
    const float* We1 = 0;
    int n16k = 0, n128 = 0;
    for (int i = 0; i < n_in; i++) {
        long long sz = in_sizes[i];
        if      (sz == (long long)NN * DD) { if (!x) x = (const float*)d_in[i]; }
        else if (sz == 2LL * EE)           { if (!ei) ei = d_in[i]; }
        else if (sz == NN)                 { if (!batch) batch = d_in[i]; }
        else if (sz == (long long)EE * DEE){ if (!ea) ea = (const float*)d_in[i]; }
        else if (sz == DD * DD)            { if (n16k < 3) w16k[n16k++] = (const float*)d_in[i]; }
        else if (sz == DEE * DD)           { if (!We1) We1 = (const float*)d_in[i]; }
        else if (sz == DD)                 { if (n128 < 12) v128[n128++] = (const float*)d_in[i]; }
    }
    const float *W1 = w16k[0], *W2 = w16k[1], *We2 = w16k[2];
    const float *b1 = v128[0], *g1 = v128[1], *bt1 = v128[2], *m1 = v128[3], *v1 = v128[4];
    const float *b2 = v128[5], *g2 = v128[6], *bt2 = v128[7], *m2 = v128[8], *v2 = v128[9];
    const float *be1 = v128[10], *be2 = v128[11];
    float* out = (float*)d_out;

    const int nb1 = (NN + 1023) / 1024;   // 98

    k_detect<<<1, 256>>>((const int*)ei);                        // 1
    k_init<<<256, 256>>>();                                      // 2
    k_hist_nodes<<<(NN + 255) / 256, 256>>>(batch);              // 3
    k_hist_edges<<<(EE + 255) / 256, 256>>>(ei, batch);          // 4 [profiled]
    k_scan1<<<nb1, 1024>>>();
    k_scan2<<<1, 128>>>(nb1);
    k_scan3<<<nb1, 1024>>>();
    k_scanG<<<1, 512>>>();
    k_scatter<<<(EE + 255) / 256, 256>>>();

    // layer 1: g_bufA = (x @ W1) * dinv ; g_bufB = BN(ReLU(di * sum))
    k_gemm<true, true><<<(NN + 127) / 128, 256>>>(x, W1, NN);
    k_gather<<<(NN * 32 + 255) / 256, 256>>>(b1, g1, bt1, m1, v1);
    // layer 2
    k_gemm<false, true><<<(NN + 127) / 128, 256>>>(x, W2, NN);
    k_gather<<<(NN * 32 + 255) / 256, 256>>>(b2, g2, bt2, m2, v2);
    // edge branch (8 blocks per graph, 2-edge ILP)
    k_edgemlp<<<GG * EBLK, 256>>>(ea, We1, be1);
    // combine: segmented node mean + edge GEMM
    k_final<<<GG, 128>>>(We2, be2, out);
}

// round 9
// speedup vs baseline: 2.1426x; 1.5819x over previous
#include <cuda_runtime.h>

#define NN 100000
#define NN2 200000
#define DD 128
#define EE 1600000
#define DEE 16
#define GG 512
#define BN_EPS 1e-5f

typedef unsigned long long u64;

// ---------------- f32x2 packed helpers -----------------------------------------
__device__ __forceinline__ void ffma2(u64& d, u64 a, u64 b) {
    asm("fma.rn.f32x2 %0, %1, %2, %0;" : "+l"(d) : "l"(a), "l"(b));
}
__device__ __forceinline__ u64 pack_dup(float x) {
    u64 d; unsigned xi = __float_as_uint(x);
    asm("mov.b64 %0, {%1, %1};" : "=l"(d) : "r"(xi));
    return d;
}
__device__ __forceinline__ float2 unpack2(u64 v) {
    unsigned lo, hi;
    asm("mov.b64 {%0, %1}, %2;" : "=r"(lo), "=r"(hi) : "l"(v));
    return make_float2(__uint_as_float(lo), __uint_as_float(hi));
}

// ---------------- scratch (static device globals; no allocation) -----------------
__device__ __align__(16) float g_bufA[NN * DD];          // 51.2 MB
__device__ __align__(16) float g_bufB[NN * DD];          // 51.2 MB
__device__ int   g_deg2[NN2];             // [0,NN): dst degree, [NN,2NN): src degree
__device__ int   g_rowptr[NN + 1];        // dst-CSR row pointers
__device__ int   g_sptr[NN + 1];          // src-CSR row pointers
__device__ int   g_curn[NN];
__device__ int   g_curs[NN];
__device__ int   g_csrsrc[EE];            // dst-CSR payload: src node
__device__ int   g_eid[EE];               // src-CSR payload: edge id
__device__ int   g_src32[EE];
__device__ int   g_dst32[EE];
__device__ int   g_egptr[GG + 1];
__device__ int   g_nptr[GG + 1];
__device__ float g_dinv[NN];
__device__ float g_hsum[GG * DD];
__device__ int   g_blksums[256];
__device__ int   g_is64;

// ---------------- index helpers (dtype-agnostic) ----------------------------------
__device__ __forceinline__ int load_idx(const void* p, long long i) {
    if (g_is64) return (int)((const long long*)p)[i];
    return ((const int*)p)[i];
}
__device__ __forceinline__ int clampi(int v, int lo, int hi) {
    return v < lo ? lo : (v > hi ? hi : v);
}

// ---------------- dtype detection: int64 values <2^31 have zero odd words ----------
__global__ void k_detect(const int* __restrict__ w) {
    __shared__ int ok;
    if (threadIdx.x == 0) ok = 1;
    __syncthreads();
    int bad = 0;
    for (int i = threadIdx.x; i < 2048; i += blockDim.x)
        if (w[2 * i + 1] != 0) bad = 1;
    if (bad) atomicAnd(&ok, 0);
    __syncthreads();
    if (threadIdx.x == 0) g_is64 = ok;
}

// ---------------- init: zero histograms / accumulators ------------------------------
__global__ void k_init() {
    int i = blockIdx.x * blockDim.x + threadIdx.x;
    int stride = gridDim.x * blockDim.x;
    for (int j = i; j < NN2; j += stride) g_deg2[j] = 0;
    for (int j = i; j < GG * DD; j += stride) g_hsum[j] = 0.f;
}

// ---------------- convert edge_index to int32 (coalesced, no atomics) ----------------
__global__ void k_convert(const void* __restrict__ ei) {
    int e = blockIdx.x * blockDim.x + threadIdx.x;
    if (e >= EE) return;
    int s = clampi(load_idx(ei, e), 0, NN - 1);
    int d = clampi(load_idx(ei, (long long)EE + e), 0, NN - 1);
    g_src32[e] = s;
    g_dst32[e] = d;
}

// ---------------- histogram: two fire-and-forget REDs per edge ------------------------
__global__ void k_hist() {
    int e = blockIdx.x * blockDim.x + threadIdx.x;
    if (e >= EE) return;
    atomicAdd(&g_deg2[g_dst32[e]], 1);
    atomicAdd(&g_deg2[NN + g_src32[e]], 1);
}

// ---------------- 3-phase exclusive scan over g_deg2[0..200k) --------------------------
__global__ void k_scan1() {
    __shared__ int s[1024];
    int b = blockIdx.x, t = threadIdx.x;
    int i = b * 1024 + t;
    int v = (i < NN2) ? g_deg2[i] : 0;
    s[t] = v;
    __syncthreads();
    for (int off = 1; off < 1024; off <<= 1) {
        int x = (t >= off) ? s[t - off] : 0;
        __syncthreads();
        s[t] += x;
        __syncthreads();
    }
    // store inclusive-minus-v (exclusive within block) temporarily back into deg2's slot
    if (i < NN2) {
        if (i < NN) g_rowptr[i] = s[t] - v;
        else        g_sptr[i - NN] = s[t] - v;
    }
    if (t == 1023) g_blksums[b] = s[t];
}

__global__ void k_scan2(int nb) {
    __shared__ int s[256];
    int t = threadIdx.x;
    int v = (t < nb) ? g_blksums[t] : 0;
    s[t] = v;
    __syncthreads();
    for (int off = 1; off < 256; off <<= 1) {
        int x = (t >= off) ? s[t - off] : 0;
        __syncthreads();
        s[t] += x;
        __syncthreads();
    }
    g_blksums[t] = s[t] - v;
}

__global__ void k_scan3() {
    int b = blockIdx.x, t = threadIdx.x;
    int i = b * 1024 + t;
    if (i < NN2) {
        int add = g_blksums[b];
        if (i < NN) {
            int rp = g_rowptr[i] + add;
            g_rowptr[i] = rp;
            g_curn[i] = rp;
            g_dinv[i] = rsqrtf((float)(g_deg2[i] + 1));   // dst degree + self-loop
        } else {
            int sp = g_sptr[i - NN] + add - EE;           // src scan offset by first half total
            g_sptr[i - NN] = sp;
            g_curs[i - NN] = sp;
        }
    }
    if (i == 0) { g_rowptr[NN] = EE; g_sptr[NN] = EE; }
}

// ---------------- nptr via binary search on sorted batch; egptr = sptr[nptr] ------------
__global__ void k_nptr(const void* __restrict__ batch) {
    int g = threadIdx.x;    // 512
    // lower_bound: first i with batch[i] >= g
    int lo = 0, hi = NN;
    while (lo < hi) {
        int mid = (lo + hi) >> 1;
        if (load_idx(batch, mid) < g) lo = mid + 1;
        else hi = mid;
    }
    g_nptr[g] = lo;
    g_egptr[g] = g_sptr[lo];
    if (g == 0) { g_nptr[GG] = NN; g_egptr[GG] = EE; }
}

// ---------------- CSR scatter (coalesced int32 reads, two independent chains) -----------
__global__ void k_scatter() {
    int e = blockIdx.x * blockDim.x + threadIdx.x;
    if (e >= EE) return;
    int s = g_src32[e];
    int d = g_dst32[e];
    int p = atomicAdd(&g_curn[d], 1);
    if (p >= 0 && p < EE) g_csrsrc[p] = s;
    int p2 = atomicAdd(&g_curs[s], 1);
    if (p2 >= 0 && p2 < EE) g_eid[p2] = e;
}

// ---------------- GEMM (FFMA2, 8x8 regtile, double-buffered): g_bufA = (X @ W) * dinv ------
#define XPAD 132
template <bool FIRST, bool SCALE>
__global__ void __launch_bounds__(256, 2)
k_gemm(const float* __restrict__ Xext, const float* __restrict__ W, int nrows) {
    const float* __restrict__ X = FIRST ? Xext : (const float*)g_bufB;
    float* __restrict__ Y = g_bufA;
    __shared__ __align__(16) float xs[2][16][XPAD];
    __shared__ __align__(16) float ws[2][16][128];
    int tid = threadIdx.x;
    int c = tid & 15;   // cols c*8 .. c*8+7
    int r = tid >> 4;   // rows r*8 .. r*8+7
    int row0 = blockIdx.x * 128;

    int x_kq = tid & 3;
    int x_rr0 = tid >> 2;

    u64 acc2[8][4];
#pragma unroll
    for (int i = 0; i < 8; i++)
#pragma unroll
        for (int j = 0; j < 4; j++) acc2[i][j] = 0ull;

#pragma unroll
    for (int l = 0; l < 2; l++) {
        int rr = x_rr0 + l * 64;
        int grow = row0 + rr;
        float4 v = make_float4(0.f, 0.f, 0.f, 0.f);
        if (grow < nrows)
            v = *reinterpret_cast<const float4*>(&X[grow * DD + x_kq * 4]);
        xs[0][x_kq * 4 + 0][rr] = v.x;
        xs[0][x_kq * 4 + 1][rr] = v.y;
        xs[0][x_kq * 4 + 2][rr] = v.z;
        xs[0][x_kq * 4 + 3][rr] = v.w;
    }
#pragma unroll
    for (int l = 0; l < 8; l++) {
        int idx = tid + l * 256;
        ws[0][idx >> 7][idx & 127] = W[(idx >> 7) * DD + (idx & 127)];
    }
    __syncthreads();

    for (int it = 0; it < 8; it++) {
        int cur = it & 1;
        float4 nx[2];
        float nw[8];
        if (it < 7) {
            int kc = (it + 1) * 16;
#pragma unroll
            for (int l = 0; l < 2; l++) {
                int rr = x_rr0 + l * 64;
                int grow = row0 + rr;
                nx[l] = make_float4(0.f, 0.f, 0.f, 0.f);
                if (grow < nrows)
                    nx[l] = *reinterpret_cast<const float4*>(&X[grow * DD + kc + x_kq * 4]);
            }
#pragma unroll
            for (int l = 0; l < 8; l++) {
                int idx = tid + l * 256;
                nw[l] = W[(kc + (idx >> 7)) * DD + (idx & 127)];
            }
        }
#pragma unroll
        for (int k = 0; k < 16; k++) {
            float4 xa = *reinterpret_cast<float4*>(&xs[cur][k][r * 8]);
            float4 xb = *reinterpret_cast<float4*>(&xs[cur][k][r * 8 + 4]);
            ulonglong2 w01 = *reinterpret_cast<ulonglong2*>(&ws[cur][k][c * 8]);
            ulonglong2 w23 = *reinterpret_cast<ulonglong2*>(&ws[cur][k][c * 8 + 4]);
            u64 wp[4] = {w01.x, w01.y, w23.x, w23.y};
            u64 xr2[8] = {pack_dup(xa.x), pack_dup(xa.y), pack_dup(xa.z), pack_dup(xa.w),
                          pack_dup(xb.x), pack_dup(xb.y), pack_dup(xb.z), pack_dup(xb.w)};
#pragma unroll
            for (int i = 0; i < 8; i++)
#pragma unroll
                for (int j = 0; j < 4; j++)
                    ffma2(acc2[i][j], xr2[i], wp[j]);
        }
        if (it < 7) {
            int nxt = cur ^ 1;
#pragma unroll
            for (int l = 0; l < 2; l++) {
                int rr = x_rr0 + l * 64;
                xs[nxt][x_kq * 4 + 0][rr] = nx[l].x;
                xs[nxt][x_kq * 4 + 1][rr] = nx[l].y;
                xs[nxt][x_kq * 4 + 2][rr] = nx[l].z;
                xs[nxt][x_kq * 4 + 3][rr] = nx[l].w;
            }
#pragma unroll
            for (int l = 0; l < 8; l++) {
                int idx = tid + l * 256;
                ws[nxt][idx >> 7][idx & 127] = nw[l];
            }
        }
        __syncthreads();
    }
#pragma unroll
    for (int i = 0; i < 8; i++) {
        int grow = row0 + r * 8 + i;
        if (grow < nrows) {
            float d = SCALE ? g_dinv[grow] : 1.f;
            float2 p0 = unpack2(acc2[i][0]);
            float2 p1 = unpack2(acc2[i][1]);
            float2 p2 = unpack2(acc2[i][2]);
            float2 p3 = unpack2(acc2[i][3]);
            float4 o0 = make_float4(p0.x * d, p0.y * d, p1.x * d, p1.y * d);
            float4 o1 = make_float4(p2.x * d, p2.y * d, p3.x * d, p3.y * d);
            *reinterpret_cast<float4*>(&Y[grow * DD + c * 8]) = o0;
            *reinterpret_cast<float4*>(&Y[grow * DD + c * 8 + 4]) = o1;
        }
    }
}

// ---------------- gather + bias + BN(eval) + ReLU ----------------------------------
__global__ void k_gather(const float* __restrict__ B, const float* __restrict__ GA,
                         const float* __restrict__ BT, const float* __restrict__ M,
                         const float* __restrict__ V) {
    int warp = (blockIdx.x * blockDim.x + threadIdx.x) >> 5;
    int lane = threadIdx.x & 31;
    if (warp >= NN) return;
    int node = warp;
    float di = g_dinv[node];
    const float4* xw4 = reinterpret_cast<const float4*>((const float*)g_bufA);
    float4 a0 = xw4[node * 32 + lane];   // self term (already * dinv_node)
    float4 a1 = make_float4(0.f, 0.f, 0.f, 0.f);
    float4 a2 = make_float4(0.f, 0.f, 0.f, 0.f);
    float4 a3 = make_float4(0.f, 0.f, 0.f, 0.f);
    int jb = g_rowptr[node], je = g_rowptr[node + 1];
    int j = jb;
    for (; j + 3 < je; j += 4) {
        int s0 = g_csrsrc[j + 0];
        int s1 = g_csrsrc[j + 1];
        int s2 = g_csrsrc[j + 2];
        int s3 = g_csrsrc[j + 3];
        float4 v0 = xw4[s0 * 32 + lane];
        float4 v1 = xw4[s1 * 32 + lane];
        float4 v2 = xw4[s2 * 32 + lane];
        float4 v3 = xw4[s3 * 32 + lane];
        a0.x += v0.x; a0.y += v0.y; a0.z += v0.z; a0.w += v0.w;
        a1.x += v1.x; a1.y += v1.y; a1.z += v1.z; a1.w += v1.w;
        a2.x += v2.x; a2.y += v2.y; a2.z += v2.z; a2.w += v2.w;
        a3.x += v3.x; a3.y += v3.y; a3.z += v3.z; a3.w += v3.w;
    }
    for (; j < je; j++) {
        int s = g_csrsrc[j];
        float4 v = xw4[s * 32 + lane];
        a0.x += v.x; a0.y += v.y; a0.z += v.z; a0.w += v.w;
    }
    float4 acc;
    acc.x = (a0.x + a1.x) + (a2.x + a3.x);
    acc.y = (a0.y + a1.y) + (a2.y + a3.y);
    acc.z = (a0.z + a1.z) + (a2.z + a3.z);
    acc.w = (a0.w + a1.w) + (a2.w + a3.w);
    int f = lane * 4;
    float4 b4  = *reinterpret_cast<const float4*>(&B[f]);
    float4 g4  = *reinterpret_cast<const float4*>(&GA[f]);
    float4 bt4 = *reinterpret_cast<const float4*>(&BT[f]);
    float4 m4  = *reinterpret_cast<const float4*>(&M[f]);
    float4 vv4 = *reinterpret_cast<const float4*>(&V[f]);
    float4 o;
    o.x = fmaxf((acc.x * di + b4.x - m4.x) * rsqrtf(vv4.x + BN_EPS) * g4.x + bt4.x, 0.f);
    o.y = fmaxf((acc.y * di + b4.y - m4.y) * rsqrtf(vv4.y + BN_EPS) * g4.y + bt4.y, 0.f);
    o.z = fmaxf((acc.z * di + b4.z - m4.z) * rsqrtf(vv4.z + BN_EPS) * g4.z + bt4.z, 0.f);
    o.w = fmaxf((acc.w * di + b4.w - m4.w) * rsqrtf(vv4.w + BN_EPS) * g4.w + bt4.w, 0.f);
    float4* out4 = reinterpret_cast<float4*>((float*)g_bufB);
    out4[node * 32 + lane] = o;
}

// ---------------- edge MLP first layer, summed per graph (FFMA2, 2-edge ILP) -----------------
#define EBLK 8
__global__ void k_edgemlp(const float* __restrict__ EA, const float* __restrict__ W1e,
                          const float* __restrict__ B1e) {
    int g = blockIdx.x >> 3;          // graph
    int q = blockIdx.x & (EBLK - 1);  // slice
    int tid = threadIdx.x, warp = tid >> 5, lane = tid & 31;
    __shared__ float eas[8][2][16];
    __shared__ float red[DD];
    ulonglong2 wc[16];
#pragma unroll
    for (int k = 0; k < 16; k++)
        wc[k] = *reinterpret_cast<const ulonglong2*>(&W1e[k * DD + lane * 4]);
    ulonglong2 b2 = *reinterpret_cast<const ulonglong2*>(&B1e[lane * 4]);

    int gb = g_egptr[g], ge = g_egptr[g + 1];
    int cnt = ge - gb;
    int per = (cnt + EBLK - 1) / EBLK;
    int jb = gb + q * per;
    int je = min(jb + per, ge);

    float4 acc = make_float4(0.f, 0.f, 0.f, 0.f);
    for (int j = jb + warp; j < je; j += 16) {
        int j2 = j + 8;
        bool has2 = (j2 < je);
        int e0 = g_eid[j];
        int e1 = has2 ? g_eid[j2] : e0;
        if (lane < 16) eas[warp][0][lane] = EA[(long long)e0 * DEE + lane];
        else           eas[warp][1][lane - 16] = EA[(long long)e1 * DEE + (lane - 16)];
        __syncwarp();
        u64 h0 = b2.x, h1 = b2.y, h2 = b2.x, h3 = b2.y;
#pragma unroll
        for (int k = 0; k < 16; k++) {
            u64 p0 = pack_dup(eas[warp][0][k]);
            u64 p1 = pack_dup(eas[warp][1][k]);
            ffma2(h0, p0, wc[k].x);
            ffma2(h1, p0, wc[k].y);
            ffma2(h2, p1, wc[k].x);
            ffma2(h3, p1, wc[k].y);
        }
        float2 u0 = unpack2(h0), u1 = unpack2(h1);
        acc.x += fmaxf(u0.x, 0.f);
        acc.y += fmaxf(u0.y, 0.f);
        acc.z += fmaxf(u1.x, 0.f);
        acc.w += fmaxf(u1.y, 0.f);
        if (has2) {
            float2 u2 = unpack2(h2), u3 = unpack2(h3);
            acc.x += fmaxf(u2.x, 0.f);
            acc.y += fmaxf(u2.y, 0.f);
            acc.z += fmaxf(u3.x, 0.f);
            acc.w += fmaxf(u3.y, 0.f);
        }
        __syncwarp();
    }
    if (tid < DD) red[tid] = 0.f;
    __syncthreads();
    int f = lane * 4;
    atomicAdd(&red[f + 0], acc.x);
    atomicAdd(&red[f + 1], acc.y);
    atomicAdd(&red[f + 2], acc.z);
    atomicAdd(&red[f + 3], acc.w);
    __syncthreads();
    if (tid < DD) atomicAdd(&g_hsum[g * DD + tid], red[tid]);
}

// ---------------- final combine: node segment-mean + edge GEMM ----------------------------
__global__ void k_final(const float* __restrict__ We2, const float* __restrict__ be2,
                        float* __restrict__ out) {
    int g = blockIdx.x;
    int t = threadIdx.x;   // 128
    __shared__ float hm[DD];
    int ec = g_egptr[g + 1] - g_egptr[g];
    float inv_e = (ec > 0) ? (1.f / (float)ec) : 0.f;
    hm[t] = g_hsum[g * DD + t] * inv_e;

    // segmented node sum (batch sorted => contiguous rows)
    int ns = g_nptr[g], ne = g_nptr[g + 1];
    const float* __restrict__ H = (const float*)g_bufB;
    float a0 = 0.f, a1 = 0.f, a2 = 0.f, a3 = 0.f;
    int rr = ns;
    for (; rr + 3 < ne; rr += 4) {
        a0 += H[(long long)rr * DD + t];
        a1 += H[(long long)(rr + 1) * DD + t];
        a2 += H[(long long)(rr + 2) * DD + t];
        a3 += H[(long long)(rr + 3) * DD + t];
    }
    for (; rr < ne; rr++) a0 += H[(long long)rr * DD + t];
    float nsumv = (a0 + a1) + (a2 + a3);

    __syncthreads();
    float acc = be2[t];
#pragma unroll 4
    for (int k = 0; k < DD; k++)
        acc = fmaf(hm[k], We2[k * DD + t], acc);
    if (ec == 0) acc = 0.f;
    int nc = ne - ns;
    float gr = nsumv / fmaxf((float)nc, 1.f);
    out[g * DD + t] = gr + acc;
}

// ---------------- launch ------------------------------------------------------------------------
extern "C" void kernel_launch(void* const* d_in, const int* in_sizes, int n_in,
                              void* d_out, int out_size) {
    // Resolve pointers by size signature.
    const float* x = 0;  const void* ei = 0;  const void* batch = 0;  const float* ea = 0;
    const float* w16k[3] = {0, 0, 0};   // W1, W2, We2 (in metadata order)
    const float* v128[12] = {0};        // b1,g1,bt1,m1,v1,b2,g2,bt2,m2,v2,be1,be2
    const float* We1 = 0;
    int n16k = 0, n128 = 0;
    for (int i = 0; i < n_in; i++) {
        long long sz = in_sizes[i];
        if      (sz == (long long)NN * DD) { if (!x) x = (const float*)d_in[i]; }
        else if (sz == 2LL * EE)           { if (!ei) ei = d_in[i]; }
        else if (sz == NN)                 { if (!batch) batch = d_in[i]; }
        else if (sz == (long long)EE * DEE){ if (!ea) ea = (const float*)d_in[i]; }
        else if (sz == DD * DD)            { if (n16k < 3) w16k[n16k++] = (const float*)d_in[i]; }
        else if (sz == DEE * DD)           { if (!We1) We1 = (const float*)d_in[i]; }
        else if (sz == DD)                 { if (n128 < 12) v128[n128++] = (const float*)d_in[i]; }
    }
    const float *W1 = w16k[0], *W2 = w16k[1], *We2 = w16k[2];
    const float *b1 = v128[0], *g1 = v128[1], *bt1 = v128[2], *m1 = v128[3], *v1 = v128[4];
    const float *b2 = v128[5], *g2 = v128[6], *bt2 = v128[7], *m2 = v128[8], *v2 = v128[9];
    const float *be1 = v128[10], *be2 = v128[11];
    float* out = (float*)d_out;

    const int nb1 = (NN2 + 1023) / 1024;   // 196

    k_detect<<<1, 256>>>((const int*)ei);                        // 1
    k_init<<<256, 256>>>();                                      // 2
    k_convert<<<(EE + 255) / 256, 256>>>(ei);                    // 3
    k_hist<<<(EE + 255) / 256, 256>>>();                         // 4 [profiled]
    k_scan1<<<nb1, 1024>>>();
    k_scan2<<<1, 256>>>(nb1);
    k_scan3<<<nb1, 1024>>>();
    k_nptr<<<1, 512>>>(batch);
    k_scatter<<<(EE + 255) / 256, 256>>>();

    // layer 1: g_bufA = (x @ W1) * dinv ; g_bufB = BN(ReLU(di * sum))
    k_gemm<true, true><<<(NN + 127) / 128, 256>>>(x, W1, NN);
    k_gather<<<(NN * 32 + 255) / 256, 256>>>(b1, g1, bt1, m1, v1);
    // layer 2
    k_gemm<false, true><<<(NN + 127) / 128, 256>>>(x, W2, NN);
    k_gather<<<(NN * 32 + 255) / 256, 256>>>(b2, g2, bt2, m2, v2);
    // edge branch (8 blocks per graph, 2-edge ILP)
    k_edgemlp<<<GG * EBLK, 256>>>(ea, We1, be1);
    // combine: segmented node mean + edge GEMM
    k_final<<<GG, 128>>>(We2, be2, out);
}

// round 10
// speedup vs baseline: 2.2856x; 1.0668x over previous
#include <cuda_runtime.h>

#define NN 100000
#define NN2 200000
#define DD 128
#define EE 1600000
#define DEE 16
#define GG 512
#define BN_EPS 1e-5f

typedef unsigned long long u64;

// ---------------- f32x2 packed helpers -----------------------------------------
__device__ __forceinline__ void ffma2(u64& d, u64 a, u64 b) {
    asm("fma.rn.f32x2 %0, %1, %2, %0;" : "+l"(d) : "l"(a), "l"(b));
}
__device__ __forceinline__ u64 pack_dup(float x) {
    u64 d; unsigned xi = __float_as_uint(x);
    asm("mov.b64 %0, {%1, %1};" : "=l"(d) : "r"(xi));
    return d;
}
__device__ __forceinline__ float2 unpack2(u64 v) {
    unsigned lo, hi;
    asm("mov.b64 {%0, %1}, %2;" : "=r"(lo), "=r"(hi) : "l"(v));
    return make_float2(__uint_as_float(lo), __uint_as_float(hi));
}

// ---------------- scratch (static device globals; no allocation) -----------------
__device__ __align__(16) float g_bufA[NN * DD];          // 51.2 MB
__device__ __align__(16) float g_bufB[NN * DD];          // 51.2 MB
__device__ int   g_deg2[NN2];             // [0,NN): dst degree, [NN,2NN): src degree
__device__ int   g_rowptr[NN + 1];        // dst-CSR row pointers
__device__ int   g_sptr[NN + 1];          // src-CSR row pointers
__device__ int   g_curn[NN];
__device__ int   g_curs[NN];
__device__ int   g_csrsrc[EE];            // dst-CSR payload: src node
__device__ int   g_eid[EE];               // src-CSR payload: edge id
__device__ int   g_src32[EE];
__device__ int   g_dst32[EE];
__device__ int   g_egptr[GG + 1];
__device__ int   g_nptr[GG + 1];
__device__ float g_dinv[NN];
__device__ float g_hsum[GG * DD];
__device__ int   g_blksums[256];
__device__ int   g_is64;

// ---------------- index helpers (dtype-agnostic) ----------------------------------
__device__ __forceinline__ int load_idx(const void* p, long long i) {
    if (g_is64) return (int)((const long long*)p)[i];
    return ((const int*)p)[i];
}
__device__ __forceinline__ int clampi(int v, int lo, int hi) {
    return v < lo ? lo : (v > hi ? hi : v);
}

// ---------------- dtype detection: int64 values <2^31 have zero odd words ----------
__global__ void k_detect(const int* __restrict__ w) {
    __shared__ int ok;
    if (threadIdx.x == 0) ok = 1;
    __syncthreads();
    int bad = 0;
    for (int i = threadIdx.x; i < 2048; i += blockDim.x)
        if (w[2 * i + 1] != 0) bad = 1;
    if (bad) atomicAnd(&ok, 0);
    __syncthreads();
    if (threadIdx.x == 0) g_is64 = ok;
}

// ---------------- init: zero histograms / accumulators ------------------------------
__global__ void k_init() {
    int i = blockIdx.x * blockDim.x + threadIdx.x;
    int stride = gridDim.x * blockDim.x;
    for (int j = i; j < NN2; j += stride) g_deg2[j] = 0;
    for (int j = i; j < GG * DD; j += stride) g_hsum[j] = 0.f;
}

// ---------------- convert + histogram in one pass --------------------------------------
__global__ void k_converthist(const void* __restrict__ ei) {
    int e = blockIdx.x * blockDim.x + threadIdx.x;
    if (e >= EE) return;
    int s = clampi(load_idx(ei, e), 0, NN - 1);
    int d = clampi(load_idx(ei, (long long)EE + e), 0, NN - 1);
    g_src32[e] = s;
    g_dst32[e] = d;
    atomicAdd(&g_deg2[d], 1);
    atomicAdd(&g_deg2[NN + s], 1);
}

// ---------------- dinv from dst degree (forks gemm1 early) ------------------------------
__global__ void k_dinv() {
    int i = blockIdx.x * blockDim.x + threadIdx.x;
    if (i < NN) g_dinv[i] = rsqrtf((float)(g_deg2[i] + 1));   // +1 = self-loop
}

// ---------------- 3-phase exclusive scan over g_deg2[0..200k) --------------------------
__global__ void k_scan1() {
    __shared__ int s[1024];
    int b = blockIdx.x, t = threadIdx.x;
    int i = b * 1024 + t;
    int v = (i < NN2) ? g_deg2[i] : 0;
    s[t] = v;
    __syncthreads();
    for (int off = 1; off < 1024; off <<= 1) {
        int x = (t >= off) ? s[t - off] : 0;
        __syncthreads();
        s[t] += x;
        __syncthreads();
    }
    if (i < NN2) {
        if (i < NN) g_rowptr[i] = s[t] - v;
        else        g_sptr[i - NN] = s[t] - v;
    }
    if (t == 1023) g_blksums[b] = s[t];
}

__global__ void k_scan2(int nb) {
    __shared__ int s[256];
    int t = threadIdx.x;
    int v = (t < nb) ? g_blksums[t] : 0;
    s[t] = v;
    __syncthreads();
    for (int off = 1; off < 256; off <<= 1) {
        int x = (t >= off) ? s[t - off] : 0;
        __syncthreads();
        s[t] += x;
        __syncthreads();
    }
    g_blksums[t] = s[t] - v;
}

__global__ void k_scan3() {
    int b = blockIdx.x, t = threadIdx.x;
    int i = b * 1024 + t;
    if (i < NN2) {
        int add = g_blksums[b];
        if (i < NN) {
            int rp = g_rowptr[i] + add;
            g_rowptr[i] = rp;
            g_curn[i] = rp;
        } else {
            int sp = g_sptr[i - NN] + add - EE;           // src scan offset by first-half total
            g_sptr[i - NN] = sp;
            g_curs[i - NN] = sp;
        }
    }
    if (i == 0) { g_rowptr[NN] = EE; g_sptr[NN] = EE; }
}

// ---------------- nptr via binary search on sorted batch; egptr = sptr[nptr] ------------
__global__ void k_nptr(const void* __restrict__ batch) {
    int g = threadIdx.x;    // 512
    int lo = 0, hi = NN;
    while (lo < hi) {
        int mid = (lo + hi) >> 1;
        if (load_idx(batch, mid) < g) lo = mid + 1;
        else hi = mid;
    }
    g_nptr[g] = lo;
    g_egptr[g] = g_sptr[lo];
    if (g == 0) { g_nptr[GG] = NN; g_egptr[GG] = EE; }
}

// ---------------- CSR scatter (coalesced int32 reads, two independent chains) -----------
__global__ void k_scatter() {
    int e = blockIdx.x * blockDim.x + threadIdx.x;
    if (e >= EE) return;
    int s = g_src32[e];
    int d = g_dst32[e];
    int p = atomicAdd(&g_curn[d], 1);
    if (p >= 0 && p < EE) g_csrsrc[p] = s;
    int p2 = atomicAdd(&g_curs[s], 1);
    if (p2 >= 0 && p2 < EE) g_eid[p2] = e;
}

// ---------------- GEMM (FFMA2, 8x8 regtile, double-buffered): g_bufA = (X @ W) * dinv ------
#define XPAD 132
template <bool FIRST>
__global__ void __launch_bounds__(256, 2)
k_gemm(const float* __restrict__ Xext, const float* __restrict__ W, int nrows) {
    const float* __restrict__ X = FIRST ? Xext : (const float*)g_bufB;
    float* __restrict__ Y = g_bufA;
    __shared__ __align__(16) float xs[2][16][XPAD];
    __shared__ __align__(16) float ws[2][16][128];
    int tid = threadIdx.x;
    int c = tid & 15;   // cols c*8 .. c*8+7
    int r = tid >> 4;   // rows r*8 .. r*8+7
    int row0 = blockIdx.x * 128;

    int x_kq = tid & 3;
    int x_rr0 = tid >> 2;

    u64 acc2[8][4];
#pragma unroll
    for (int i = 0; i < 8; i++)
#pragma unroll
        for (int j = 0; j < 4; j++) acc2[i][j] = 0ull;

#pragma unroll
    for (int l = 0; l < 2; l++) {
        int rr = x_rr0 + l * 64;
        int grow = row0 + rr;
        float4 v = make_float4(0.f, 0.f, 0.f, 0.f);
        if (grow < nrows)
            v = *reinterpret_cast<const float4*>(&X[grow * DD + x_kq * 4]);
        xs[0][x_kq * 4 + 0][rr] = v.x;
        xs[0][x_kq * 4 + 1][rr] = v.y;
        xs[0][x_kq * 4 + 2][rr] = v.z;
        xs[0][x_kq * 4 + 3][rr] = v.w;
    }
#pragma unroll
    for (int l = 0; l < 8; l++) {
        int idx = tid + l * 256;
        ws[0][idx >> 7][idx & 127] = W[(idx >> 7) * DD + (idx & 127)];
    }
    __syncthreads();

    for (int it = 0; it < 8; it++) {
        int cur = it & 1;
        float4 nx[2];
        float nw[8];
        if (it < 7) {
            int kc = (it + 1) * 16;
#pragma unroll
            for (int l = 0; l < 2; l++) {
                int rr = x_rr0 + l * 64;
                int grow = row0 + rr;
                nx[l] = make_float4(0.f, 0.f, 0.f, 0.f);
                if (grow < nrows)
                    nx[l] = *reinterpret_cast<const float4*>(&X[grow * DD + kc + x_kq * 4]);
            }
#pragma unroll
            for (int l = 0; l < 8; l++) {
                int idx = tid + l * 256;
                nw[l] = W[(kc + (idx >> 7)) * DD + (idx & 127)];
            }
        }
#pragma unroll
        for (int k = 0; k < 16; k++) {
            float4 xa = *reinterpret_cast<float4*>(&xs[cur][k][r * 8]);
            float4 xb = *reinterpret_cast<float4*>(&xs[cur][k][r * 8 + 4]);
            ulonglong2 w01 = *reinterpret_cast<ulonglong2*>(&ws[cur][k][c * 8]);
            ulonglong2 w23 = *reinterpret_cast<ulonglong2*>(&ws[cur][k][c * 8 + 4]);
            u64 wp[4] = {w01.x, w01.y, w23.x, w23.y};
            u64 xr2[8] = {pack_dup(xa.x), pack_dup(xa.y), pack_dup(xa.z), pack_dup(xa.w),
                          pack_dup(xb.x), pack_dup(xb.y), pack_dup(xb.z), pack_dup(xb.w)};
#pragma unroll
            for (int i = 0; i < 8; i++)
#pragma unroll
                for (int j = 0; j < 4; j++)
                    ffma2(acc2[i][j], xr2[i], wp[j]);
        }
        if (it < 7) {
            int nxt = cur ^ 1;
#pragma unroll
            for (int l = 0; l < 2; l++) {
                int rr = x_rr0 + l * 64;
                xs[nxt][x_kq * 4 + 0][rr] = nx[l].x;
                xs[nxt][x_kq * 4 + 1][rr] = nx[l].y;
                xs[nxt][x_kq * 4 + 2][rr] = nx[l].z;
                xs[nxt][x_kq * 4 + 3][rr] = nx[l].w;
            }
#pragma unroll
            for (int l = 0; l < 8; l++) {
                int idx = tid + l * 256;
                ws[nxt][idx >> 7][idx & 127] = nw[l];
            }
        }
        __syncthreads();
    }
#pragma unroll
    for (int i = 0; i < 8; i++) {
        int grow = row0 + r * 8 + i;
        if (grow < nrows) {
            float d = g_dinv[grow];
            float2 p0 = unpack2(acc2[i][0]);
            float2 p1 = unpack2(acc2[i][1]);
            float2 p2 = unpack2(acc2[i][2]);
            float2 p3 = unpack2(acc2[i][3]);
            float4 o0 = make_float4(p0.x * d, p0.y * d, p1.x * d, p1.y * d);
            float4 o1 = make_float4(p2.x * d, p2.y * d, p3.x * d, p3.y * d);
            *reinterpret_cast<float4*>(&Y[grow * DD + c * 8]) = o0;
            *reinterpret_cast<float4*>(&Y[grow * DD + c * 8 + 4]) = o1;
        }
    }
}

// ---------------- gather + bias + BN(eval) + ReLU ----------------------------------
__global__ void k_gather(const float* __restrict__ B, const float* __restrict__ GA,
                         const float* __restrict__ BT, const float* __restrict__ M,
                         const float* __restrict__ V) {
    int warp = (blockIdx.x * blockDim.x + threadIdx.x) >> 5;
    int lane = threadIdx.x & 31;
    if (warp >= NN) return;
    int node = warp;
    float di = g_dinv[node];
    const float4* xw4 = reinterpret_cast<const float4*>((const float*)g_bufA);
    float4 a0 = xw4[node * 32 + lane];   // self term (already * dinv_node)
    float4 a1 = make_float4(0.f, 0.f, 0.f, 0.f);
    float4 a2 = make_float4(0.f, 0.f, 0.f, 0.f);
    float4 a3 = make_float4(0.f, 0.f, 0.f, 0.f);
    int jb = g_rowptr[node], je = g_rowptr[node + 1];
    int j = jb;
    for (; j + 3 < je; j += 4) {
        int s0 = g_csrsrc[j + 0];
        int s1 = g_csrsrc[j + 1];
        int s2 = g_csrsrc[j + 2];
        int s3 = g_csrsrc[j + 3];
        float4 v0 = xw4[s0 * 32 + lane];
        float4 v1 = xw4[s1 * 32 + lane];
        float4 v2 = xw4[s2 * 32 + lane];
        float4 v3 = xw4[s3 * 32 + lane];
        a0.x += v0.x; a0.y += v0.y; a0.z += v0.z; a0.w += v0.w;
        a1.x += v1.x; a1.y += v1.y; a1.z += v1.z; a1.w += v1.w;
        a2.x += v2.x; a2.y += v2.y; a2.z += v2.z; a2.w += v2.w;
        a3.x += v3.x; a3.y += v3.y; a3.z += v3.z; a3.w += v3.w;
    }
    for (; j < je; j++) {
        int s = g_csrsrc[j];
        float4 v = xw4[s * 32 + lane];
        a0.x += v.x; a0.y += v.y; a0.z += v.z; a0.w += v.w;
    }
    float4 acc;
    acc.x = (a0.x + a1.x) + (a2.x + a3.x);
    acc.y = (a0.y + a1.y) + (a2.y + a3.y);
    acc.z = (a0.z + a1.z) + (a2.z + a3.z);
    acc.w = (a0.w + a1.w) + (a2.w + a3.w);
    int f = lane * 4;
    float4 b4  = *reinterpret_cast<const float4*>(&B[f]);
    float4 g4  = *reinterpret_cast<const float4*>(&GA[f]);
    float4 bt4 = *reinterpret_cast<const float4*>(&BT[f]);
    float4 m4  = *reinterpret_cast<const float4*>(&M[f]);
    float4 vv4 = *reinterpret_cast<const float4*>(&V[f]);
    float4 o;
    o.x = fmaxf((acc.x * di + b4.x - m4.x) * rsqrtf(vv4.x + BN_EPS) * g4.x + bt4.x, 0.f);
    o.y = fmaxf((acc.y * di + b4.y - m4.y) * rsqrtf(vv4.y + BN_EPS) * g4.y + bt4.y, 0.f);
    o.z = fmaxf((acc.z * di + b4.z - m4.z) * rsqrtf(vv4.z + BN_EPS) * g4.z + bt4.z, 0.f);
    o.w = fmaxf((acc.w * di + b4.w - m4.w) * rsqrtf(vv4.w + BN_EPS) * g4.w + bt4.w, 0.f);
    float4* out4 = reinterpret_cast<float4*>((float*)g_bufB);
    out4[node * 32 + lane] = o;
}

// ---------------- edge MLP first layer, summed per graph (FFMA2, 2-edge ILP) -----------------
#define EBLK 8
__global__ void k_edgemlp(const float* __restrict__ EA, const float* __restrict__ W1e,
                          const float* __restrict__ B1e) {
    int g = blockIdx.x >> 3;          // graph
    int q = blockIdx.x & (EBLK - 1);  // slice
    int tid = threadIdx.x, warp = tid >> 5, lane = tid & 31;
    __shared__ float eas[8][2][16];
    __shared__ float red[DD];
    ulonglong2 wc[16];
#pragma unroll
    for (int k = 0; k < 16; k++)
        wc[k] = *reinterpret_cast<const ulonglong2*>(&W1e[k * DD + lane * 4]);
    ulonglong2 b2 = *reinterpret_cast<const ulonglong2*>(&B1e[lane * 4]);

    int gb = g_egptr[g], ge = g_egptr[g + 1];
    int cnt = ge - gb;
    int per = (cnt + EBLK - 1) / EBLK;
    int jb = gb + q * per;
    int je = min(jb + per, ge);

    float4 acc = make_float4(0.f, 0.f, 0.f, 0.f);
    for (int j = jb + warp; j < je; j += 16) {
        int j2 = j + 8;
        bool has2 = (j2 < je);
        int e0 = g_eid[j];
        int e1 = has2 ? g_eid[j2] : e0;
        if (lane < 16) eas[warp][0][lane] = EA[(long long)e0 * DEE + lane];
        else           eas[warp][1][lane - 16] = EA[(long long)e1 * DEE + (lane - 16)];
        __syncwarp();
        u64 h0 = b2.x, h1 = b2.y, h2 = b2.x, h3 = b2.y;
#pragma unroll
        for (int k = 0; k < 16; k++) {
            u64 p0 = pack_dup(eas[warp][0][k]);
            u64 p1 = pack_dup(eas[warp][1][k]);
            ffma2(h0, p0, wc[k].x);
            ffma2(h1, p0, wc[k].y);
            ffma2(h2, p1, wc[k].x);
            ffma2(h3, p1, wc[k].y);
        }
        float2 u0 = unpack2(h0), u1 = unpack2(h1);
        acc.x += fmaxf(u0.x, 0.f);
        acc.y += fmaxf(u0.y, 0.f);
        acc.z += fmaxf(u1.x, 0.f);
        acc.w += fmaxf(u1.y, 0.f);
        if (has2) {
            float2 u2 = unpack2(h2), u3 = unpack2(h3);
            acc.x += fmaxf(u2.x, 0.f);
            acc.y += fmaxf(u2.y, 0.f);
            acc.z += fmaxf(u3.x, 0.f);
            acc.w += fmaxf(u3.y, 0.f);
        }
        __syncwarp();
    }
    if (tid < DD) red[tid] = 0.f;
    __syncthreads();
    int f = lane * 4;
    atomicAdd(&red[f + 0], acc.x);
    atomicAdd(&red[f + 1], acc.y);
    atomicAdd(&red[f + 2], acc.z);
    atomicAdd(&red[f + 3], acc.w);
    __syncthreads();
    if (tid < DD) atomicAdd(&g_hsum[g * DD + tid], red[tid]);
}

// ---------------- final combine: node segment-mean + edge GEMM ----------------------------
__global__ void k_final(const float* __restrict__ We2, const float* __restrict__ be2,
                        float* __restrict__ out) {
    int g = blockIdx.x;
    int t = threadIdx.x;   // 128
    __shared__ float hm[DD];
    int ec = g_egptr[g + 1] - g_egptr[g];
    float inv_e = (ec > 0) ? (1.f / (float)ec) : 0.f;
    hm[t] = g_hsum[g * DD + t] * inv_e;

    int ns = g_nptr[g], ne = g_nptr[g + 1];
    const float* __restrict__ H = (const float*)g_bufB;
    float a0 = 0.f, a1 = 0.f, a2 = 0.f, a3 = 0.f;
    int rr = ns;
    for (; rr + 3 < ne; rr += 4) {
        a0 += H[(long long)rr * DD + t];
        a1 += H[(long long)(rr + 1) * DD + t];
        a2 += H[(long long)(rr + 2) * DD + t];
        a3 += H[(long long)(rr + 3) * DD + t];
    }
    for (; rr < ne; rr++) a0 += H[(long long)rr * DD + t];
    float nsumv = (a0 + a1) + (a2 + a3);

    __syncthreads();
    float acc = be2[t];
#pragma unroll 4
    for (int k = 0; k < DD; k++)
        acc = fmaf(hm[k], We2[k * DD + t], acc);
    if (ec == 0) acc = 0.f;
    int nc = ne - ns;
    float gr = nsumv / fmaxf((float)nc, 1.f);
    out[g * DD + t] = gr + acc;
}

// ---------------- launch ------------------------------------------------------------------------
extern "C" void kernel_launch(void* const* d_in, const int* in_sizes, int n_in,
                              void* d_out, int out_size) {
    // Resolve pointers by size signature.
    const float* x = 0;  const void* ei = 0;  const void* batch = 0;  const float* ea = 0;
    const float* w16k[3] = {0, 0, 0};   // W1, W2, We2 (in metadata order)
    const float* v128[12] = {0};        // b1,g1,bt1,m1,v1,b2,g2,bt2,m2,v2,be1,be2
    const float* We1 = 0;
    int n16k = 0, n128 = 0;
    for (int i = 0; i < n_in; i++) {
        long long sz = in_sizes[i];
        if      (sz == (long long)NN * DD) { if (!x) x = (const float*)d_in[i]; }
        else if (sz == 2LL * EE)           { if (!ei) ei = d_in[i]; }
        else if (sz == NN)                 { if (!batch) batch = d_in[i]; }
        else if (sz == (long long)EE * DEE){ if (!ea) ea = (const float*)d_in[i]; }
        else if (sz == DD * DD)            { if (n16k < 3) w16k[n16k++] = (const float*)d_in[i]; }
        else if (sz == DEE * DD)           { if (!We1) We1 = (const float*)d_in[i]; }
        else if (sz == DD)                 { if (n128 < 12) v128[n128++] = (const float*)d_in[i]; }
    }
    const float *W1 = w16k[0], *W2 = w16k[1], *We2 = w16k[2];
    const float *b1 = v128[0], *g1 = v128[1], *bt1 = v128[2], *m1 = v128[3], *v1 = v128[4];
    const float *b2 = v128[5], *g2 = v128[6], *bt2 = v128[7], *m2 = v128[8], *v2 = v128[9];
    const float *be1 = v128[10], *be2 = v128[11];
    float* out = (float*)d_out;

    // one-time stream/event setup (created on the first, non-capturing call)
    static cudaStream_t sB = 0, sC = 0;
    static cudaEvent_t evDinv = 0, evGemm1 = 0, evScat = 0, evEdge = 0;
    if (!sB) {
        cudaStreamCreateWithFlags(&sB, cudaStreamNonBlocking);
        cudaStreamCreateWithFlags(&sC, cudaStreamNonBlocking);
        cudaEventCreateWithFlags(&evDinv, cudaEventDisableTiming);
        cudaEventCreateWithFlags(&evGemm1, cudaEventDisableTiming);
        cudaEventCreateWithFlags(&evScat, cudaEventDisableTiming);
        cudaEventCreateWithFlags(&evEdge, cudaEventDisableTiming);
    }

    const int nb1 = (NN2 + 1023) / 1024;   // 196

    // main stream: prep chain
    k_detect<<<1, 256>>>((const int*)ei);
    k_init<<<256, 256>>>();
    k_converthist<<<(EE + 255) / 256, 256>>>(ei);
    k_dinv<<<(NN + 255) / 256, 256>>>();
    cudaEventRecord(evDinv, 0);

    // side stream B: layer-1 GEMM (needs x, W1, dinv only) overlaps scans+scatter
    cudaStreamWaitEvent(sB, evDinv, 0);
    k_gemm<true><<<(NN + 127) / 128, 256, 0, sB>>>(x, W1, NN);
    cudaEventRecord(evGemm1, sB);

    // main stream continues: scans -> nptr -> scatter
    k_scan1<<<nb1, 1024>>>();
    k_scan2<<<1, 256>>>(nb1);
    k_scan3<<<nb1, 1024>>>();
    k_nptr<<<1, 512>>>(batch);
    k_scatter<<<(EE + 255) / 256, 256>>>();
    cudaEventRecord(evScat, 0);

    // side stream C: edge MLP (needs src-CSR) overlaps gather1/gemm2/gather2
    cudaStreamWaitEvent(sC, evScat, 0);
    k_edgemlp<<<GG * EBLK, 256, 0, sC>>>(ea, We1, be1);
    cudaEventRecord(evEdge, sC);

    // main stream: join gemm1, then the node chain
    cudaStreamWaitEvent(0, evGemm1, 0);
    k_gather<<<(NN * 32 + 255) / 256, 256>>>(b1, g1, bt1, m1, v1);
    k_gemm<false><<<(NN + 127) / 128, 256>>>(x, W2, NN);
    k_gather<<<(NN * 32 + 255) / 256, 256>>>(b2, g2, bt2, m2, v2);

    // join edge branch, combine
    cudaStreamWaitEvent(0, evEdge, 0);
    k_final<<<GG, 128>>>(We2, be2, out);
}

// round 11
// speedup vs baseline: 2.4297x; 1.0631x over previous
#include <cuda_runtime.h>
#include <cuda_fp16.h>

#define NN 100000
#define NN2 200000
#define DD 128
#define EE 1600000
#define DEE 16
#define GG 512
#define BN_EPS 1e-5f

typedef unsigned long long u64;

// ---------------- f32x2 packed helpers -----------------------------------------
__device__ __forceinline__ void ffma2(u64& d, u64 a, u64 b) {
    asm("fma.rn.f32x2 %0, %1, %2, %0;" : "+l"(d) : "l"(a), "l"(b));
}
__device__ __forceinline__ u64 pack_dup(float x) {
    u64 d; unsigned xi = __float_as_uint(x);
    asm("mov.b64 %0, {%1, %1};" : "=l"(d) : "r"(xi));
    return d;
}
__device__ __forceinline__ float2 unpack2(u64 v) {
    unsigned lo, hi;
    asm("mov.b64 {%0, %1}, %2;" : "=r"(lo), "=r"(hi) : "l"(v));
    return make_float2(__uint_as_float(lo), __uint_as_float(hi));
}

// ---------------- scratch (static device globals; no allocation) -----------------
__device__ __align__(16) __half g_bufA[NN * DD];         // 25.6 MB (fp16 gather payload)
__device__ __align__(16) float g_bufB[NN * DD];          // 51.2 MB
__device__ int   g_deg2[NN2];             // [0,NN): dst degree, [NN,2NN): src degree
__device__ int   g_rowptr[NN + 1];        // dst-CSR row pointers
__device__ int   g_sptr[NN + 1];          // src-CSR row pointers
__device__ int   g_curn[NN];
__device__ int   g_curs[NN];
__device__ int   g_csrsrc[EE];            // dst-CSR payload: src node
__device__ int   g_eid[EE];               // src-CSR payload: edge id
__device__ int   g_src32[EE];
__device__ int   g_dst32[EE];
__device__ int   g_egptr[GG + 1];
__device__ int   g_nptr[GG + 1];
__device__ float g_dinv[NN];
__device__ float g_hsum[GG * DD];
__device__ int   g_blksums[256];
__device__ int   g_is64;

// ---------------- index helpers (dtype-agnostic) ----------------------------------
__device__ __forceinline__ int load_idx(const void* p, long long i) {
    if (g_is64) return (int)((const long long*)p)[i];
    return ((const int*)p)[i];
}
__device__ __forceinline__ int clampi(int v, int lo, int hi) {
    return v < lo ? lo : (v > hi ? hi : v);
}

// ---------------- dtype detection: int64 values <2^31 have zero odd words ----------
__global__ void k_detect(const int* __restrict__ w) {
    __shared__ int ok;
    if (threadIdx.x == 0) ok = 1;
    __syncthreads();
    int bad = 0;
    for (int i = threadIdx.x; i < 2048; i += blockDim.x)
        if (w[2 * i + 1] != 0) bad = 1;
    if (bad) atomicAnd(&ok, 0);
    __syncthreads();
    if (threadIdx.x == 0) g_is64 = ok;
}

// ---------------- init: zero histograms / accumulators ------------------------------
__global__ void k_init() {
    int i = blockIdx.x * blockDim.x + threadIdx.x;
    int stride = gridDim.x * blockDim.x;
    for (int j = i; j < NN2; j += stride) g_deg2[j] = 0;
    for (int j = i; j < GG * DD; j += stride) g_hsum[j] = 0.f;
}

// ---------------- convert + histogram in one pass --------------------------------------
__global__ void k_converthist(const void* __restrict__ ei) {
    int e = blockIdx.x * blockDim.x + threadIdx.x;
    if (e >= EE) return;
    int s = clampi(load_idx(ei, e), 0, NN - 1);
    int d = clampi(load_idx(ei, (long long)EE + e), 0, NN - 1);
    g_src32[e] = s;
    g_dst32[e] = d;
    atomicAdd(&g_deg2[d], 1);
    atomicAdd(&g_deg2[NN + s], 1);
}

// ---------------- dinv from dst degree (forks gemm1 early) ------------------------------
__global__ void k_dinv() {
    int i = blockIdx.x * blockDim.x + threadIdx.x;
    if (i < NN) g_dinv[i] = rsqrtf((float)(g_deg2[i] + 1));   // +1 = self-loop
}

// ---------------- 3-phase exclusive scan over g_deg2[0..200k) --------------------------
__global__ void k_scan1() {
    __shared__ int s[1024];
    int b = blockIdx.x, t = threadIdx.x;
    int i = b * 1024 + t;
    int v = (i < NN2) ? g_deg2[i] : 0;
    s[t] = v;
    __syncthreads();
    for (int off = 1; off < 1024; off <<= 1) {
        int x = (t >= off) ? s[t - off] : 0;
        __syncthreads();
        s[t] += x;
        __syncthreads();
    }
    if (i < NN2) {
        if (i < NN) g_rowptr[i] = s[t] - v;
        else        g_sptr[i - NN] = s[t] - v;
    }
    if (t == 1023) g_blksums[b] = s[t];
}

__global__ void k_scan2(int nb) {
    __shared__ int s[256];
    int t = threadIdx.x;
    int v = (t < nb) ? g_blksums[t] : 0;
    s[t] = v;
    __syncthreads();
    for (int off = 1; off < 256; off <<= 1) {
        int x = (t >= off) ? s[t - off] : 0;
        __syncthreads();
        s[t] += x;
        __syncthreads();
    }
    g_blksums[t] = s[t] - v;
}

__global__ void k_scan3() {
    int b = blockIdx.x, t = threadIdx.x;
    int i = b * 1024 + t;
    if (i < NN2) {
        int add = g_blksums[b];
        if (i < NN) {
            int rp = g_rowptr[i] + add;
            g_rowptr[i] = rp;
            g_curn[i] = rp;
        } else {
            int sp = g_sptr[i - NN] + add - EE;           // src scan offset by first-half total
            g_sptr[i - NN] = sp;
            g_curs[i - NN] = sp;
        }
    }
    if (i == 0) { g_rowptr[NN] = EE; g_sptr[NN] = EE; }
}

// ---------------- nptr via binary search on sorted batch; egptr = sptr[nptr] ------------
__global__ void k_nptr(const void* __restrict__ batch) {
    int g = threadIdx.x;    // 512
    int lo = 0, hi = NN;
    while (lo < hi) {
        int mid = (lo + hi) >> 1;
        if (load_idx(batch, mid) < g) lo = mid + 1;
        else hi = mid;
    }
    g_nptr[g] = lo;
    g_egptr[g] = g_sptr[lo];
    if (g == 0) { g_nptr[GG] = NN; g_egptr[GG] = EE; }
}

// ---------------- CSR scatter (coalesced int32 reads, two independent chains) -----------
__global__ void k_scatter() {
    int e = blockIdx.x * blockDim.x + threadIdx.x;
    if (e >= EE) return;
    int s = g_src32[e];
    int d = g_dst32[e];
    int p = atomicAdd(&g_curn[d], 1);
    if (p >= 0 && p < EE) g_csrsrc[p] = s;
    int p2 = atomicAdd(&g_curs[s], 1);
    if (p2 >= 0 && p2 < EE) g_eid[p2] = e;
}

// ---------------- GEMM (FFMA2, 8x8 regtile, double-buffered): g_bufA = fp16((X@W)*dinv) ----
#define XPAD 132
template <bool FIRST>
__global__ void __launch_bounds__(256, 2)
k_gemm(const float* __restrict__ Xext, const float* __restrict__ W, int nrows) {
    const float* __restrict__ X = FIRST ? Xext : (const float*)g_bufB;
    __half* __restrict__ Y = g_bufA;
    __shared__ __align__(16) float xs[2][16][XPAD];
    __shared__ __align__(16) float ws[2][16][128];
    int tid = threadIdx.x;
    int c = tid & 15;   // cols c*8 .. c*8+7
    int r = tid >> 4;   // rows r*8 .. r*8+7
    int row0 = blockIdx.x * 128;

    int x_kq = tid & 3;
    int x_rr0 = tid >> 2;

    u64 acc2[8][4];
#pragma unroll
    for (int i = 0; i < 8; i++)
#pragma unroll
        for (int j = 0; j < 4; j++) acc2[i][j] = 0ull;

#pragma unroll
    for (int l = 0; l < 2; l++) {
        int rr = x_rr0 + l * 64;
        int grow = row0 + rr;
        float4 v = make_float4(0.f, 0.f, 0.f, 0.f);
        if (grow < nrows)
            v = *reinterpret_cast<const float4*>(&X[grow * DD + x_kq * 4]);
        xs[0][x_kq * 4 + 0][rr] = v.x;
        xs[0][x_kq * 4 + 1][rr] = v.y;
        xs[0][x_kq * 4 + 2][rr] = v.z;
        xs[0][x_kq * 4 + 3][rr] = v.w;
    }
#pragma unroll
    for (int l = 0; l < 8; l++) {
        int idx = tid + l * 256;
        ws[0][idx >> 7][idx & 127] = W[(idx >> 7) * DD + (idx & 127)];
    }
    __syncthreads();

    for (int it = 0; it < 8; it++) {
        int cur = it & 1;
        float4 nx[2];
        float nw[8];
        if (it < 7) {
            int kc = (it + 1) * 16;
#pragma unroll
            for (int l = 0; l < 2; l++) {
                int rr = x_rr0 + l * 64;
                int grow = row0 + rr;
                nx[l] = make_float4(0.f, 0.f, 0.f, 0.f);
                if (grow < nrows)
                    nx[l] = *reinterpret_cast<const float4*>(&X[grow * DD + kc + x_kq * 4]);
            }
#pragma unroll
            for (int l = 0; l < 8; l++) {
                int idx = tid + l * 256;
                nw[l] = W[(kc + (idx >> 7)) * DD + (idx & 127)];
            }
        }
#pragma unroll
        for (int k = 0; k < 16; k++) {
            float4 xa = *reinterpret_cast<float4*>(&xs[cur][k][r * 8]);
            float4 xb = *reinterpret_cast<float4*>(&xs[cur][k][r * 8 + 4]);
            ulonglong2 w01 = *reinterpret_cast<ulonglong2*>(&ws[cur][k][c * 8]);
            ulonglong2 w23 = *reinterpret_cast<ulonglong2*>(&ws[cur][k][c * 8 + 4]);
            u64 wp[4] = {w01.x, w01.y, w23.x, w23.y};
            u64 xr2[8] = {pack_dup(xa.x), pack_dup(xa.y), pack_dup(xa.z), pack_dup(xa.w),
                          pack_dup(xb.x), pack_dup(xb.y), pack_dup(xb.z), pack_dup(xb.w)};
#pragma unroll
            for (int i = 0; i < 8; i++)
#pragma unroll
                for (int j = 0; j < 4; j++)
                    ffma2(acc2[i][j], xr2[i], wp[j]);
        }
        if (it < 7) {
            int nxt = cur ^ 1;
#pragma unroll
            for (int l = 0; l < 2; l++) {
                int rr = x_rr0 + l * 64;
                xs[nxt][x_kq * 4 + 0][rr] = nx[l].x;
                xs[nxt][x_kq * 4 + 1][rr] = nx[l].y;
                xs[nxt][x_kq * 4 + 2][rr] = nx[l].z;
                xs[nxt][x_kq * 4 + 3][rr] = nx[l].w;
            }
#pragma unroll
            for (int l = 0; l < 8; l++) {
                int idx = tid + l * 256;
                ws[nxt][idx >> 7][idx & 127] = nw[l];
            }
        }
        __syncthreads();
    }
#pragma unroll
    for (int i = 0; i < 8; i++) {
        int grow = row0 + r * 8 + i;
        if (grow < nrows) {
            float d = g_dinv[grow];
            float2 p0 = unpack2(acc2[i][0]);
            float2 p1 = unpack2(acc2[i][1]);
            float2 p2 = unpack2(acc2[i][2]);
            float2 p3 = unpack2(acc2[i][3]);
            __half2 hh[4];
            hh[0] = __floats2half2_rn(p0.x * d, p0.y * d);
            hh[1] = __floats2half2_rn(p1.x * d, p1.y * d);
            hh[2] = __floats2half2_rn(p2.x * d, p2.y * d);
            hh[3] = __floats2half2_rn(p3.x * d, p3.y * d);
            *reinterpret_cast<uint4*>(&Y[grow * DD + c * 8]) = *reinterpret_cast<uint4*>(hh);
        }
    }
}

// ---------------- gather (fp16 payload) + bias + BN(eval) + ReLU ------------------------
__global__ void k_gather(const float* __restrict__ B, const float* __restrict__ GA,
                         const float* __restrict__ BT, const float* __restrict__ M,
                         const float* __restrict__ V) {
    int warp = (blockIdx.x * blockDim.x + threadIdx.x) >> 5;
    int lane = threadIdx.x & 31;
    if (warp >= NN) return;
    int node = warp;
    float di = g_dinv[node];
    const uint2* xw2 = reinterpret_cast<const uint2*>((const __half*)g_bufA);
    // lane covers features lane*4 .. lane*4+3 = one uint2 (4 halfs)
    uint2 u = xw2[node * 32 + lane];
    float2 s01 = __half22float2(*reinterpret_cast<__half2*>(&u.x));
    float2 s23 = __half22float2(*reinterpret_cast<__half2*>(&u.y));
    float4 a0 = make_float4(s01.x, s01.y, s23.x, s23.y);
    float4 a1 = make_float4(0.f, 0.f, 0.f, 0.f);
    float4 a2 = make_float4(0.f, 0.f, 0.f, 0.f);
    float4 a3 = make_float4(0.f, 0.f, 0.f, 0.f);
    int jb = g_rowptr[node], je = g_rowptr[node + 1];
    int j = jb;
    for (; j + 3 < je; j += 4) {
        int s0 = g_csrsrc[j + 0];
        int s1 = g_csrsrc[j + 1];
        int s2 = g_csrsrc[j + 2];
        int s3 = g_csrsrc[j + 3];
        uint2 u0 = xw2[s0 * 32 + lane];
        uint2 u1 = xw2[s1 * 32 + lane];
        uint2 u2 = xw2[s2 * 32 + lane];
        uint2 u3 = xw2[s3 * 32 + lane];
        float2 f0a = __half22float2(*reinterpret_cast<__half2*>(&u0.x));
        float2 f0b = __half22float2(*reinterpret_cast<__half2*>(&u0.y));
        float2 f1a = __half22float2(*reinterpret_cast<__half2*>(&u1.x));
        float2 f1b = __half22float2(*reinterpret_cast<__half2*>(&u1.y));
        float2 f2a = __half22float2(*reinterpret_cast<__half2*>(&u2.x));
        float2 f2b = __half22float2(*reinterpret_cast<__half2*>(&u2.y));
        float2 f3a = __half22float2(*reinterpret_cast<__half2*>(&u3.x));
        float2 f3b = __half22float2(*reinterpret_cast<__half2*>(&u3.y));
        a0.x += f0a.x; a0.y += f0a.y; a0.z += f0b.x; a0.w += f0b.y;
        a1.x += f1a.x; a1.y += f1a.y; a1.z += f1b.x; a1.w += f1b.y;
        a2.x += f2a.x; a2.y += f2a.y; a2.z += f2b.x; a2.w += f2b.y;
        a3.x += f3a.x; a3.y += f3a.y; a3.z += f3b.x; a3.w += f3b.y;
    }
    for (; j < je; j++) {
        int s = g_csrsrc[j];
        uint2 uv = xw2[s * 32 + lane];
        float2 fa = __half22float2(*reinterpret_cast<__half2*>(&uv.x));
        float2 fb = __half22float2(*reinterpret_cast<__half2*>(&uv.y));
        a0.x += fa.x; a0.y += fa.y; a0.z += fb.x; a0.w += fb.y;
    }
    float4 acc;
    acc.x = (a0.x + a1.x) + (a2.x + a3.x);
    acc.y = (a0.y + a1.y) + (a2.y + a3.y);
    acc.z = (a0.z + a1.z) + (a2.z + a3.z);
    acc.w = (a0.w + a1.w) + (a2.w + a3.w);
    int f = lane * 4;
    float4 b4  = *reinterpret_cast<const float4*>(&B[f]);
    float4 g4  = *reinterpret_cast<const float4*>(&GA[f]);
    float4 bt4 = *reinterpret_cast<const float4*>(&BT[f]);
    float4 m4  = *reinterpret_cast<const float4*>(&M[f]);
    float4 vv4 = *reinterpret_cast<const float4*>(&V[f]);
    float4 o;
    o.x = fmaxf((acc.x * di + b4.x - m4.x) * rsqrtf(vv4.x + BN_EPS) * g4.x + bt4.x, 0.f);
    o.y = fmaxf((acc.y * di + b4.y - m4.y) * rsqrtf(vv4.y + BN_EPS) * g4.y + bt4.y, 0.f);
    o.z = fmaxf((acc.z * di + b4.z - m4.z) * rsqrtf(vv4.z + BN_EPS) * g4.z + bt4.z, 0.f);
    o.w = fmaxf((acc.w * di + b4.w - m4.w) * rsqrtf(vv4.w + BN_EPS) * g4.w + bt4.w, 0.f);
    float4* out4 = reinterpret_cast<float4*>((float*)g_bufB);
    out4[node * 32 + lane] = o;
}

// ---------------- edge MLP first layer, summed per graph (FFMA2, 2-edge ILP) -----------------
#define EBLK 8
__global__ void k_edgemlp(const float* __restrict__ EA, const float* __restrict__ W1e,
                          const float* __restrict__ B1e) {
    int g = blockIdx.x >> 3;          // graph
    int q = blockIdx.x & (EBLK - 1);  // slice
    int tid = threadIdx.x, warp = tid >> 5, lane = tid & 31;
    __shared__ float eas[8][2][16];
    __shared__ float red[DD];
    ulonglong2 wc[16];
#pragma unroll
    for (int k = 0; k < 16; k++)
        wc[k] = *reinterpret_cast<const ulonglong2*>(&W1e[k * DD + lane * 4]);
    ulonglong2 b2 = *reinterpret_cast<const ulonglong2*>(&B1e[lane * 4]);

    int gb = g_egptr[g], ge = g_egptr[g + 1];
    int cnt = ge - gb;
    int per = (cnt + EBLK - 1) / EBLK;
    int jb = gb + q * per;
    int je = min(jb + per, ge);

    float4 acc = make_float4(0.f, 0.f, 0.f, 0.f);
    for (int j = jb + warp; j < je; j += 16) {
        int j2 = j + 8;
        bool has2 = (j2 < je);
        int e0 = g_eid[j];
        int e1 = has2 ? g_eid[j2] : e0;
        if (lane < 16) eas[warp][0][lane] = EA[(long long)e0 * DEE + lane];
        else           eas[warp][1][lane - 16] = EA[(long long)e1 * DEE + (lane - 16)];
        __syncwarp();
        u64 h0 = b2.x, h1 = b2.y, h2 = b2.x, h3 = b2.y;
#pragma unroll
        for (int k = 0; k < 16; k++) {
            u64 p0 = pack_dup(eas[warp][0][k]);
            u64 p1 = pack_dup(eas[warp][1][k]);
            ffma2(h0, p0, wc[k].x);
            ffma2(h1, p0, wc[k].y);
            ffma2(h2, p1, wc[k].x);
            ffma2(h3, p1, wc[k].y);
        }
        float2 u0 = unpack2(h0), u1 = unpack2(h1);
        acc.x += fmaxf(u0.x, 0.f);
        acc.y += fmaxf(u0.y, 0.f);
        acc.z += fmaxf(u1.x, 0.f);
        acc.w += fmaxf(u1.y, 0.f);
        if (has2) {
            float2 u2 = unpack2(h2), u3 = unpack2(h3);
            acc.x += fmaxf(u2.x, 0.f);
            acc.y += fmaxf(u2.y, 0.f);
            acc.z += fmaxf(u3.x, 0.f);
            acc.w += fmaxf(u3.y, 0.f);
        }
        __syncwarp();
    }
    if (tid < DD) red[tid] = 0.f;
    __syncthreads();
    int f = lane * 4;
    atomicAdd(&red[f + 0], acc.x);
    atomicAdd(&red[f + 1], acc.y);
    atomicAdd(&red[f + 2], acc.z);
    atomicAdd(&red[f + 3], acc.w);
    __syncthreads();
    if (tid < DD) atomicAdd(&g_hsum[g * DD + tid], red[tid]);
}

// ---------------- final combine: node segment-mean + edge GEMM ----------------------------
__global__ void k_final(const float* __restrict__ We2, const float* __restrict__ be2,
                        float* __restrict__ out) {
    int g = blockIdx.x;
    int t = threadIdx.x;   // 128
    __shared__ float hm[DD];
    int ec = g_egptr[g + 1] - g_egptr[g];
    float inv_e = (ec > 0) ? (1.f / (float)ec) : 0.f;
    hm[t] = g_hsum[g * DD + t] * inv_e;

    int ns = g_nptr[g], ne = g_nptr[g + 1];
    const float* __restrict__ H = (const float*)g_bufB;
    float a0 = 0.f, a1 = 0.f, a2 = 0.f, a3 = 0.f;
    int rr = ns;
    for (; rr + 3 < ne; rr += 4) {
        a0 += H[(long long)rr * DD + t];
        a1 += H[(long long)(rr + 1) * DD + t];
        a2 += H[(long long)(rr + 2) * DD + t];
        a3 += H[(long long)(rr + 3) * DD + t];
    }
    for (; rr < ne; rr++) a0 += H[(long long)rr * DD + t];
    float nsumv = (a0 + a1) + (a2 + a3);

    __syncthreads();
    float acc = be2[t];
#pragma unroll 4
    for (int k = 0; k < DD; k++)
        acc = fmaf(hm[k], We2[k * DD + t], acc);
    if (ec == 0) acc = 0.f;
    int nc = ne - ns;
    float gr = nsumv / fmaxf((float)nc, 1.f);
    out[g * DD + t] = gr + acc;
}

// ---------------- launch ------------------------------------------------------------------------
extern "C" void kernel_launch(void* const* d_in, const int* in_sizes, int n_in,
                              void* d_out, int out_size) {
    // Resolve pointers by size signature.
    const float* x = 0;  const void* ei = 0;  const void* batch = 0;  const float* ea = 0;
    const float* w16k[3] = {0, 0, 0};   // W1, W2, We2 (in metadata order)
    const float* v128[12] = {0};        // b1,g1,bt1,m1,v1,b2,g2,bt2,m2,v2,be1,be2
    const float* We1 = 0;
    int n16k = 0, n128 = 0;
    for (int i = 0; i < n_in; i++) {
        long long sz = in_sizes[i];
        if      (sz == (long long)NN * DD) { if (!x) x = (const float*)d_in[i]; }
        else if (sz == 2LL * EE)           { if (!ei) ei = d_in[i]; }
        else if (sz == NN)                 { if (!batch) batch = d_in[i]; }
        else if (sz == (long long)EE * DEE){ if (!ea) ea = (const float*)d_in[i]; }
        else if (sz == DD * DD)            { if (n16k < 3) w16k[n16k++] = (const float*)d_in[i]; }
        else if (sz == DEE * DD)           { if (!We1) We1 = (const float*)d_in[i]; }
        else if (sz == DD)                 { if (n128 < 12) v128[n128++] = (const float*)d_in[i]; }
    }
    const float *W1 = w16k[0], *W2 = w16k[1], *We2 = w16k[2];
    const float *b1 = v128[0], *g1 = v128[1], *bt1 = v128[2], *m1 = v128[3], *v1 = v128[4];
    const float *b2 = v128[5], *g2 = v128[6], *bt2 = v128[7], *m2 = v128[8], *v2 = v128[9];
    const float *be1 = v128[10], *be2 = v128[11];
    float* out = (float*)d_out;

    static cudaStream_t sB = 0, sC = 0;
    static cudaEvent_t evDinv = 0, evGemm1 = 0, evScat = 0, evEdge = 0;
    if (!sB) {
        cudaStreamCreateWithFlags(&sB, cudaStreamNonBlocking);
        cudaStreamCreateWithFlags(&sC, cudaStreamNonBlocking);
        cudaEventCreateWithFlags(&evDinv, cudaEventDisableTiming);
        cudaEventCreateWithFlags(&evGemm1, cudaEventDisableTiming);
        cudaEventCreateWithFlags(&evScat, cudaEventDisableTiming);
        cudaEventCreateWithFlags(&evEdge, cudaEventDisableTiming);
    }

    const int nb1 = (NN2 + 1023) / 1024;   // 196

    // main stream: prep chain
    k_detect<<<1, 256>>>((const int*)ei);
    k_init<<<256, 256>>>();
    k_converthist<<<(EE + 255) / 256, 256>>>(ei);
    k_dinv<<<(NN + 255) / 256, 256>>>();
    cudaEventRecord(evDinv, 0);

    // side stream B: layer-1 GEMM overlaps scans+scatter
    cudaStreamWaitEvent(sB, evDinv, 0);
    k_gemm<true><<<(NN + 127) / 128, 256, 0, sB>>>(x, W1, NN);
    cudaEventRecord(evGemm1, sB);

    // main stream: scans -> nptr -> scatter
    k_scan1<<<nb1, 1024>>>();
    k_scan2<<<1, 256>>>(nb1);
    k_scan3<<<nb1, 1024>>>();
    k_nptr<<<1, 512>>>(batch);
    k_scatter<<<(EE + 255) / 256, 256>>>();
    cudaEventRecord(evScat, 0);

    // side stream C: edge MLP overlaps node chain
    cudaStreamWaitEvent(sC, evScat, 0);
    k_edgemlp<<<GG * EBLK, 256, 0, sC>>>(ea, We1, be1);
    cudaEventRecord(evEdge, sC);

    // main stream: join gemm1, node chain
    cudaStreamWaitEvent(0, evGemm1, 0);
    k_gather<<<(NN * 32 + 255) / 256, 256>>>(b1, g1, bt1, m1, v1);
    k_gemm<false><<<(NN + 127) / 128, 256>>>(x, W2, NN);
    k_gather<<<(NN * 32 + 255) / 256, 256>>>(b2, g2, bt2, m2, v2);

    // join edge branch, combine
    cudaStreamWaitEvent(0, evEdge, 0);
    k_final<<<GG, 128>>>(We2, be2, out);
}

// round 12
// speedup vs baseline: 2.4440x; 1.0059x over previous
#include <cuda_runtime.h>
#include <cuda_fp16.h>

#define NN 100000
#define NN2 200000
#define DD 128
#define EE 1600000
#define DEE 16
#define GG 512
#define BN_EPS 1e-5f
#define NCHUNK 4
#define CHUNKN 25000

typedef unsigned long long u64;

// ---------------- f32x2 packed helpers -----------------------------------------
__device__ __forceinline__ void ffma2(u64& d, u64 a, u64 b) {
    asm("fma.rn.f32x2 %0, %1, %2, %0;" : "+l"(d) : "l"(a), "l"(b));
}
__device__ __forceinline__ u64 pack_dup(float x) {
    u64 d; unsigned xi = __float_as_uint(x);
    asm("mov.b64 %0, {%1, %1};" : "=l"(d) : "r"(xi));
    return d;
}
__device__ __forceinline__ float2 unpack2(u64 v) {
    unsigned lo, hi;
    asm("mov.b64 {%0, %1}, %2;" : "=r"(lo), "=r"(hi) : "l"(v));
    return make_float2(__uint_as_float(lo), __uint_as_float(hi));
}

// ---------------- scratch (static device globals; no allocation) -----------------
__device__ __align__(16) __half g_bufA[NN * DD];         // 25.6 MB layer-1 xw' fp16
__device__ __align__(16) __half g_bufC[NN * DD];         // 25.6 MB layer-2 xw' fp16
__device__ __align__(16) float g_bufB[NN * DD];          // 51.2 MB h (fp32)
__device__ int   g_deg2[NN2];             // [0,NN): dst degree, [NN,2NN): src degree
__device__ int   g_rowptr[NN + 1];        // dst-CSR row pointers
__device__ int   g_sptr[NN + 1];          // src-CSR row pointers
__device__ int   g_curn[NN];
__device__ int   g_curs[NN];
__device__ int   g_csrsrc[EE];            // dst-CSR payload: src node
__device__ int   g_eid[EE];               // src-CSR payload: edge id
__device__ int   g_src32[EE];
__device__ int   g_dst32[EE];
__device__ int   g_egptr[GG + 1];
__device__ int   g_nptr[GG + 1];
__device__ float g_dinv[NN];
__device__ float g_hsum[GG * DD];
__device__ int   g_blksums[256];
__device__ int   g_is64;

// ---------------- index helpers (dtype-agnostic) ----------------------------------
__device__ __forceinline__ int load_idx(const void* p, long long i) {
    if (g_is64) return (int)((const long long*)p)[i];
    return ((const int*)p)[i];
}
__device__ __forceinline__ int clampi(int v, int lo, int hi) {
    return v < lo ? lo : (v > hi ? hi : v);
}

// ---------------- init + dtype detect in one kernel -----------------------------------
__global__ void k_initdetect(const int* __restrict__ w) {
    if (blockIdx.x == 0) {
        __shared__ int ok;
        if (threadIdx.x == 0) ok = 1;
        __syncthreads();
        int bad = 0;
        for (int i = threadIdx.x; i < 2048; i += blockDim.x)
            if (w[2 * i + 1] != 0) bad = 1;
        if (bad) atomicAnd(&ok, 0);
        __syncthreads();
        if (threadIdx.x == 0) g_is64 = ok;
    }
    int i = blockIdx.x * blockDim.x + threadIdx.x;
    int stride = gridDim.x * blockDim.x;
    for (int j = i; j < NN2; j += stride) g_deg2[j] = 0;
    for (int j = i; j < GG * DD; j += stride) g_hsum[j] = 0.f;
}

// ---------------- convert + histogram in one pass --------------------------------------
__global__ void k_converthist(const void* __restrict__ ei) {
    int e = blockIdx.x * blockDim.x + threadIdx.x;
    if (e >= EE) return;
    int s = clampi(load_idx(ei, e), 0, NN - 1);
    int d = clampi(load_idx(ei, (long long)EE + e), 0, NN - 1);
    g_src32[e] = s;
    g_dst32[e] = d;
    atomicAdd(&g_deg2[d], 1);
    atomicAdd(&g_deg2[NN + s], 1);
}

// ---------------- dinv from dst degree (forks gemm1 early) ------------------------------
__global__ void k_dinv() {
    int i = blockIdx.x * blockDim.x + threadIdx.x;
    if (i < NN) g_dinv[i] = rsqrtf((float)(g_deg2[i] + 1));   // +1 = self-loop
}

// ---------------- 3-phase exclusive scan over g_deg2[0..200k) --------------------------
__global__ void k_scan1() {
    __shared__ int s[1024];
    int b = blockIdx.x, t = threadIdx.x;
    int i = b * 1024 + t;
    int v = (i < NN2) ? g_deg2[i] : 0;
    s[t] = v;
    __syncthreads();
    for (int off = 1; off < 1024; off <<= 1) {
        int x = (t >= off) ? s[t - off] : 0;
        __syncthreads();
        s[t] += x;
        __syncthreads();
    }
    if (i < NN2) {
        if (i < NN) g_rowptr[i] = s[t] - v;
        else        g_sptr[i - NN] = s[t] - v;
    }
    if (t == 1023) g_blksums[b] = s[t];
}

__global__ void k_scan2(int nb) {
    __shared__ int s[256];
    int t = threadIdx.x;
    int v = (t < nb) ? g_blksums[t] : 0;
    s[t] = v;
    __syncthreads();
    for (int off = 1; off < 256; off <<= 1) {
        int x = (t >= off) ? s[t - off] : 0;
        __syncthreads();
        s[t] += x;
        __syncthreads();
    }
    g_blksums[t] = s[t] - v;
}

__global__ void k_scan3() {
    int b = blockIdx.x, t = threadIdx.x;
    int i = b * 1024 + t;
    if (i < NN2) {
        int add = g_blksums[b];
        if (i < NN) {
            int rp = g_rowptr[i] + add;
            g_rowptr[i] = rp;
            g_curn[i] = rp;
        } else {
            int sp = g_sptr[i - NN] + add - EE;
            g_sptr[i - NN] = sp;
            g_curs[i - NN] = sp;
        }
    }
    if (i == 0) { g_rowptr[NN] = EE; g_sptr[NN] = EE; }
}

// ---------------- nptr via binary search on sorted batch; egptr = sptr[nptr] ------------
__global__ void k_nptr(const void* __restrict__ batch) {
    int g = threadIdx.x;    // 512
    int lo = 0, hi = NN;
    while (lo < hi) {
        int mid = (lo + hi) >> 1;
        if (load_idx(batch, mid) < g) lo = mid + 1;
        else hi = mid;
    }
    g_nptr[g] = lo;
    g_egptr[g] = g_sptr[lo];
    if (g == 0) { g_nptr[GG] = NN; g_egptr[GG] = EE; }
}

// ---------------- CSR scatters (split, independent) ----------------------------------------
__global__ void k_scatter_dst() {
    int e = blockIdx.x * blockDim.x + threadIdx.x;
    if (e >= EE) return;
    int s = g_src32[e];
    int d = g_dst32[e];
    int p = atomicAdd(&g_curn[d], 1);
    if (p >= 0 && p < EE) g_csrsrc[p] = s;
}

__global__ void k_scatter_src() {
    int e = blockIdx.x * blockDim.x + threadIdx.x;
    if (e >= EE) return;
    int s = g_src32[e];
    int p2 = atomicAdd(&g_curs[s], 1);
    if (p2 >= 0 && p2 < EE) g_eid[p2] = e;
}

// ---------------- GEMM (FFMA2, 8x8 regtile, double-buffered) -------------------------------
// OUT=false -> g_bufA, OUT=true -> g_bufC. rows [rstart, rend).
#define XPAD 132
template <bool FIRST, bool OUTC>
__global__ void __launch_bounds__(256, 2)
k_gemm(const float* __restrict__ Xext, const float* __restrict__ W, int rstart, int rend) {
    const float* __restrict__ X = FIRST ? Xext : (const float*)g_bufB;
    __half* __restrict__ Y = OUTC ? g_bufC : g_bufA;
    __shared__ __align__(16) float xs[2][16][XPAD];
    __shared__ __align__(16) float ws[2][16][128];
    int tid = threadIdx.x;
    int c = tid & 15;
    int r = tid >> 4;
    int row0 = rstart + blockIdx.x * 128;

    int x_kq = tid & 3;
    int x_rr0 = tid >> 2;

    u64 acc2[8][4];
#pragma unroll
    for (int i = 0; i < 8; i++)
#pragma unroll
        for (int j = 0; j < 4; j++) acc2[i][j] = 0ull;

#pragma unroll
    for (int l = 0; l < 2; l++) {
        int rr = x_rr0 + l * 64;
        int grow = row0 + rr;
        float4 v = make_float4(0.f, 0.f, 0.f, 0.f);
        if (grow < rend)
            v = *reinterpret_cast<const float4*>(&X[grow * DD + x_kq * 4]);
        xs[0][x_kq * 4 + 0][rr] = v.x;
        xs[0][x_kq * 4 + 1][rr] = v.y;
        xs[0][x_kq * 4 + 2][rr] = v.z;
        xs[0][x_kq * 4 + 3][rr] = v.w;
    }
#pragma unroll
    for (int l = 0; l < 8; l++) {
        int idx = tid + l * 256;
        ws[0][idx >> 7][idx & 127] = W[(idx >> 7) * DD + (idx & 127)];
    }
    __syncthreads();

    for (int it = 0; it < 8; it++) {
        int cur = it & 1;
        float4 nx[2];
        float nw[8];
        if (it < 7) {
            int kc = (it + 1) * 16;
#pragma unroll
            for (int l = 0; l < 2; l++) {
                int rr = x_rr0 + l * 64;
                int grow = row0 + rr;
                nx[l] = make_float4(0.f, 0.f, 0.f, 0.f);
                if (grow < rend)
                    nx[l] = *reinterpret_cast<const float4*>(&X[grow * DD + kc + x_kq * 4]);
            }
#pragma unroll
            for (int l = 0; l < 8; l++) {
                int idx = tid + l * 256;
                nw[l] = W[(kc + (idx >> 7)) * DD + (idx & 127)];
            }
        }
#pragma unroll
        for (int k = 0; k < 16; k++) {
            float4 xa = *reinterpret_cast<float4*>(&xs[cur][k][r * 8]);
            float4 xb = *reinterpret_cast<float4*>(&xs[cur][k][r * 8 + 4]);
            ulonglong2 w01 = *reinterpret_cast<ulonglong2*>(&ws[cur][k][c * 8]);
            ulonglong2 w23 = *reinterpret_cast<ulonglong2*>(&ws[cur][k][c * 8 + 4]);
            u64 wp[4] = {w01.x, w01.y, w23.x, w23.y};
            u64 xr2[8] = {pack_dup(xa.x), pack_dup(xa.y), pack_dup(xa.z), pack_dup(xa.w),
                          pack_dup(xb.x), pack_dup(xb.y), pack_dup(xb.z), pack_dup(xb.w)};
#pragma unroll
            for (int i = 0; i < 8; i++)
#pragma unroll
                for (int j = 0; j < 4; j++)
                    ffma2(acc2[i][j], xr2[i], wp[j]);
        }
        if (it < 7) {
            int nxt = cur ^ 1;
#pragma unroll
            for (int l = 0; l < 2; l++) {
                int rr = x_rr0 + l * 64;
                xs[nxt][x_kq * 4 + 0][rr] = nx[l].x;
                xs[nxt][x_kq * 4 + 1][rr] = nx[l].y;
                xs[nxt][x_kq * 4 + 2][rr] = nx[l].z;
                xs[nxt][x_kq * 4 + 3][rr] = nx[l].w;
            }
#pragma unroll
            for (int l = 0; l < 8; l++) {
                int idx = tid + l * 256;
                ws[nxt][idx >> 7][idx & 127] = nw[l];
            }
        }
        __syncthreads();
    }
#pragma unroll
    for (int i = 0; i < 8; i++) {
        int grow = row0 + r * 8 + i;
        if (grow < rend) {
            float d = g_dinv[grow];
            float2 p0 = unpack2(acc2[i][0]);
            float2 p1 = unpack2(acc2[i][1]);
            float2 p2 = unpack2(acc2[i][2]);
            float2 p3 = unpack2(acc2[i][3]);
            __half2 hh[4];
            hh[0] = __floats2half2_rn(p0.x * d, p0.y * d);
            hh[1] = __floats2half2_rn(p1.x * d, p1.y * d);
            hh[2] = __floats2half2_rn(p2.x * d, p2.y * d);
            hh[3] = __floats2half2_rn(p3.x * d, p3.y * d);
            *reinterpret_cast<uint4*>(&Y[grow * DD + c * 8]) = *reinterpret_cast<uint4*>(hh);
        }
    }
}

// ---------------- gather (fp16 payload) + bias + BN(eval) + ReLU, node range ---------------
// SRC_C=false -> payload g_bufA, true -> g_bufC. nodes [nstart, nstart+ncount).
template <bool SRCC>
__global__ void k_gather(const float* __restrict__ B, const float* __restrict__ GA,
                         const float* __restrict__ BT, const float* __restrict__ M,
                         const float* __restrict__ V, int nstart, int ncount) {
    int w = (blockIdx.x * blockDim.x + threadIdx.x) >> 5;
    int lane = threadIdx.x & 31;
    if (w >= ncount) return;
    int node = nstart + w;
    float di = g_dinv[node];
    const uint2* xw2 = reinterpret_cast<const uint2*>(SRCC ? (const __half*)g_bufC
                                                           : (const __half*)g_bufA);
    uint2 u = xw2[node * 32 + lane];
    float2 s01 = __half22float2(*reinterpret_cast<__half2*>(&u.x));
    float2 s23 = __half22float2(*reinterpret_cast<__half2*>(&u.y));
    float4 A0 = make_float4(s01.x, s01.y, s23.x, s23.y);
    float4 A1 = make_float4(0.f, 0.f, 0.f, 0.f);
    float4 A2 = make_float4(0.f, 0.f, 0.f, 0.f);
    float4 A3 = make_float4(0.f, 0.f, 0.f, 0.f);
    int jb = g_rowptr[node], je = g_rowptr[node + 1];
    int j = jb;
    for (; j + 7 < je; j += 8) {
        uint2 u0 = xw2[g_csrsrc[j + 0] * 32 + lane];
        uint2 u1 = xw2[g_csrsrc[j + 1] * 32 + lane];
        uint2 u2 = xw2[g_csrsrc[j + 2] * 32 + lane];
        uint2 u3 = xw2[g_csrsrc[j + 3] * 32 + lane];
        uint2 u4 = xw2[g_csrsrc[j + 4] * 32 + lane];
        uint2 u5 = xw2[g_csrsrc[j + 5] * 32 + lane];
        uint2 u6 = xw2[g_csrsrc[j + 6] * 32 + lane];
        uint2 u7 = xw2[g_csrsrc[j + 7] * 32 + lane];
        float2 fa, fb;
        fa = __half22float2(*reinterpret_cast<__half2*>(&u0.x));
        fb = __half22float2(*reinterpret_cast<__half2*>(&u0.y));
        A0.x += fa.x; A0.y += fa.y; A0.z += fb.x; A0.w += fb.y;
        fa = __half22float2(*reinterpret_cast<__half2*>(&u1.x));
        fb = __half22float2(*reinterpret_cast<__half2*>(&u1.y));
        A1.x += fa.x; A1.y += fa.y; A1.z += fb.x; A1.w += fb.y;
        fa = __half22float2(*reinterpret_cast<__half2*>(&u2.x));
        fb = __half22float2(*reinterpret_cast<__half2*>(&u2.y));
        A2.x += fa.x; A2.y += fa.y; A2.z += fb.x; A2.w += fb.y;
        fa = __half22float2(*reinterpret_cast<__half2*>(&u3.x));
        fb = __half22float2(*reinterpret_cast<__half2*>(&u3.y));
        A3.x += fa.x; A3.y += fa.y; A3.z += fb.x; A3.w += fb.y;
        fa = __half22float2(*reinterpret_cast<__half2*>(&u4.x));
        fb = __half22float2(*reinterpret_cast<__half2*>(&u4.y));
        A0.x += fa.x; A0.y += fa.y; A0.z += fb.x; A0.w += fb.y;
        fa = __half22float2(*reinterpret_cast<__half2*>(&u5.x));
        fb = __half22float2(*reinterpret_cast<__half2*>(&u5.y));
        A1.x += fa.x; A1.y += fa.y; A1.z += fb.x; A1.w += fb.y;
        fa = __half22float2(*reinterpret_cast<__half2*>(&u6.x));
        fb = __half22float2(*reinterpret_cast<__half2*>(&u6.y));
        A2.x += fa.x; A2.y += fa.y; A2.z += fb.x; A2.w += fb.y;
        fa = __half22float2(*reinterpret_cast<__half2*>(&u7.x));
        fb = __half22float2(*reinterpret_cast<__half2*>(&u7.y));
        A3.x += fa.x; A3.y += fa.y; A3.z += fb.x; A3.w += fb.y;
    }
    for (; j < je; j++) {
        uint2 uv = xw2[g_csrsrc[j] * 32 + lane];
        float2 fa = __half22float2(*reinterpret_cast<__half2*>(&uv.x));
        float2 fb = __half22float2(*reinterpret_cast<__half2*>(&uv.y));
        A0.x += fa.x; A0.y += fa.y; A0.z += fb.x; A0.w += fb.y;
    }
    float4 acc;
    acc.x = (A0.x + A1.x) + (A2.x + A3.x);
    acc.y = (A0.y + A1.y) + (A2.y + A3.y);
    acc.z = (A0.z + A1.z) + (A2.z + A3.z);
    acc.w = (A0.w + A1.w) + (A2.w + A3.w);
    int f = lane * 4;
    float4 b4  = *reinterpret_cast<const float4*>(&B[f]);
    float4 g4  = *reinterpret_cast<const float4*>(&GA[f]);
    float4 bt4 = *reinterpret_cast<const float4*>(&BT[f]);
    float4 m4  = *reinterpret_cast<const float4*>(&M[f]);
    float4 vv4 = *reinterpret_cast<const float4*>(&V[f]);
    float4 o;
    o.x = fmaxf((acc.x * di + b4.x - m4.x) * rsqrtf(vv4.x + BN_EPS) * g4.x + bt4.x, 0.f);
    o.y = fmaxf((acc.y * di + b4.y - m4.y) * rsqrtf(vv4.y + BN_EPS) * g4.y + bt4.y, 0.f);
    o.z = fmaxf((acc.z * di + b4.z - m4.z) * rsqrtf(vv4.z + BN_EPS) * g4.z + bt4.z, 0.f);
    o.w = fmaxf((acc.w * di + b4.w - m4.w) * rsqrtf(vv4.w + BN_EPS) * g4.w + bt4.w, 0.f);
    float4* out4 = reinterpret_cast<float4*>((float*)g_bufB);
    out4[node * 32 + lane] = o;
}

// ---------------- edge MLP first layer, summed per graph (FFMA2, 2-edge ILP) -----------------
#define EBLK 8
__global__ void k_edgemlp(const float* __restrict__ EA, const float* __restrict__ W1e,
                          const float* __restrict__ B1e) {
    int g = blockIdx.x >> 3;
    int q = blockIdx.x & (EBLK - 1);
    int tid = threadIdx.x, warp = tid >> 5, lane = tid & 31;
    __shared__ float eas[8][2][16];
    __shared__ float red[DD];
    ulonglong2 wc[16];
#pragma unroll
    for (int k = 0; k < 16; k++)
        wc[k] = *reinterpret_cast<const ulonglong2*>(&W1e[k * DD + lane * 4]);
    ulonglong2 b2 = *reinterpret_cast<const ulonglong2*>(&B1e[lane * 4]);

    int gb = g_egptr[g], ge = g_egptr[g + 1];
    int cnt = ge - gb;
    int per = (cnt + EBLK - 1) / EBLK;
    int jb = gb + q * per;
    int je = min(jb + per, ge);

    float4 acc = make_float4(0.f, 0.f, 0.f, 0.f);
    for (int j = jb + warp; j < je; j += 16) {
        int j2 = j + 8;
        bool has2 = (j2 < je);
        int e0 = g_eid[j];
        int e1 = has2 ? g_eid[j2] : e0;
        if (lane < 16) eas[warp][0][lane] = EA[(long long)e0 * DEE + lane];
        else           eas[warp][1][lane - 16] = EA[(long long)e1 * DEE + (lane - 16)];
        __syncwarp();
        u64 h0 = b2.x, h1 = b2.y, h2 = b2.x, h3 = b2.y;
#pragma unroll
        for (int k = 0; k < 16; k++) {
            u64 p0 = pack_dup(eas[warp][0][k]);
            u64 p1 = pack_dup(eas[warp][1][k]);
            ffma2(h0, p0, wc[k].x);
            ffma2(h1, p0, wc[k].y);
            ffma2(h2, p1, wc[k].x);
            ffma2(h3, p1, wc[k].y);
        }
        float2 u0 = unpack2(h0), u1 = unpack2(h1);
        acc.x += fmaxf(u0.x, 0.f);
        acc.y += fmaxf(u0.y, 0.f);
        acc.z += fmaxf(u1.x, 0.f);
        acc.w += fmaxf(u1.y, 0.f);
        if (has2) {
            float2 u2 = unpack2(h2), u3 = unpack2(h3);
            acc.x += fmaxf(u2.x, 0.f);
            acc.y += fmaxf(u2.y, 0.f);
            acc.z += fmaxf(u3.x, 0.f);
            acc.w += fmaxf(u3.y, 0.f);
        }
        __syncwarp();
    }
    if (tid < DD) red[tid] = 0.f;
    __syncthreads();
    int f = lane * 4;
    atomicAdd(&red[f + 0], acc.x);
    atomicAdd(&red[f + 1], acc.y);
    atomicAdd(&red[f + 2], acc.z);
    atomicAdd(&red[f + 3], acc.w);
    __syncthreads();
    if (tid < DD) atomicAdd(&g_hsum[g * DD + tid], red[tid]);
}

// ---------------- final combine: node segment-mean + edge GEMM ----------------------------
__global__ void k_final(const float* __restrict__ We2, const float* __restrict__ be2,
                        float* __restrict__ out) {
    int g = blockIdx.x;
    int t = threadIdx.x;   // 128
    __shared__ float hm[DD];
    int ec = g_egptr[g + 1] - g_egptr[g];
    float inv_e = (ec > 0) ? (1.f / (float)ec) : 0.f;
    hm[t] = g_hsum[g * DD + t] * inv_e;

    int ns = g_nptr[g], ne = g_nptr[g + 1];
    const float* __restrict__ H = (const float*)g_bufB;
    float a0 = 0.f, a1 = 0.f, a2 = 0.f, a3 = 0.f;
    int rr = ns;
    for (; rr + 3 < ne; rr += 4) {
        a0 += H[(long long)rr * DD + t];
        a1 += H[(long long)(rr + 1) * DD + t];
        a2 += H[(long long)(rr + 2) * DD + t];
        a3 += H[(long long)(rr + 3) * DD + t];
    }
    for (; rr < ne; rr++) a0 += H[(long long)rr * DD + t];
    float nsumv = (a0 + a1) + (a2 + a3);

    __syncthreads();
    float acc = be2[t];
#pragma unroll 4
    for (int k = 0; k < DD; k++)
        acc = fmaf(hm[k], We2[k * DD + t], acc);
    if (ec == 0) acc = 0.f;
    int nc = ne - ns;
    float gr = nsumv / fmaxf((float)nc, 1.f);
    out[g * DD + t] = gr + acc;
}

// ---------------- launch ------------------------------------------------------------------------
extern "C" void kernel_launch(void* const* d_in, const int* in_sizes, int n_in,
                              void* d_out, int out_size) {
    const float* x = 0;  const void* ei = 0;  const void* batch = 0;  const float* ea = 0;
    const float* w16k[3] = {0, 0, 0};
    const float* v128[12] = {0};
    const float* We1 = 0;
    int n16k = 0, n128 = 0;
    for (int i = 0; i < n_in; i++) {
        long long sz = in_sizes[i];
        if      (sz == (long long)NN * DD) { if (!x) x = (const float*)d_in[i]; }
        else if (sz == 2LL * EE)           { if (!ei) ei = d_in[i]; }
        else if (sz == NN)                 { if (!batch) batch = d_in[i]; }
        else if (sz == (long long)EE * DEE){ if (!ea) ea = (const float*)d_in[i]; }
        else if (sz == DD * DD)            { if (n16k < 3) w16k[n16k++] = (const float*)d_in[i]; }
        else if (sz == DEE * DD)           { if (!We1) We1 = (const float*)d_in[i]; }
        else if (sz == DD)                 { if (n128 < 12) v128[n128++] = (const float*)d_in[i]; }
    }
    const float *W1 = w16k[0], *W2 = w16k[1], *We2 = w16k[2];
    const float *b1 = v128[0], *g1 = v128[1], *bt1 = v128[2], *m1 = v128[3], *v1 = v128[4];
    const float *b2 = v128[5], *g2 = v128[6], *bt2 = v128[7], *m2 = v128[8], *v2 = v128[9];
    const float *be1 = v128[10], *be2 = v128[11];
    float* out = (float*)d_out;

    static cudaStream_t sB = 0, sC = 0;
    static cudaEvent_t evDinv = 0, evGemm1 = 0, evScan3 = 0, evEdge = 0, evGm2 = 0;
    static cudaEvent_t evG1[NCHUNK] = {0};
    if (!sB) {
        cudaStreamCreateWithFlags(&sB, cudaStreamNonBlocking);
        cudaStreamCreateWithFlags(&sC, cudaStreamNonBlocking);
        cudaEventCreateWithFlags(&evDinv, cudaEventDisableTiming);
        cudaEventCreateWithFlags(&evGemm1, cudaEventDisableTiming);
        cudaEventCreateWithFlags(&evScan3, cudaEventDisableTiming);
        cudaEventCreateWithFlags(&evEdge, cudaEventDisableTiming);
        cudaEventCreateWithFlags(&evGm2, cudaEventDisableTiming);
        for (int i = 0; i < NCHUNK; i++)
            cudaEventCreateWithFlags(&evG1[i], cudaEventDisableTiming);
    }

    const int nb1 = (NN2 + 1023) / 1024;   // 196

    // main: init(+detect) -> converthist -> dinv
    k_initdetect<<<256, 256>>>((const int*)ei);
    k_converthist<<<(EE + 255) / 256, 256>>>(ei);
    k_dinv<<<(NN + 255) / 256, 256>>>();
    cudaEventRecord(evDinv, 0);

    // stream B: layer-1 GEMM (full) overlaps scans+scatter_dst
    cudaStreamWaitEvent(sB, evDinv, 0);
    k_gemm<true, false><<<(NN + 127) / 128, 256, 0, sB>>>(x, W1, 0, NN);
    cudaEventRecord(evGemm1, sB);

    // main: scans
    k_scan1<<<nb1, 1024>>>();
    k_scan2<<<1, 256>>>(nb1);
    k_scan3<<<nb1, 1024>>>();
    cudaEventRecord(evScan3, 0);

    // stream C: nptr -> scatter_src -> edgemlp (edge branch fully off critical path)
    cudaStreamWaitEvent(sC, evScan3, 0);
    k_nptr<<<1, 512, 0, sC>>>(batch);
    k_scatter_src<<<(EE + 255) / 256, 256, 0, sC>>>();
    k_edgemlp<<<GG * EBLK, 256, 0, sC>>>(ea, We1, be1);
    cudaEventRecord(evEdge, sC);

    // main: dst scatter, then join gemm1
    k_scatter_dst<<<(EE + 255) / 256, 256>>>();
    cudaStreamWaitEvent(0, evGemm1, 0);

    // pipelined gather1 (main) / gemm2 (stream B), 4 chunks of 25k nodes
    const int gblocks = (CHUNKN * 32 + 255) / 256;
    const int mblocks = (CHUNKN + 127) / 128;
    for (int ci = 0; ci < NCHUNK; ci++) {
        int ns = ci * CHUNKN;
        k_gather<false><<<gblocks, 256>>>(b1, g1, bt1, m1, v1, ns, CHUNKN);
        cudaEventRecord(evG1[ci], 0);
        cudaStreamWaitEvent(sB, evG1[ci], 0);
        k_gemm<false, true><<<mblocks, 256, 0, sB>>>(x, W2, ns, ns + CHUNKN);
    }
    cudaEventRecord(evGm2, sB);

    // gather2 (full) after all gemm2 chunks
    cudaStreamWaitEvent(0, evGm2, 0);
    k_gather<true><<<(NN * 32 + 255) / 256, 256>>>(b2, g2, bt2, m2, v2, 0, NN);

    // join edge branch, combine
    cudaStreamWaitEvent(0, evEdge, 0);
    k_final<<<GG, 128>>>(We2, be2, out);
}